// round 1
// baseline (speedup 1.0000x reference)
#include <cuda_runtime.h>
#include <math.h>

// ---------------------------------------------------------------------------
// KimiDeltaAttention  (B=1, T=1024, DM=2048, H=16, DH=128, KD=2048, KC=4)
// Round 0: correct fp32 implementation.
//   - SIMT SGEMM 128x128x8 tiles (8x8 per thread) for all dense projections
//   - split-K (16-way, atomicAdd) for the tall-skinny rank-128 projections
//   - warp-per-column recurrence: 2048 independent 128-dim column recurrences,
//     state in registers (4 floats/lane), per-step q/k/exp(g) staged through
//     double-buffered shared memory, one __syncthreads per step.
// ---------------------------------------------------------------------------

#define T_LEN 1024
#define DM    2048
#define NH    16
#define DH    128
#define KD    2048

static constexpr size_t NTK = (size_t)T_LEN * KD;   // 2097152

// scratch: q0,k0,v0,qc,kc,vc,eg,gout,o,og (10 x NTK) + fa + ga + beta
__device__ float g_scratch[10 * 2097152 + 262144 + 16384];

#define OFF_Q0   ((size_t)0)
#define OFF_K0   (NTK * 1)
#define OFF_V0   (NTK * 2)
#define OFF_QC   (NTK * 3)
#define OFF_KC   (NTK * 4)
#define OFF_VC   (NTK * 5)
#define OFF_EG   (NTK * 6)
#define OFF_GOUT (NTK * 7)
#define OFF_O    (NTK * 8)
#define OFF_OG   (NTK * 9)
#define OFF_FA   (NTK * 10)
#define OFF_GA   (NTK * 10 + 131072)
#define OFF_BETA (NTK * 10 + 262144)

// ---------------------------------------------------------------------------
// SGEMM: C[M,N] (+)= A[M,K_part] * B[K_part,N]  (row-major, fp32)
// BM=BN=128, BK=8, 256 threads, 8x8 accumulators per thread.
// Assumes M % 128 == 0, N % 128 == 0, kSplit % 8 == 0.
// gridDim.z * kSplit == K for split-K (ATOMIC=1), else gridDim.z==1, kSplit==K.
// ---------------------------------------------------------------------------
template <int ATOMIC>
__global__ __launch_bounds__(256)
void sgemm_k(const float* __restrict__ A, const float* __restrict__ B,
             float* __restrict__ C, int M, int N, int K, int kSplit)
{
    __shared__ __align__(16) float As[8][128];
    __shared__ __align__(16) float Bs[8][128];

    const int tid  = threadIdx.x;
    const int bm   = blockIdx.y;
    const int bn   = blockIdx.x;
    const int k0   = blockIdx.z * kSplit;

    const int arow = tid >> 1;            // 0..127
    const int acol = (tid & 1) << 2;      // 0 or 4
    const int brow = tid >> 5;            // 0..7
    const int bcol = (tid & 31) << 2;     // 0..124
    const int ty   = tid >> 4;            // 0..15
    const int tx   = tid & 15;            // 0..15

    float acc[8][8];
#pragma unroll
    for (int i = 0; i < 8; i++)
#pragma unroll
        for (int j = 0; j < 8; j++) acc[i][j] = 0.f;

    const float* Ag = A + (size_t)(bm * 128 + arow) * K;
    const float* Bg = B + (size_t)(bn * 128) + bcol;

    for (int kt = 0; kt < kSplit; kt += 8) {
        float4 av = *(const float4*)(Ag + (k0 + kt + acol));
        As[acol + 0][arow] = av.x;
        As[acol + 1][arow] = av.y;
        As[acol + 2][arow] = av.z;
        As[acol + 3][arow] = av.w;
        *(float4*)&Bs[brow][bcol] =
            *(const float4*)(Bg + (size_t)(k0 + kt + brow) * N);
        __syncthreads();

#pragma unroll
        for (int kk = 0; kk < 8; kk++) {
            float4 a0 = *(const float4*)&As[kk][ty * 8];
            float4 a1 = *(const float4*)&As[kk][ty * 8 + 4];
            float4 b0 = *(const float4*)&Bs[kk][tx * 8];
            float4 b1 = *(const float4*)&Bs[kk][tx * 8 + 4];
            float a[8] = {a0.x, a0.y, a0.z, a0.w, a1.x, a1.y, a1.z, a1.w};
            float b[8] = {b0.x, b0.y, b0.z, b0.w, b1.x, b1.y, b1.z, b1.w};
#pragma unroll
            for (int i = 0; i < 8; i++)
#pragma unroll
                for (int j = 0; j < 8; j++)
                    acc[i][j] = fmaf(a[i], b[j], acc[i][j]);
        }
        __syncthreads();
    }

#pragma unroll
    for (int i = 0; i < 8; i++) {
        float* Cp = C + (size_t)(bm * 128 + ty * 8 + i) * N + bn * 128 + tx * 8;
        if (ATOMIC) {
#pragma unroll
            for (int j = 0; j < 8; j++) atomicAdd(Cp + j, acc[i][j]);
        } else {
            *(float4*)(Cp + 0) = make_float4(acc[i][0], acc[i][1], acc[i][2], acc[i][3]);
            *(float4*)(Cp + 4) = make_float4(acc[i][4], acc[i][5], acc[i][6], acc[i][7]);
        }
    }
}

// ---------------------------------------------------------------------------
// zero kernel
// ---------------------------------------------------------------------------
__global__ void zero_k(float* __restrict__ p, int n)
{
    int i = blockIdx.x * 256 + threadIdx.x;
    if (i < n) p[i] = 0.f;
}

// ---------------------------------------------------------------------------
// depthwise causal conv (K=4) + SiLU for q,k,v  (blockIdx.y selects tensor)
// ---------------------------------------------------------------------------
__global__ __launch_bounds__(256)
void conv_silu_k(const float* __restrict__ i0, const float* __restrict__ i1,
                 const float* __restrict__ i2,
                 const float* __restrict__ w0, const float* __restrict__ w1,
                 const float* __restrict__ w2,
                 float* __restrict__ o0, float* __restrict__ o1,
                 float* __restrict__ o2)
{
    const float* in; const float* w; float* out;
    if (blockIdx.y == 0)      { in = i0; w = w0; out = o0; }
    else if (blockIdx.y == 1) { in = i1; w = w1; out = o1; }
    else                      { in = i2; w = w2; out = o2; }

    int idx = blockIdx.x * 256 + threadIdx.x;           // 0 .. T*KD-1
    int t = idx >> 11;
    int c = idx & (KD - 1);
    float acc = 0.f;
#pragma unroll
    for (int j = 0; j < 4; j++) {
        int tt = t + j - 3;
        if (tt >= 0) acc = fmaf(w[j * KD + c], in[(size_t)tt * KD + c], acc);
    }
    out[idx] = acc / (1.f + expf(-acc));                // silu
}

// ---------------------------------------------------------------------------
// gate prep (in-place on g_raw buffer):
//   eg = exp( -exp(A_log[h]) * softplus_stable(graw + dt_bias[c]) )
// ---------------------------------------------------------------------------
__global__ __launch_bounds__(256)
void gprep_k(float* __restrict__ eg, const float* __restrict__ dt_bias,
             const float* __restrict__ A_log)
{
    int idx = blockIdx.x * 256 + threadIdx.x;
    int c = idx & (KD - 1);
    int h = c >> 7;
    float xr = eg[idx] + dt_bias[c];
    xr = fminf(fmaxf(xr, -20.f), 20.f);
    float sp = log1pf(expf(xr));
    float g = -expf(A_log[h]) * sp;
    eg[idx] = expf(g);
}

// ---------------------------------------------------------------------------
// beta = sigmoid(x @ Wb)   Wb: [DM,16] row-major. One block per t, warp per h.
// ---------------------------------------------------------------------------
__global__ __launch_bounds__(512)
void beta_k(const float* __restrict__ x, const float* __restrict__ Wb,
            float* __restrict__ beta)
{
    __shared__ float sx[DM];
    int t = blockIdx.x;
    for (int i = threadIdx.x; i < DM; i += 512) sx[i] = x[(size_t)t * DM + i];
    __syncthreads();
    int h = threadIdx.x >> 5, lane = threadIdx.x & 31;
    float acc = 0.f;
    for (int k = lane; k < DM; k += 32) acc = fmaf(sx[k], Wb[k * NH + h], acc);
#pragma unroll
    for (int m = 16; m > 0; m >>= 1) acc += __shfl_xor_sync(0xffffffffu, acc, m);
    if (lane == 0) beta[t * NH + h] = 1.f / (1.f + expf(-acc));
}

// ---------------------------------------------------------------------------
// block-of-128 reduce helper
// ---------------------------------------------------------------------------
__device__ __forceinline__ float block128_sum(float v, float* shm)
{
#pragma unroll
    for (int m = 16; m > 0; m >>= 1) v += __shfl_xor_sync(0xffffffffu, v, m);
    int w = threadIdx.x >> 5;
    if ((threadIdx.x & 31) == 0) shm[w] = v;
    __syncthreads();
    return shm[0] + shm[1] + shm[2] + shm[3];
}

// ---------------------------------------------------------------------------
// in-place per-(t,h) l2 norm over DH, times scale.  grid (T, H), block 128.
// ---------------------------------------------------------------------------
__global__ __launch_bounds__(128)
void l2norm_k(float* __restrict__ p, float scale)
{
    __shared__ float shm[4];
    int t = blockIdx.x, h = blockIdx.y, d = threadIdx.x;
    size_t idx = (size_t)t * KD + h * DH + d;
    float v = p[idx];
    float ss = block128_sum(v * v, shm);
    p[idx] = v * rsqrtf(ss + 1e-6f) * scale;
}

// ---------------------------------------------------------------------------
// Recurrence. One warp per V-column (2048 columns). Lane owns 4 k-entries of
// the 128-dim column state in registers. 8 columns (same head) per CTA share
// per-step q/k/exp(g)/v/beta through double-buffered shared memory.
// ---------------------------------------------------------------------------
__global__ __launch_bounds__(256)
void recur_k(const float* __restrict__ qf, const float* __restrict__ kf,
             const float* __restrict__ vv, const float* __restrict__ eg,
             const float* __restrict__ beta, float* __restrict__ o)
{
    __shared__ __align__(16) float sq[2][128];
    __shared__ __align__(16) float sk[2][128];
    __shared__ __align__(16) float se[2][128];
    __shared__ float sv[2][8];
    __shared__ float sb[2];

    const int tid     = threadIdx.x;
    const int wid     = tid >> 5;
    const int lane    = tid & 31;
    const int colbase = blockIdx.x * 8;       // 8 columns, all in one head
    const int head    = colbase >> 7;
    const int col     = colbase + wid;

    // preload t = 0 into buffer 0
    {
        size_t off = (size_t)head * DH;       // t=0
        if (tid < 128) {
            sq[0][tid] = qf[off + tid];
            se[0][tid] = eg[off + tid];
        } else {
            int i = tid - 128;
            sk[0][i] = kf[off + i];
            if (i < 8)  sv[0][i] = vv[colbase + i];
            if (i == 8) sb[0] = beta[head];
        }
    }

    float s0 = 0.f, s1 = 0.f, s2 = 0.f, s3 = 0.f;

    for (int t = 0; t < T_LEN; t++) {
        const int buf = t & 1;
        __syncthreads();

        // prefetch next step into the other buffer
        if (t + 1 < T_LEN) {
            size_t off = (size_t)(t + 1) * KD + head * DH;
            if (tid < 128) {
                sq[buf ^ 1][tid] = qf[off + tid];
                se[buf ^ 1][tid] = eg[off + tid];
            } else {
                int i = tid - 128;
                sk[buf ^ 1][i] = kf[off + i];
                if (i < 8)  sv[buf ^ 1][i] = vv[(size_t)(t + 1) * KD + colbase + i];
                if (i == 8) sb[buf ^ 1] = beta[(t + 1) * NH + head];
            }
        }

        float4 egv = ((const float4*)se[buf])[lane];
        float4 kv  = ((const float4*)sk[buf])[lane];
        float4 qv  = ((const float4*)sq[buf])[lane];
        float vval = sv[buf][wid];
        float bet  = sb[buf];

        // state decay
        s0 *= egv.x; s1 *= egv.y; s2 *= egv.z; s3 *= egv.w;

        // inner = k . state_col
        float inner = s0 * kv.x + s1 * kv.y + s2 * kv.z + s3 * kv.w;
#pragma unroll
        for (int m = 16; m > 0; m >>= 1)
            inner += __shfl_xor_sync(0xffffffffu, inner, m);

        // delta update
        float upd = bet * (vval - inner);
        s0 = fmaf(kv.x, upd, s0);
        s1 = fmaf(kv.y, upd, s1);
        s2 = fmaf(kv.z, upd, s2);
        s3 = fmaf(kv.w, upd, s3);

        // output = q . state_col
        float oc = s0 * qv.x + s1 * qv.y + s2 * qv.z + s3 * qv.w;
#pragma unroll
        for (int m = 16; m > 0; m >>= 1)
            oc += __shfl_xor_sync(0xffffffffu, oc, m);
        if (lane == 0) o[(size_t)t * KD + col] = oc;
    }
}

// ---------------------------------------------------------------------------
// epilogue: og = o * rsqrt(mean(o^2)+eps) * norm_w * sigmoid(gout)
// grid (T, H), block 128
// ---------------------------------------------------------------------------
__global__ __launch_bounds__(128)
void epi_k(const float* __restrict__ o, const float* __restrict__ gout,
           const float* __restrict__ norm_w, float* __restrict__ og)
{
    __shared__ float shm[4];
    int t = blockIdx.x, h = blockIdx.y, d = threadIdx.x;
    size_t idx = (size_t)t * KD + h * DH + d;
    float ov = o[idx];
    float ss = block128_sum(ov * ov, shm);
    float rstd = rsqrtf(ss * (1.f / 128.f) + 1e-6f);
    float gate = 1.f / (1.f + expf(-gout[idx]));
    og[idx] = ov * rstd * norm_w[d] * gate;
}

// ---------------------------------------------------------------------------
// launch
// ---------------------------------------------------------------------------
extern "C" void kernel_launch(void* const* d_in, const int* in_sizes, int n_in,
                              void* d_out, int out_size)
{
    (void)in_sizes; (void)n_in; (void)out_size;
    const float* x      = (const float*)d_in[0];
    const float* Wq     = (const float*)d_in[1];
    const float* Wk     = (const float*)d_in[2];
    const float* Wv     = (const float*)d_in[3];
    const float* conv_q = (const float*)d_in[4];
    const float* conv_k = (const float*)d_in[5];
    const float* conv_v = (const float*)d_in[6];
    const float* Wfa    = (const float*)d_in[7];
    const float* Wfb    = (const float*)d_in[8];
    const float* dt_b   = (const float*)d_in[9];
    const float* A_log  = (const float*)d_in[10];
    const float* Wb     = (const float*)d_in[11];
    const float* Wga    = (const float*)d_in[12];
    const float* Wgb    = (const float*)d_in[13];
    const float* norm_w = (const float*)d_in[14];
    const float* Wo     = (const float*)d_in[15];
    float* out = (float*)d_out;

    float* s = nullptr;
    cudaGetSymbolAddress((void**)&s, g_scratch);
    float* q0   = s + OFF_Q0;
    float* k0   = s + OFF_K0;
    float* v0   = s + OFF_V0;
    float* qc   = s + OFF_QC;
    float* kc   = s + OFF_KC;
    float* vc   = s + OFF_VC;
    float* eg   = s + OFF_EG;
    float* gout = s + OFF_GOUT;
    float* o    = s + OFF_O;
    float* og   = s + OFF_OG;
    float* fa   = s + OFF_FA;
    float* ga   = s + OFF_GA;
    float* beta = s + OFF_BETA;

    dim3 gBig(16, 8, 1);       // N=2048 tiles x M=1024 tiles

    // q/k/v projections
    sgemm_k<0><<<gBig, 256>>>(x, Wq, q0, T_LEN, KD, DM, DM);
    sgemm_k<0><<<gBig, 256>>>(x, Wk, k0, T_LEN, KD, DM, DM);
    sgemm_k<0><<<gBig, 256>>>(x, Wv, v0, T_LEN, KD, DM, DM);

    // causal depthwise conv + silu
    conv_silu_k<<<dim3((unsigned)(NTK / 256), 3), 256>>>(
        q0, k0, v0, conv_q, conv_k, conv_v, qc, kc, vc);

    // low-rank gate chains (split-K with atomics for the skinny stage)
    zero_k<<<1024, 256>>>(fa, 262144);   // zeroes fa and ga (contiguous)
    sgemm_k<1><<<dim3(1, 8, 16), 256>>>(x, Wfa, fa, T_LEN, DH, DM, 128);
    sgemm_k<1><<<dim3(1, 8, 16), 256>>>(x, Wga, ga, T_LEN, DH, DM, 128);
    sgemm_k<0><<<gBig, 256>>>(fa, Wfb, eg,   T_LEN, KD, DH, DH);
    sgemm_k<0><<<gBig, 256>>>(ga, Wgb, gout, T_LEN, KD, DH, DH);

    // exp(g) precompute, beta, qk l2norm
    gprep_k<<<(unsigned)(NTK / 256), 256>>>(eg, dt_b, A_log);
    beta_k<<<T_LEN, 512>>>(x, Wb, beta);
    l2norm_k<<<dim3(T_LEN, NH), 128>>>(qc, 0.08838834764831845f); // DH^-0.5
    l2norm_k<<<dim3(T_LEN, NH), 128>>>(kc, 1.0f);

    // gated delta recurrence
    recur_k<<<256, 256>>>(qc, kc, vc, eg, beta, o);

    // gated rmsnorm epilogue + output projection
    epi_k<<<dim3(T_LEN, NH), 128>>>(o, gout, norm_w, og);
    sgemm_k<0><<<gBig, 256>>>(og, Wo, out, T_LEN, DM, KD, KD);
}

// round 4
// speedup vs baseline: 1.8588x; 1.8588x over previous
#include <cuda_runtime.h>
#include <math.h>
#include <cstdint>

// ---------------------------------------------------------------------------
// KimiDeltaAttention  (B=1, T=1024, DM=2048, H=16, DH=128, KD=2048, KC=4)
// Round 3 (resubmit of R2 after infra failure): tf32 mma.sync GEMMs.
//   - 128x128 CTA tile, BK=16, 8 warps m32xn64, m16n8k8 tf32 MMA
//   - 3-stage cp.async ring, padded smem (stride 20 floats, conflict-free)
//   - all MMA operands pre-rounded with cvt.rna.tf32.f32 (unbiased)
// ---------------------------------------------------------------------------

#define T_LEN 1024
#define DM    2048
#define NH    16
#define DH    128
#define KD    2048

static constexpr size_t NTK = (size_t)T_LEN * KD;   // 2097152

#define OFF_Q0   ((size_t)0)
#define OFF_K0   (NTK * 1)
#define OFF_V0   (NTK * 2)
#define OFF_QC   (NTK * 3)
#define OFF_KC   (NTK * 4)
#define OFF_VC   (NTK * 5)
#define OFF_EG   (NTK * 6)
#define OFF_GOUT (NTK * 7)
#define OFF_O    (NTK * 8)
#define OFF_OG   (NTK * 9)
#define OFF_XR   (NTK * 10)
#define OFF_FA   (NTK * 11)
#define OFF_GA   (NTK * 11 + 131072)
#define OFF_BETA (NTK * 11 + 262144)
#define OFF_WQT  (NTK * 11 + 278528)
#define OFF_WKT  (OFF_WQT + 4194304)
#define OFF_WVT  (OFF_WKT + 4194304)
#define OFF_WOT  (OFF_WVT + 4194304)
#define OFF_WFBT (OFF_WOT + 4194304)
#define OFF_WGBT (OFF_WFBT + 262144)
#define SCRATCH_FLOATS (OFF_WGBT + 262144)

__device__ float g_scratch[SCRATCH_FLOATS];

// ---------------------------------------------------------------------------
// helpers
// ---------------------------------------------------------------------------
__device__ __forceinline__ uint32_t smem_u32(const void* p) {
    uint32_t a;
    asm("{ .reg .u64 t; cvta.to.shared.u64 t, %1; cvt.u32.u64 %0, t; }"
        : "=r"(a) : "l"(p));
    return a;
}

__device__ __forceinline__ void cp16(uint32_t dst, const void* src) {
    asm volatile("cp.async.cg.shared.global [%0], [%1], 16;"
                 :: "r"(dst), "l"(src) : "memory");
}
#define CP_COMMIT() asm volatile("cp.async.commit_group;" ::: "memory")
#define CP_WAIT(n)  asm volatile("cp.async.wait_group %0;" :: "n"(n) : "memory")

// unbiased fp32 -> tf32 rounding (round-to-nearest on 19-bit mantissa)
__device__ __forceinline__ float tf32r(float x) {
    uint32_t u;
    asm("cvt.rna.tf32.f32 %0, %1;" : "=r"(u) : "f"(x));
    return __uint_as_float(u);
}

// ---------------------------------------------------------------------------
// tf32 mma.sync GEMM: C[M,N] = A[M,K] * Bt[N,K]^T  (row-major fp32, tf32-
// pre-rounded inputs). grid (N/128, M/128), 256 threads.
// ---------------------------------------------------------------------------
#define SA_STR   20                      // padded row stride (floats)
#define STAGE_F  (128 * SA_STR)          // floats per matrix per stage
#define MMA_SMEM (3 * 2 * STAGE_F * 4)   // 61440 bytes

__global__ __launch_bounds__(256)
void mmagemm_k(const float* __restrict__ A, const float* __restrict__ Bt,
               float* __restrict__ C, int M, int N, int K)
{
    extern __shared__ float sbase[];

    const int tid  = threadIdx.x;
    const int wid  = tid >> 5;
    const int lane = tid & 31;
    const int wm   = wid >> 1;           // 0..3
    const int wn   = wid & 1;            // 0..1
    const int m0   = blockIdx.y * 128;
    const int n0   = blockIdx.x * 128;
    const int NT   = K >> 4;

    float acc[2][8][4];
#pragma unroll
    for (int a = 0; a < 2; a++)
#pragma unroll
        for (int b = 0; b < 8; b++)
#pragma unroll
            for (int c = 0; c < 4; c++) acc[a][b][c] = 0.f;

    auto load_stage = [&](int s, int i) {
        const float* gA = A  + (size_t)m0 * K + i * 16;
        const float* gB = Bt + (size_t)n0 * K + i * 16;
        float* dA = sbase + s * 2 * STAGE_F;
        float* dB = dA + STAGE_F;
#pragma unroll
        for (int t = 0; t < 2; t++) {
            int c   = tid + t * 256;     // 0..511
            int row = c >> 2;
            int c4  = (c & 3) * 4;
            cp16(smem_u32(dA + row * SA_STR + c4), gA + (size_t)row * K + c4);
            cp16(smem_u32(dB + row * SA_STR + c4), gB + (size_t)row * K + c4);
        }
        CP_COMMIT();
    };

    load_stage(0, 0);
    load_stage(1, 1);

    for (int i = 0; i < NT; i++) {
        const int s = i % 3;
        if (i + 1 < NT) { CP_WAIT(1); } else { CP_WAIT(0); }
        __syncthreads();

        const float* sA = sbase + s * 2 * STAGE_F;
        const float* sB = sA + STAGE_F;

#pragma unroll
        for (int kk = 0; kk < 16; kk += 8) {
            uint32_t bf[8][2];
#pragma unroll
            for (int nt = 0; nt < 8; nt++) {
                int n = wn * 64 + nt * 8 + (lane >> 2);
                bf[nt][0] = __float_as_uint(sB[n * SA_STR + kk + (lane & 3)]);
                bf[nt][1] = __float_as_uint(sB[n * SA_STR + kk + (lane & 3) + 4]);
            }
#pragma unroll
            for (int mt = 0; mt < 2; mt++) {
                int r = wm * 32 + mt * 16 + (lane >> 2);
                uint32_t a0 = __float_as_uint(sA[r * SA_STR + kk + (lane & 3)]);
                uint32_t a1 = __float_as_uint(sA[(r + 8) * SA_STR + kk + (lane & 3)]);
                uint32_t a2 = __float_as_uint(sA[r * SA_STR + kk + (lane & 3) + 4]);
                uint32_t a3 = __float_as_uint(sA[(r + 8) * SA_STR + kk + (lane & 3) + 4]);
#pragma unroll
                for (int nt = 0; nt < 8; nt++) {
                    asm volatile(
                        "mma.sync.aligned.m16n8k8.row.col.f32.tf32.tf32.f32 "
                        "{%0,%1,%2,%3}, {%4,%5,%6,%7}, {%8,%9}, {%0,%1,%2,%3};"
                        : "+f"(acc[mt][nt][0]), "+f"(acc[mt][nt][1]),
                          "+f"(acc[mt][nt][2]), "+f"(acc[mt][nt][3])
                        : "r"(a0), "r"(a1), "r"(a2), "r"(a3),
                          "r"(bf[nt][0]), "r"(bf[nt][1]));
                }
            }
        }
        if (i + 2 < NT) load_stage((i + 2) % 3, i + 2);
    }

    // writeback
#pragma unroll
    for (int mt = 0; mt < 2; mt++) {
        int r = m0 + wm * 32 + mt * 16 + (lane >> 2);
#pragma unroll
        for (int nt = 0; nt < 8; nt++) {
            int cn = n0 + wn * 64 + nt * 8 + (lane & 3) * 2;
            *(float2*)(C + (size_t)r * N + cn) =
                make_float2(acc[mt][nt][0], acc[mt][nt][1]);
            *(float2*)(C + (size_t)(r + 8) * N + cn) =
                make_float2(acc[mt][nt][2], acc[mt][nt][3]);
        }
    }
}

// ---------------------------------------------------------------------------
// transpose + tf32-round: out[C][R] = round(in[R][C])
// ---------------------------------------------------------------------------
__global__ __launch_bounds__(256)
void transpose_k(const float* __restrict__ in, float* __restrict__ out,
                 int R, int C)
{
    __shared__ float t[32][33];
    int cb = blockIdx.x * 32, rb = blockIdx.y * 32;
    int x = threadIdx.x & 31, y = threadIdx.x >> 5;
#pragma unroll
    for (int j = 0; j < 32; j += 8)
        t[y + j][x] = in[(size_t)(rb + y + j) * C + cb + x];
    __syncthreads();
#pragma unroll
    for (int j = 0; j < 32; j += 8)
        out[(size_t)(cb + y + j) * R + rb + x] = tf32r(t[x][y + j]);
}

// round-copy / in-place round
__global__ void roundcopy_k(const float* __restrict__ in, float* __restrict__ o,
                            int n)
{
    int i = blockIdx.x * 256 + threadIdx.x;
    if (i < n) o[i] = tf32r(in[i]);
}

// ---------------------------------------------------------------------------
// SIMT split-K SGEMM (tall-skinny rank-128 projections)
// ---------------------------------------------------------------------------
template <int ATOMIC>
__global__ __launch_bounds__(256)
void sgemm_k(const float* __restrict__ A, const float* __restrict__ B,
             float* __restrict__ C, int M, int N, int K, int kSplit)
{
    __shared__ __align__(16) float As[8][128];
    __shared__ __align__(16) float Bs[8][128];

    const int tid  = threadIdx.x;
    const int bm   = blockIdx.y;
    const int bn   = blockIdx.x;
    const int k0   = blockIdx.z * kSplit;

    const int arow = tid >> 1;
    const int acol = (tid & 1) << 2;
    const int brow = tid >> 5;
    const int bcol = (tid & 31) << 2;
    const int ty   = tid >> 4;
    const int tx   = tid & 15;

    float acc[8][8];
#pragma unroll
    for (int i = 0; i < 8; i++)
#pragma unroll
        for (int j = 0; j < 8; j++) acc[i][j] = 0.f;

    const float* Ag = A + (size_t)(bm * 128 + arow) * K;
    const float* Bg = B + (size_t)(bn * 128) + bcol;

    for (int kt = 0; kt < kSplit; kt += 8) {
        float4 av = *(const float4*)(Ag + (k0 + kt + acol));
        As[acol + 0][arow] = av.x;
        As[acol + 1][arow] = av.y;
        As[acol + 2][arow] = av.z;
        As[acol + 3][arow] = av.w;
        *(float4*)&Bs[brow][bcol] =
            *(const float4*)(Bg + (size_t)(k0 + kt + brow) * N);
        __syncthreads();

#pragma unroll
        for (int kk = 0; kk < 8; kk++) {
            float4 a0 = *(const float4*)&As[kk][ty * 8];
            float4 a1 = *(const float4*)&As[kk][ty * 8 + 4];
            float4 b0 = *(const float4*)&Bs[kk][tx * 8];
            float4 b1 = *(const float4*)&Bs[kk][tx * 8 + 4];
            float a[8] = {a0.x, a0.y, a0.z, a0.w, a1.x, a1.y, a1.z, a1.w};
            float b[8] = {b0.x, b0.y, b0.z, b0.w, b1.x, b1.y, b1.z, b1.w};
#pragma unroll
            for (int i = 0; i < 8; i++)
#pragma unroll
                for (int j = 0; j < 8; j++)
                    acc[i][j] = fmaf(a[i], b[j], acc[i][j]);
        }
        __syncthreads();
    }

#pragma unroll
    for (int i = 0; i < 8; i++) {
        float* Cp = C + (size_t)(bm * 128 + ty * 8 + i) * N + bn * 128 + tx * 8;
        if (ATOMIC) {
#pragma unroll
            for (int j = 0; j < 8; j++) atomicAdd(Cp + j, acc[i][j]);
        } else {
            *(float4*)(Cp + 0) = make_float4(acc[i][0], acc[i][1], acc[i][2], acc[i][3]);
            *(float4*)(Cp + 4) = make_float4(acc[i][4], acc[i][5], acc[i][6], acc[i][7]);
        }
    }
}

__global__ void zero_k(float* __restrict__ p, int n)
{
    int i = blockIdx.x * 256 + threadIdx.x;
    if (i < n) p[i] = 0.f;
}

// ---------------------------------------------------------------------------
// depthwise causal conv (K=4) + SiLU
// ---------------------------------------------------------------------------
__global__ __launch_bounds__(256)
void conv_silu_k(const float* __restrict__ i0, const float* __restrict__ i1,
                 const float* __restrict__ i2,
                 const float* __restrict__ w0, const float* __restrict__ w1,
                 const float* __restrict__ w2,
                 float* __restrict__ o0, float* __restrict__ o1,
                 float* __restrict__ o2)
{
    const float* in; const float* w; float* out;
    if (blockIdx.y == 0)      { in = i0; w = w0; out = o0; }
    else if (blockIdx.y == 1) { in = i1; w = w1; out = o1; }
    else                      { in = i2; w = w2; out = o2; }

    int idx = blockIdx.x * 256 + threadIdx.x;
    int t = idx >> 11;
    int c = idx & (KD - 1);
    float acc = 0.f;
#pragma unroll
    for (int j = 0; j < 4; j++) {
        int tt = t + j - 3;
        if (tt >= 0) acc = fmaf(w[j * KD + c], in[(size_t)tt * KD + c], acc);
    }
    out[idx] = acc / (1.f + expf(-acc));
}

// ---------------------------------------------------------------------------
// gate prep: eg = exp(-exp(A_log[h]) * softplus_stable(graw + dt_bias))
// ---------------------------------------------------------------------------
__global__ __launch_bounds__(256)
void gprep_k(float* __restrict__ eg, const float* __restrict__ dt_bias,
             const float* __restrict__ A_log)
{
    int idx = blockIdx.x * 256 + threadIdx.x;
    int c = idx & (KD - 1);
    int h = c >> 7;
    float xr = eg[idx] + dt_bias[c];
    xr = fminf(fmaxf(xr, -20.f), 20.f);
    float sp = log1pf(expf(xr));
    float g = -expf(A_log[h]) * sp;
    eg[idx] = expf(g);
}

// ---------------------------------------------------------------------------
// beta = sigmoid(x @ Wb)
// ---------------------------------------------------------------------------
__global__ __launch_bounds__(512)
void beta_k(const float* __restrict__ x, const float* __restrict__ Wb,
            float* __restrict__ beta)
{
    __shared__ float sx[DM];
    int t = blockIdx.x;
    for (int i = threadIdx.x; i < DM; i += 512) sx[i] = x[(size_t)t * DM + i];
    __syncthreads();
    int h = threadIdx.x >> 5, lane = threadIdx.x & 31;
    float acc = 0.f;
    for (int k = lane; k < DM; k += 32) acc = fmaf(sx[k], Wb[k * NH + h], acc);
#pragma unroll
    for (int m = 16; m > 0; m >>= 1) acc += __shfl_xor_sync(0xffffffffu, acc, m);
    if (lane == 0) beta[t * NH + h] = 1.f / (1.f + expf(-acc));
}

__device__ __forceinline__ float block128_sum(float v, float* shm)
{
#pragma unroll
    for (int m = 16; m > 0; m >>= 1) v += __shfl_xor_sync(0xffffffffu, v, m);
    int w = threadIdx.x >> 5;
    if ((threadIdx.x & 31) == 0) shm[w] = v;
    __syncthreads();
    return shm[0] + shm[1] + shm[2] + shm[3];
}

__global__ __launch_bounds__(128)
void l2norm_k(float* __restrict__ p, float scale)
{
    __shared__ float shm[4];
    int t = blockIdx.x, h = blockIdx.y, d = threadIdx.x;
    size_t idx = (size_t)t * KD + h * DH + d;
    float v = p[idx];
    float ss = block128_sum(v * v, shm);
    p[idx] = v * rsqrtf(ss + 1e-6f) * scale;
}

// ---------------------------------------------------------------------------
// gated delta recurrence: one warp per V-column
// ---------------------------------------------------------------------------
__global__ __launch_bounds__(256)
void recur_k(const float* __restrict__ qf, const float* __restrict__ kf,
             const float* __restrict__ vv, const float* __restrict__ eg,
             const float* __restrict__ beta, float* __restrict__ o)
{
    __shared__ __align__(16) float sq[2][128];
    __shared__ __align__(16) float sk[2][128];
    __shared__ __align__(16) float se[2][128];
    __shared__ float sv[2][8];
    __shared__ float sb[2];

    const int tid     = threadIdx.x;
    const int wid     = tid >> 5;
    const int lane    = tid & 31;
    const int colbase = blockIdx.x * 8;
    const int head    = colbase >> 7;
    const int col     = colbase + wid;

    {
        size_t off = (size_t)head * DH;
        if (tid < 128) {
            sq[0][tid] = qf[off + tid];
            se[0][tid] = eg[off + tid];
        } else {
            int i = tid - 128;
            sk[0][i] = kf[off + i];
            if (i < 8)  sv[0][i] = vv[colbase + i];
            if (i == 8) sb[0] = beta[head];
        }
    }

    float s0 = 0.f, s1 = 0.f, s2 = 0.f, s3 = 0.f;

    for (int t = 0; t < T_LEN; t++) {
        const int buf = t & 1;
        __syncthreads();

        if (t + 1 < T_LEN) {
            size_t off = (size_t)(t + 1) * KD + head * DH;
            if (tid < 128) {
                sq[buf ^ 1][tid] = qf[off + tid];
                se[buf ^ 1][tid] = eg[off + tid];
            } else {
                int i = tid - 128;
                sk[buf ^ 1][i] = kf[off + i];
                if (i < 8)  sv[buf ^ 1][i] = vv[(size_t)(t + 1) * KD + colbase + i];
                if (i == 8) sb[buf ^ 1] = beta[(t + 1) * NH + head];
            }
        }

        float4 egv = ((const float4*)se[buf])[lane];
        float4 kv  = ((const float4*)sk[buf])[lane];
        float4 qv  = ((const float4*)sq[buf])[lane];
        float vval = sv[buf][wid];
        float bet  = sb[buf];

        s0 *= egv.x; s1 *= egv.y; s2 *= egv.z; s3 *= egv.w;

        float inner = s0 * kv.x + s1 * kv.y + s2 * kv.z + s3 * kv.w;
#pragma unroll
        for (int m = 16; m > 0; m >>= 1)
            inner += __shfl_xor_sync(0xffffffffu, inner, m);

        float upd = bet * (vval - inner);
        s0 = fmaf(kv.x, upd, s0);
        s1 = fmaf(kv.y, upd, s1);
        s2 = fmaf(kv.z, upd, s2);
        s3 = fmaf(kv.w, upd, s3);

        float oc = s0 * qv.x + s1 * qv.y + s2 * qv.z + s3 * qv.w;
#pragma unroll
        for (int m = 16; m > 0; m >>= 1)
            oc += __shfl_xor_sync(0xffffffffu, oc, m);
        if (lane == 0) o[(size_t)t * KD + col] = oc;
    }
}

// ---------------------------------------------------------------------------
// epilogue: og = round(o * rsqrt(mean(o^2)+eps) * norm_w * sigmoid(gout))
// ---------------------------------------------------------------------------
__global__ __launch_bounds__(128)
void epi_k(const float* __restrict__ o, const float* __restrict__ gout,
           const float* __restrict__ norm_w, float* __restrict__ og)
{
    __shared__ float shm[4];
    int t = blockIdx.x, h = blockIdx.y, d = threadIdx.x;
    size_t idx = (size_t)t * KD + h * DH + d;
    float ov = o[idx];
    float ss = block128_sum(ov * ov, shm);
    float rstd = rsqrtf(ss * (1.f / 128.f) + 1e-6f);
    float gate = 1.f / (1.f + expf(-gout[idx]));
    og[idx] = tf32r(ov * rstd * norm_w[d] * gate);
}

// ---------------------------------------------------------------------------
// launch
// ---------------------------------------------------------------------------
extern "C" void kernel_launch(void* const* d_in, const int* in_sizes, int n_in,
                              void* d_out, int out_size)
{
    (void)in_sizes; (void)n_in; (void)out_size;
    const float* x      = (const float*)d_in[0];
    const float* Wq     = (const float*)d_in[1];
    const float* Wk     = (const float*)d_in[2];
    const float* Wv     = (const float*)d_in[3];
    const float* conv_q = (const float*)d_in[4];
    const float* conv_k = (const float*)d_in[5];
    const float* conv_v = (const float*)d_in[6];
    const float* Wfa    = (const float*)d_in[7];
    const float* Wfb    = (const float*)d_in[8];
    const float* dt_b   = (const float*)d_in[9];
    const float* A_log  = (const float*)d_in[10];
    const float* Wb     = (const float*)d_in[11];
    const float* Wga    = (const float*)d_in[12];
    const float* Wgb    = (const float*)d_in[13];
    const float* norm_w = (const float*)d_in[14];
    const float* Wo     = (const float*)d_in[15];
    float* out = (float*)d_out;

    float* s = nullptr;
    cudaGetSymbolAddress((void**)&s, g_scratch);
    float* q0   = s + OFF_Q0;
    float* k0   = s + OFF_K0;
    float* v0   = s + OFF_V0;
    float* qc   = s + OFF_QC;
    float* kc   = s + OFF_KC;
    float* vc   = s + OFF_VC;
    float* eg   = s + OFF_EG;
    float* gout = s + OFF_GOUT;
    float* o    = s + OFF_O;
    float* og   = s + OFF_OG;
    float* xr   = s + OFF_XR;
    float* fa   = s + OFF_FA;
    float* ga   = s + OFF_GA;
    float* beta = s + OFF_BETA;
    float* WqT  = s + OFF_WQT;
    float* WkT  = s + OFF_WKT;
    float* WvT  = s + OFF_WVT;
    float* WoT  = s + OFF_WOT;
    float* WfbT = s + OFF_WFBT;
    float* WgbT = s + OFF_WGBT;

    cudaFuncSetAttribute(mmagemm_k, cudaFuncAttributeMaxDynamicSharedMemorySize,
                         MMA_SMEM);

    // weight transposes ([K,N] -> [N,K] K-major, tf32-rounded)
    transpose_k<<<dim3(64, 64), 256>>>(Wq,  WqT,  DM, KD);
    transpose_k<<<dim3(64, 64), 256>>>(Wk,  WkT,  DM, KD);
    transpose_k<<<dim3(64, 64), 256>>>(Wv,  WvT,  DM, KD);
    transpose_k<<<dim3(64, 64), 256>>>(Wo,  WoT,  KD, DM);
    transpose_k<<<dim3(64, 4),  256>>>(Wfb, WfbT, DH, KD);
    transpose_k<<<dim3(64, 4),  256>>>(Wgb, WgbT, DH, KD);

    // tf32-rounded copy of x (A operand of q/k/v GEMMs)
    roundcopy_k<<<(unsigned)(NTK / 256), 256>>>(x, xr, (int)NTK);

    dim3 gBig(16, 8);   // N/128 x M/128

    // q/k/v projections (tf32 tensor cores)
    mmagemm_k<<<gBig, 256, MMA_SMEM>>>(xr, WqT, q0, T_LEN, KD, DM);
    mmagemm_k<<<gBig, 256, MMA_SMEM>>>(xr, WkT, k0, T_LEN, KD, DM);
    mmagemm_k<<<gBig, 256, MMA_SMEM>>>(xr, WvT, v0, T_LEN, KD, DM);

    // causal depthwise conv + silu
    conv_silu_k<<<dim3((unsigned)(NTK / 256), 3), 256>>>(
        q0, k0, v0, conv_q, conv_k, conv_v, qc, kc, vc);

    // low-rank gate chains: skinny stage SIMT split-K, wide stage tf32 MMA
    zero_k<<<1024, 256>>>(fa, 262144);
    sgemm_k<1><<<dim3(1, 8, 16), 256>>>(x, Wfa, fa, T_LEN, DH, DM, 128);
    sgemm_k<1><<<dim3(1, 8, 16), 256>>>(x, Wga, ga, T_LEN, DH, DM, 128);
    roundcopy_k<<<1024, 256>>>(fa, fa, 262144);   // round fa+ga in place
    mmagemm_k<<<gBig, 256, MMA_SMEM>>>(fa, WfbT, eg,   T_LEN, KD, DH);
    mmagemm_k<<<gBig, 256, MMA_SMEM>>>(ga, WgbT, gout, T_LEN, KD, DH);

    // gate prep, beta, qk l2norm
    gprep_k<<<(unsigned)(NTK / 256), 256>>>(eg, dt_b, A_log);
    beta_k<<<T_LEN, 512>>>(x, Wb, beta);
    l2norm_k<<<dim3(T_LEN, NH), 128>>>(qc, 0.08838834764831845f);
    l2norm_k<<<dim3(T_LEN, NH), 128>>>(kc, 1.0f);

    // gated delta recurrence
    recur_k<<<256, 256>>>(qc, kc, vc, eg, beta, o);

    // gated rmsnorm epilogue + output projection
    epi_k<<<dim3(T_LEN, NH), 128>>>(o, gout, norm_w, og);
    mmagemm_k<<<gBig, 256, MMA_SMEM>>>(og, WoT, out, T_LEN, DM, KD);
}

// round 5
// speedup vs baseline: 2.3518x; 1.2652x over previous
#include <cuda_runtime.h>
#include <math.h>
#include <cstdint>

// ---------------------------------------------------------------------------
// KimiDeltaAttention  (B=1, T=1024, DM=2048, H=16, DH=128, KD=2048, KC=4)
// Round 4: tf32 mma.sync GEMMs + restructured recurrence.
//   - qkv fused into ONE GEMM (N=6144), launch_bounds(256,2) for 2 CTA/SM
//   - recurrence: 16 lanes/column, single 4-level butterfly with 3
//     interleaved reduction chains, no smem/no barriers, register prefetch
//   - conv+silu+l2norm fused into one kernel
// ---------------------------------------------------------------------------

#define T_LEN 1024
#define DM    2048
#define NH    16
#define DH    128
#define KD    2048

static constexpr size_t NTK = (size_t)T_LEN * KD;   // 2097152

#define OFF_QKV  ((size_t)0)                  // fused q|k|v GEMM out [T][6144]
#define OFF_QC   (NTK * 3)
#define OFF_KC   (NTK * 4)
#define OFF_VC   (NTK * 5)
#define OFF_EG   (NTK * 6)
#define OFF_GOUT (NTK * 7)
#define OFF_O    (NTK * 8)
#define OFF_OG   (NTK * 9)
#define OFF_XR   (NTK * 10)
#define OFF_FA   (NTK * 11)
#define OFF_GA   (NTK * 11 + 131072)
#define OFF_BETA (NTK * 11 + 262144)
#define OFF_WQT  (NTK * 11 + 278528)
#define OFF_WKT  (OFF_WQT + 4194304)
#define OFF_WVT  (OFF_WKT + 4194304)
#define OFF_WOT  (OFF_WVT + 4194304)
#define OFF_WFBT (OFF_WOT + 4194304)
#define OFF_WGBT (OFF_WFBT + 262144)
#define SCRATCH_FLOATS (OFF_WGBT + 262144)

__device__ float g_scratch[SCRATCH_FLOATS];

// ---------------------------------------------------------------------------
// helpers
// ---------------------------------------------------------------------------
__device__ __forceinline__ uint32_t smem_u32(const void* p) {
    uint32_t a;
    asm("{ .reg .u64 t; cvta.to.shared.u64 t, %1; cvt.u32.u64 %0, t; }"
        : "=r"(a) : "l"(p));
    return a;
}

__device__ __forceinline__ void cp16(uint32_t dst, const void* src) {
    asm volatile("cp.async.cg.shared.global [%0], [%1], 16;"
                 :: "r"(dst), "l"(src) : "memory");
}
#define CP_COMMIT() asm volatile("cp.async.commit_group;" ::: "memory")
#define CP_WAIT(n)  asm volatile("cp.async.wait_group %0;" :: "n"(n) : "memory")

// unbiased fp32 -> tf32 rounding
__device__ __forceinline__ float tf32r(float x) {
    uint32_t u;
    asm("cvt.rna.tf32.f32 %0, %1;" : "=r"(u) : "f"(x));
    return __uint_as_float(u);
}

// ---------------------------------------------------------------------------
// tf32 mma.sync GEMM: C[M,N] = A[M,K] * Bt[N,K]^T  (row-major fp32, tf32-
// pre-rounded inputs). grid (N/128, M/128), 256 threads, 2 CTA/SM.
// ---------------------------------------------------------------------------
#define SA_STR   20
#define STAGE_F  (128 * SA_STR)
#define MMA_SMEM (3 * 2 * STAGE_F * 4)   // 61440 bytes

__global__ __launch_bounds__(256, 2)
void mmagemm_k(const float* __restrict__ A, const float* __restrict__ Bt,
               float* __restrict__ C, int M, int N, int K)
{
    extern __shared__ float sbase[];

    const int tid  = threadIdx.x;
    const int wid  = tid >> 5;
    const int lane = tid & 31;
    const int wm   = wid >> 1;
    const int wn   = wid & 1;
    const int m0   = blockIdx.y * 128;
    const int n0   = blockIdx.x * 128;
    const int NT   = K >> 4;

    float acc[2][8][4];
#pragma unroll
    for (int a = 0; a < 2; a++)
#pragma unroll
        for (int b = 0; b < 8; b++)
#pragma unroll
            for (int c = 0; c < 4; c++) acc[a][b][c] = 0.f;

    auto load_stage = [&](int s, int i) {
        const float* gA = A  + (size_t)m0 * K + i * 16;
        const float* gB = Bt + (size_t)n0 * K + i * 16;
        float* dA = sbase + s * 2 * STAGE_F;
        float* dB = dA + STAGE_F;
#pragma unroll
        for (int t = 0; t < 2; t++) {
            int c   = tid + t * 256;
            int row = c >> 2;
            int c4  = (c & 3) * 4;
            cp16(smem_u32(dA + row * SA_STR + c4), gA + (size_t)row * K + c4);
            cp16(smem_u32(dB + row * SA_STR + c4), gB + (size_t)row * K + c4);
        }
        CP_COMMIT();
    };

    load_stage(0, 0);
    load_stage(1, 1);

    for (int i = 0; i < NT; i++) {
        const int s = i % 3;
        if (i + 1 < NT) { CP_WAIT(1); } else { CP_WAIT(0); }
        __syncthreads();

        const float* sA = sbase + s * 2 * STAGE_F;
        const float* sB = sA + STAGE_F;

#pragma unroll
        for (int kk = 0; kk < 16; kk += 8) {
            uint32_t bf[8][2];
#pragma unroll
            for (int nt = 0; nt < 8; nt++) {
                int n = wn * 64 + nt * 8 + (lane >> 2);
                bf[nt][0] = __float_as_uint(sB[n * SA_STR + kk + (lane & 3)]);
                bf[nt][1] = __float_as_uint(sB[n * SA_STR + kk + (lane & 3) + 4]);
            }
#pragma unroll
            for (int mt = 0; mt < 2; mt++) {
                int r = wm * 32 + mt * 16 + (lane >> 2);
                uint32_t a0 = __float_as_uint(sA[r * SA_STR + kk + (lane & 3)]);
                uint32_t a1 = __float_as_uint(sA[(r + 8) * SA_STR + kk + (lane & 3)]);
                uint32_t a2 = __float_as_uint(sA[r * SA_STR + kk + (lane & 3) + 4]);
                uint32_t a3 = __float_as_uint(sA[(r + 8) * SA_STR + kk + (lane & 3) + 4]);
#pragma unroll
                for (int nt = 0; nt < 8; nt++) {
                    asm volatile(
                        "mma.sync.aligned.m16n8k8.row.col.f32.tf32.tf32.f32 "
                        "{%0,%1,%2,%3}, {%4,%5,%6,%7}, {%8,%9}, {%0,%1,%2,%3};"
                        : "+f"(acc[mt][nt][0]), "+f"(acc[mt][nt][1]),
                          "+f"(acc[mt][nt][2]), "+f"(acc[mt][nt][3])
                        : "r"(a0), "r"(a1), "r"(a2), "r"(a3),
                          "r"(bf[nt][0]), "r"(bf[nt][1]));
                }
            }
        }
        if (i + 2 < NT) load_stage((i + 2) % 3, i + 2);
    }

#pragma unroll
    for (int mt = 0; mt < 2; mt++) {
        int r = m0 + wm * 32 + mt * 16 + (lane >> 2);
#pragma unroll
        for (int nt = 0; nt < 8; nt++) {
            int cn = n0 + wn * 64 + nt * 8 + (lane & 3) * 2;
            *(float2*)(C + (size_t)r * N + cn) =
                make_float2(acc[mt][nt][0], acc[mt][nt][1]);
            *(float2*)(C + (size_t)(r + 8) * N + cn) =
                make_float2(acc[mt][nt][2], acc[mt][nt][3]);
        }
    }
}

// ---------------------------------------------------------------------------
// transpose + tf32-round
// ---------------------------------------------------------------------------
__global__ __launch_bounds__(256)
void transpose_k(const float* __restrict__ in, float* __restrict__ out,
                 int R, int C)
{
    __shared__ float t[32][33];
    int cb = blockIdx.x * 32, rb = blockIdx.y * 32;
    int x = threadIdx.x & 31, y = threadIdx.x >> 5;
#pragma unroll
    for (int j = 0; j < 32; j += 8)
        t[y + j][x] = in[(size_t)(rb + y + j) * C + cb + x];
    __syncthreads();
#pragma unroll
    for (int j = 0; j < 32; j += 8)
        out[(size_t)(cb + y + j) * R + rb + x] = tf32r(t[x][y + j]);
}

__global__ void roundcopy_k(const float* __restrict__ in, float* __restrict__ o,
                            int n)
{
    int i = blockIdx.x * 256 + threadIdx.x;
    if (i < n) o[i] = tf32r(in[i]);
}

// ---------------------------------------------------------------------------
// SIMT split-K SGEMM (tall-skinny rank-128 projections)
// ---------------------------------------------------------------------------
template <int ATOMIC>
__global__ __launch_bounds__(256)
void sgemm_k(const float* __restrict__ A, const float* __restrict__ B,
             float* __restrict__ C, int M, int N, int K, int kSplit)
{
    __shared__ __align__(16) float As[8][128];
    __shared__ __align__(16) float Bs[8][128];

    const int tid  = threadIdx.x;
    const int bm   = blockIdx.y;
    const int bn   = blockIdx.x;
    const int k0   = blockIdx.z * kSplit;

    const int arow = tid >> 1;
    const int acol = (tid & 1) << 2;
    const int brow = tid >> 5;
    const int bcol = (tid & 31) << 2;
    const int ty   = tid >> 4;
    const int tx   = tid & 15;

    float acc[8][8];
#pragma unroll
    for (int i = 0; i < 8; i++)
#pragma unroll
        for (int j = 0; j < 8; j++) acc[i][j] = 0.f;

    const float* Ag = A + (size_t)(bm * 128 + arow) * K;
    const float* Bg = B + (size_t)(bn * 128) + bcol;

    for (int kt = 0; kt < kSplit; kt += 8) {
        float4 av = *(const float4*)(Ag + (k0 + kt + acol));
        As[acol + 0][arow] = av.x;
        As[acol + 1][arow] = av.y;
        As[acol + 2][arow] = av.z;
        As[acol + 3][arow] = av.w;
        *(float4*)&Bs[brow][bcol] =
            *(const float4*)(Bg + (size_t)(k0 + kt + brow) * N);
        __syncthreads();

#pragma unroll
        for (int kk = 0; kk < 8; kk++) {
            float4 a0 = *(const float4*)&As[kk][ty * 8];
            float4 a1 = *(const float4*)&As[kk][ty * 8 + 4];
            float4 b0 = *(const float4*)&Bs[kk][tx * 8];
            float4 b1 = *(const float4*)&Bs[kk][tx * 8 + 4];
            float a[8] = {a0.x, a0.y, a0.z, a0.w, a1.x, a1.y, a1.z, a1.w};
            float b[8] = {b0.x, b0.y, b0.z, b0.w, b1.x, b1.y, b1.z, b1.w};
#pragma unroll
            for (int i = 0; i < 8; i++)
#pragma unroll
                for (int j = 0; j < 8; j++)
                    acc[i][j] = fmaf(a[i], b[j], acc[i][j]);
        }
        __syncthreads();
    }

#pragma unroll
    for (int i = 0; i < 8; i++) {
        float* Cp = C + (size_t)(bm * 128 + ty * 8 + i) * N + bn * 128 + tx * 8;
        if (ATOMIC) {
#pragma unroll
            for (int j = 0; j < 8; j++) atomicAdd(Cp + j, acc[i][j]);
        } else {
            *(float4*)(Cp + 0) = make_float4(acc[i][0], acc[i][1], acc[i][2], acc[i][3]);
            *(float4*)(Cp + 4) = make_float4(acc[i][4], acc[i][5], acc[i][6], acc[i][7]);
        }
    }
}

__global__ void zero_k(float* __restrict__ p, int n)
{
    int i = blockIdx.x * 256 + threadIdx.x;
    if (i < n) p[i] = 0.f;
}

// ---------------------------------------------------------------------------
// block-of-128 reduce helper
// ---------------------------------------------------------------------------
__device__ __forceinline__ float block128_sum(float v, float* shm)
{
#pragma unroll
    for (int m = 16; m > 0; m >>= 1) v += __shfl_xor_sync(0xffffffffu, v, m);
    int w = threadIdx.x >> 5;
    if ((threadIdx.x & 31) == 0) shm[w] = v;
    __syncthreads();
    return shm[0] + shm[1] + shm[2] + shm[3];
}

// ---------------------------------------------------------------------------
// fused: depthwise causal conv (K=4) + SiLU for q,k,v  +  l2norm of q,k
// qkv: [T][6144] (q | k | v).  grid (T, NH), block 128.
// ---------------------------------------------------------------------------
__global__ __launch_bounds__(128)
void conv_l2_k(const float* __restrict__ qkv,
               const float* __restrict__ wq, const float* __restrict__ wk,
               const float* __restrict__ wv,
               float* __restrict__ qc, float* __restrict__ kc,
               float* __restrict__ vc)
{
    __shared__ float shm[4];
    int t = blockIdx.x, h = blockIdx.y, d = threadIdx.x;
    int c = h * DH + d;
    float aq = 0.f, ak = 0.f, av = 0.f;
#pragma unroll
    for (int j = 0; j < 4; j++) {
        int tt = t + j - 3;
        if (tt >= 0) {
            size_t base = (size_t)tt * 6144;
            aq = fmaf(wq[j * KD + c], qkv[base + c], aq);
            ak = fmaf(wk[j * KD + c], qkv[base + 2048 + c], ak);
            av = fmaf(wv[j * KD + c], qkv[base + 4096 + c], av);
        }
    }
    aq = aq / (1.f + expf(-aq));
    ak = ak / (1.f + expf(-ak));
    av = av / (1.f + expf(-av));

    size_t idx = (size_t)t * KD + c;
    vc[idx] = av;

    float ssq = block128_sum(aq * aq, shm);
    __syncthreads();
    float ssk = block128_sum(ak * ak, shm);
    qc[idx] = aq * rsqrtf(ssq + 1e-6f) * 0.08838834764831845f;
    kc[idx] = ak * rsqrtf(ssk + 1e-6f);
}

// ---------------------------------------------------------------------------
// gate prep: eg = exp(-exp(A_log[h]) * softplus_stable(graw + dt_bias))
// ---------------------------------------------------------------------------
__global__ __launch_bounds__(256)
void gprep_k(float* __restrict__ eg, const float* __restrict__ dt_bias,
             const float* __restrict__ A_log)
{
    int idx = blockIdx.x * 256 + threadIdx.x;
    int c = idx & (KD - 1);
    int h = c >> 7;
    float xr = eg[idx] + dt_bias[c];
    xr = fminf(fmaxf(xr, -20.f), 20.f);
    float sp = log1pf(expf(xr));
    float g = -expf(A_log[h]) * sp;
    eg[idx] = expf(g);
}

// ---------------------------------------------------------------------------
// beta = sigmoid(x @ Wb)
// ---------------------------------------------------------------------------
__global__ __launch_bounds__(512)
void beta_k(const float* __restrict__ x, const float* __restrict__ Wb,
            float* __restrict__ beta)
{
    __shared__ float sx[DM];
    int t = blockIdx.x;
    for (int i = threadIdx.x; i < DM; i += 512) sx[i] = x[(size_t)t * DM + i];
    __syncthreads();
    int h = threadIdx.x >> 5, lane = threadIdx.x & 31;
    float acc = 0.f;
    for (int k = lane; k < DM; k += 32) acc = fmaf(sx[k], Wb[k * NH + h], acc);
#pragma unroll
    for (int m = 16; m > 0; m >>= 1) acc += __shfl_xor_sync(0xffffffffu, acc, m);
    if (lane == 0) beta[t * NH + h] = 1.f / (1.f + expf(-acc));
}

// ---------------------------------------------------------------------------
// gated delta recurrence, v2: 16 lanes per column (2 cols/warp),
// 8 state floats/lane, no smem/no barriers, single 4-level butterfly with
// three interleaved reduction chains (k.S', q.S', q.k), register prefetch.
// grid: 128 CTAs x 256 threads (16 columns per CTA, all in one head).
// ---------------------------------------------------------------------------
__global__ __launch_bounds__(256)
void recur2_k(const float* __restrict__ qf, const float* __restrict__ kf,
              const float* __restrict__ vv, const float* __restrict__ eg,
              const float* __restrict__ beta, float* __restrict__ o)
{
    const int tid  = threadIdx.x;
    const int wid  = tid >> 5;
    const int lane = tid & 31;
    const int sub  = lane >> 4;            // column within warp
    const int l16  = lane & 15;
    const int colbase = blockIdx.x * 16;   // same head for whole CTA
    const int head = colbase >> 7;
    const int col  = colbase + wid * 2 + sub;
    const int j0   = head * DH + l16 * 8;  // this lane's 8 k-dims

    float s[8];
#pragma unroll
    for (int i = 0; i < 8; i++) s[i] = 0.f;

    float4 kv0, kv1, qv0, qv1, ev0, ev1;
    float vcur, bcur;
    kv0 = *(const float4*)(kf + j0); kv1 = *(const float4*)(kf + j0 + 4);
    qv0 = *(const float4*)(qf + j0); qv1 = *(const float4*)(qf + j0 + 4);
    ev0 = *(const float4*)(eg + j0); ev1 = *(const float4*)(eg + j0 + 4);
    vcur = vv[col];
    bcur = beta[head];

    for (int t = 0; t < T_LEN; t++) {
        // prefetch t+1 (clamped)
        int tn = (t + 1 < T_LEN) ? t + 1 : t;
        size_t off = (size_t)tn * KD + j0;
        float4 nk0 = *(const float4*)(kf + off);
        float4 nk1 = *(const float4*)(kf + off + 4);
        float4 nq0 = *(const float4*)(qf + off);
        float4 nq1 = *(const float4*)(qf + off + 4);
        float4 ne0 = *(const float4*)(eg + off);
        float4 ne1 = *(const float4*)(eg + off + 4);
        float  nv  = vv[(size_t)tn * KD + col];
        float  nb  = beta[tn * NH + head];

        // decay
        s[0] *= ev0.x; s[1] *= ev0.y; s[2] *= ev0.z; s[3] *= ev0.w;
        s[4] *= ev1.x; s[5] *= ev1.y; s[6] *= ev1.z; s[7] *= ev1.w;

        // partial dots: r1 = k.S', r2 = q.S', r3 = q.k
        float r1 = s[0] * kv0.x; float r2 = s[0] * qv0.x; float r3 = kv0.x * qv0.x;
        r1 = fmaf(s[1], kv0.y, r1); r2 = fmaf(s[1], qv0.y, r2); r3 = fmaf(kv0.y, qv0.y, r3);
        r1 = fmaf(s[2], kv0.z, r1); r2 = fmaf(s[2], qv0.z, r2); r3 = fmaf(kv0.z, qv0.z, r3);
        r1 = fmaf(s[3], kv0.w, r1); r2 = fmaf(s[3], qv0.w, r2); r3 = fmaf(kv0.w, qv0.w, r3);
        r1 = fmaf(s[4], kv1.x, r1); r2 = fmaf(s[4], qv1.x, r2); r3 = fmaf(kv1.x, qv1.x, r3);
        r1 = fmaf(s[5], kv1.y, r1); r2 = fmaf(s[5], qv1.y, r2); r3 = fmaf(kv1.y, qv1.y, r3);
        r1 = fmaf(s[6], kv1.z, r1); r2 = fmaf(s[6], qv1.z, r2); r3 = fmaf(kv1.z, qv1.z, r3);
        r1 = fmaf(s[7], kv1.w, r1); r2 = fmaf(s[7], qv1.w, r2); r3 = fmaf(kv1.w, qv1.w, r3);

        // 4-level butterfly over the 16-lane group, 3 interleaved chains
#pragma unroll
        for (int m = 8; m > 0; m >>= 1) {
            r1 += __shfl_xor_sync(0xffffffffu, r1, m);
            r2 += __shfl_xor_sync(0xffffffffu, r2, m);
            r3 += __shfl_xor_sync(0xffffffffu, r3, m);
        }

        float upd = bcur * (vcur - r1);

        // state update
        s[0] = fmaf(kv0.x, upd, s[0]); s[1] = fmaf(kv0.y, upd, s[1]);
        s[2] = fmaf(kv0.z, upd, s[2]); s[3] = fmaf(kv0.w, upd, s[3]);
        s[4] = fmaf(kv1.x, upd, s[4]); s[5] = fmaf(kv1.y, upd, s[5]);
        s[6] = fmaf(kv1.z, upd, s[6]); s[7] = fmaf(kv1.w, upd, s[7]);

        // o = q.S_new = r2 + r3*upd
        if (l16 == 0) o[(size_t)t * KD + col] = fmaf(r3, upd, r2);

        kv0 = nk0; kv1 = nk1; qv0 = nq0; qv1 = nq1; ev0 = ne0; ev1 = ne1;
        vcur = nv; bcur = nb;
    }
}

// ---------------------------------------------------------------------------
// epilogue: og = round(o * rsqrt(mean(o^2)+eps) * norm_w * sigmoid(gout))
// ---------------------------------------------------------------------------
__global__ __launch_bounds__(128)
void epi_k(const float* __restrict__ o, const float* __restrict__ gout,
           const float* __restrict__ norm_w, float* __restrict__ og)
{
    __shared__ float shm[4];
    int t = blockIdx.x, h = blockIdx.y, d = threadIdx.x;
    size_t idx = (size_t)t * KD + h * DH + d;
    float ov = o[idx];
    float ss = block128_sum(ov * ov, shm);
    float rstd = rsqrtf(ss * (1.f / 128.f) + 1e-6f);
    float gate = 1.f / (1.f + expf(-gout[idx]));
    og[idx] = tf32r(ov * rstd * norm_w[d] * gate);
}

// ---------------------------------------------------------------------------
// launch
// ---------------------------------------------------------------------------
extern "C" void kernel_launch(void* const* d_in, const int* in_sizes, int n_in,
                              void* d_out, int out_size)
{
    (void)in_sizes; (void)n_in; (void)out_size;
    const float* x      = (const float*)d_in[0];
    const float* Wq     = (const float*)d_in[1];
    const float* Wk     = (const float*)d_in[2];
    const float* Wv     = (const float*)d_in[3];
    const float* conv_q = (const float*)d_in[4];
    const float* conv_k = (const float*)d_in[5];
    const float* conv_v = (const float*)d_in[6];
    const float* Wfa    = (const float*)d_in[7];
    const float* Wfb    = (const float*)d_in[8];
    const float* dt_b   = (const float*)d_in[9];
    const float* A_log  = (const float*)d_in[10];
    const float* Wb     = (const float*)d_in[11];
    const float* Wga    = (const float*)d_in[12];
    const float* Wgb    = (const float*)d_in[13];
    const float* norm_w = (const float*)d_in[14];
    const float* Wo     = (const float*)d_in[15];
    float* out = (float*)d_out;

    float* s = nullptr;
    cudaGetSymbolAddress((void**)&s, g_scratch);
    float* qkv  = s + OFF_QKV;
    float* qc   = s + OFF_QC;
    float* kc   = s + OFF_KC;
    float* vc   = s + OFF_VC;
    float* eg   = s + OFF_EG;
    float* gout = s + OFF_GOUT;
    float* o    = s + OFF_O;
    float* og   = s + OFF_OG;
    float* xr   = s + OFF_XR;
    float* fa   = s + OFF_FA;
    float* ga   = s + OFF_GA;
    float* beta = s + OFF_BETA;
    float* WqT  = s + OFF_WQT;
    float* WoT  = s + OFF_WOT;
    float* WfbT = s + OFF_WFBT;
    float* WgbT = s + OFF_WGBT;

    cudaFuncSetAttribute(mmagemm_k, cudaFuncAttributeMaxDynamicSharedMemorySize,
                         MMA_SMEM);

    // weight transposes ([K,N] -> [N,K] K-major, tf32-rounded)
    // WqT|WkT|WvT are contiguous -> one [6144][2048] B matrix
    transpose_k<<<dim3(64, 64), 256>>>(Wq,  s + OFF_WQT, DM, KD);
    transpose_k<<<dim3(64, 64), 256>>>(Wk,  s + OFF_WKT, DM, KD);
    transpose_k<<<dim3(64, 64), 256>>>(Wv,  s + OFF_WVT, DM, KD);
    transpose_k<<<dim3(64, 64), 256>>>(Wo,  WoT,  KD, DM);
    transpose_k<<<dim3(64, 4),  256>>>(Wfb, WfbT, DH, KD);
    transpose_k<<<dim3(64, 4),  256>>>(Wgb, WgbT, DH, KD);

    // tf32-rounded copy of x
    roundcopy_k<<<(unsigned)(NTK / 256), 256>>>(x, xr, (int)NTK);

    // fused q|k|v projection: one GEMM, N=6144 (384 CTAs, 2 CTA/SM)
    mmagemm_k<<<dim3(48, 8), 256, MMA_SMEM>>>(xr, WqT, qkv, T_LEN, 6144, DM);

    // fused causal conv + silu + qk l2norm
    conv_l2_k<<<dim3(T_LEN, NH), 128>>>(qkv, conv_q, conv_k, conv_v,
                                        qc, kc, vc);

    // low-rank gate chains
    zero_k<<<1024, 256>>>(fa, 262144);
    sgemm_k<1><<<dim3(1, 8, 16), 256>>>(x, Wfa, fa, T_LEN, DH, DM, 128);
    sgemm_k<1><<<dim3(1, 8, 16), 256>>>(x, Wga, ga, T_LEN, DH, DM, 128);
    roundcopy_k<<<1024, 256>>>(fa, fa, 262144);   // rounds fa+ga (contiguous)
    mmagemm_k<<<dim3(16, 8), 256, MMA_SMEM>>>(fa, WfbT, eg,   T_LEN, KD, DH);
    mmagemm_k<<<dim3(16, 8), 256, MMA_SMEM>>>(ga, WgbT, gout, T_LEN, KD, DH);

    // gate prep + beta
    gprep_k<<<(unsigned)(NTK / 256), 256>>>(eg, dt_b, A_log);
    beta_k<<<T_LEN, 512>>>(x, Wb, beta);

    // gated delta recurrence (v2)
    recur2_k<<<128, 256>>>(qc, kc, vc, eg, beta, o);

    // gated rmsnorm epilogue + output projection
    epi_k<<<dim3(T_LEN, NH), 128>>>(o, gout, norm_w, og);
    mmagemm_k<<<dim3(16, 8), 256, MMA_SMEM>>>(og, WoT, out, T_LEN, DM, KD);
}

// round 7
// speedup vs baseline: 2.8869x; 1.2275x over previous
#include <cuda_runtime.h>
#include <cuda_fp16.h>
#include <math.h>
#include <cstdint>

// ---------------------------------------------------------------------------
// KimiDeltaAttention  (B=1, T=1024, DM=2048, H=16, DH=128, KD=2048, KC=4)
// Round 6 (resubmit after infra failure): fp16 mma.sync (m16n8k16) GEMMs.
//   fp16 mantissa == tf32 mantissa (10 bits) -> same accuracy, 2x rate,
//   half the operand traffic. 128x128 tile, BK=32, 3-stage cp.async,
//   80B-padded rows (conflict-free ldmatrix), 2 CTA/SM.
// ---------------------------------------------------------------------------

#define T_LEN 1024
#define DM    2048
#define NH    16
#define DH    128
#define KD    2048

static constexpr size_t NTK = (size_t)T_LEN * KD;   // 2097152

// fp32 scratch
#define OFF_QKV  ((size_t)0)                  // fused q|k|v GEMM out [T][6144]
#define OFF_QC   (NTK * 3)
#define OFF_KC   (NTK * 4)
#define OFF_VC   (NTK * 5)
#define OFF_EG   (NTK * 6)
#define OFF_GOUT (NTK * 7)
#define OFF_O    (NTK * 8)
#define OFF_FA   (NTK * 9)                    // fa | ga contiguous (fp32)
#define OFF_BETA (NTK * 9 + 262144)
#define SCRATCH_FLOATS (OFF_BETA + 16384)
__device__ float g_scratch[SCRATCH_FLOATS];

// fp16 scratch (halfs)
#define HO_W3   ((size_t)0)                   // [6144][2048]  WqT|WkT|WvT
#define HO_WO   ((size_t)12582912)            // [2048][2048]
#define HO_WFB  ((size_t)16777216)            // [2048][128]
#define HO_WGB  ((size_t)17039360)            // [2048][128]
#define HO_X    ((size_t)17301504)            // [1024][2048]
#define HO_FG   ((size_t)19398656)            // [1024][128] fa then [1024][128] ga
#define HO_OG   ((size_t)19660800)            // [1024][2048]
#define HBUF_HALFS ((size_t)21757952)
__device__ __half g_hbuf[HBUF_HALFS];

// ---------------------------------------------------------------------------
// helpers
// ---------------------------------------------------------------------------
__device__ __forceinline__ uint32_t smem_u32(const void* p) {
    uint32_t a;
    asm("{ .reg .u64 t; cvta.to.shared.u64 t, %1; cvt.u32.u64 %0, t; }"
        : "=r"(a) : "l"(p));
    return a;
}
__device__ __forceinline__ void cp16(uint32_t dst, const void* src) {
    asm volatile("cp.async.cg.shared.global [%0], [%1], 16;"
                 :: "r"(dst), "l"(src) : "memory");
}
#define CP_COMMIT() asm volatile("cp.async.commit_group;" ::: "memory")
#define CP_WAIT(n)  asm volatile("cp.async.wait_group %0;" :: "n"(n) : "memory")

#define LDMX4(r0, r1, r2, r3, addr) \
    asm volatile("ldmatrix.sync.aligned.m8n8.x4.shared.b16 {%0,%1,%2,%3}, [%4];" \
                 : "=r"(r0), "=r"(r1), "=r"(r2), "=r"(r3) : "r"(addr))

// ---------------------------------------------------------------------------
// fp16 GEMM: C[M,N](f32) = A[M,K](h, lda) * Bt[N,K](h, ldb)^T
// grid (N/128, M/128), 256 threads, 2 CTA/SM. K % 32 == 0, K >= 64.
// ---------------------------------------------------------------------------
#define H_RS    40                     // padded row stride (halfs) = 80 B
#define H_STAGE (128 * H_RS)           // halfs per matrix per stage
#define H_SMEM  (3 * 2 * H_STAGE * 2)  // 61440 bytes

__global__ __launch_bounds__(256, 2)
void hgemm_k(const __half* __restrict__ A, int lda,
             const __half* __restrict__ Bt, int ldb,
             float* __restrict__ C, int M, int N, int K)
{
    extern __shared__ __half hsm[];

    const int tid  = threadIdx.x;
    const int wid  = tid >> 5;
    const int lane = tid & 31;
    const int wm   = wid >> 1;           // 0..3
    const int wn   = wid & 1;            // 0..1
    const int m0   = blockIdx.y * 128;
    const int n0   = blockIdx.x * 128;
    const int NT   = K >> 5;

    float acc[2][8][4];
#pragma unroll
    for (int a = 0; a < 2; a++)
#pragma unroll
        for (int b = 0; b < 8; b++)
#pragma unroll
            for (int c = 0; c < 4; c++) acc[a][b][c] = 0.f;

    auto load_stage = [&](int s, int i) {
        const __half* gA = A  + (size_t)m0 * lda + i * 32;
        const __half* gB = Bt + (size_t)n0 * ldb + i * 32;
        __half* dA = hsm + s * 2 * H_STAGE;
        __half* dB = dA + H_STAGE;
#pragma unroll
        for (int t = 0; t < 2; t++) {
            int idx = tid + t * 256;       // 0..511
            int row = idx >> 2;
            int seg = (idx & 3) * 8;       // halfs (16B chunks)
            cp16(smem_u32(dA + row * H_RS + seg), gA + (size_t)row * lda + seg);
            cp16(smem_u32(dB + row * H_RS + seg), gB + (size_t)row * ldb + seg);
        }
        CP_COMMIT();
    };

    load_stage(0, 0);
    load_stage(1, 1);

    for (int i = 0; i < NT; i++) {
        const int s = i % 3;
        if (i + 1 < NT) { CP_WAIT(1); } else { CP_WAIT(0); }
        __syncthreads();

        const uint32_t uA = smem_u32(hsm + s * 2 * H_STAGE);
        const uint32_t uB = uA + H_STAGE * 2;

#pragma unroll
        for (int kk = 0; kk < 32; kk += 16) {
            // A fragments: 2x ldmatrix.x4 (m32 x k16)
            uint32_t af[2][4];
#pragma unroll
            for (int mt = 0; mt < 2; mt++) {
                int row = wm * 32 + mt * 16 + (lane & 15);
                int kof = kk + ((lane >> 4) << 3);
                LDMX4(af[mt][0], af[mt][1], af[mt][2], af[mt][3],
                      uA + (row * H_RS + kof) * 2);
            }
            // B fragments: 4x ldmatrix.x4 (n64 x k16)
            uint32_t bf[4][4];
#pragma unroll
            for (int g = 0; g < 4; g++) {
                int nrow = wn * 64 + g * 16 + ((lane >> 4) << 3) + (lane & 7);
                int kof = kk + (((lane >> 3) & 1) << 3);
                LDMX4(bf[g][0], bf[g][1], bf[g][2], bf[g][3],
                      uB + (nrow * H_RS + kof) * 2);
            }
#pragma unroll
            for (int mt = 0; mt < 2; mt++)
#pragma unroll
                for (int nt = 0; nt < 8; nt++) {
                    int g = nt >> 1, sub = nt & 1;
                    asm volatile(
                        "mma.sync.aligned.m16n8k16.row.col.f32.f16.f16.f32 "
                        "{%0,%1,%2,%3}, {%4,%5,%6,%7}, {%8,%9}, {%0,%1,%2,%3};"
                        : "+f"(acc[mt][nt][0]), "+f"(acc[mt][nt][1]),
                          "+f"(acc[mt][nt][2]), "+f"(acc[mt][nt][3])
                        : "r"(af[mt][0]), "r"(af[mt][1]),
                          "r"(af[mt][2]), "r"(af[mt][3]),
                          "r"(bf[g][sub * 2]), "r"(bf[g][sub * 2 + 1]));
                }
        }
        if (i + 2 < NT) load_stage((i + 2) % 3, i + 2);
    }

#pragma unroll
    for (int mt = 0; mt < 2; mt++) {
        int r = m0 + wm * 32 + mt * 16 + (lane >> 2);
#pragma unroll
        for (int nt = 0; nt < 8; nt++) {
            int cn = n0 + wn * 64 + nt * 8 + (lane & 3) * 2;
            *(float2*)(C + (size_t)r * N + cn) =
                make_float2(acc[mt][nt][0], acc[mt][nt][1]);
            *(float2*)(C + (size_t)(r + 8) * N + cn) =
                make_float2(acc[mt][nt][2], acc[mt][nt][3]);
        }
    }
}

// ---------------------------------------------------------------------------
// transpose to half: out[C][R] = (half)in[R][C]
// ---------------------------------------------------------------------------
__global__ __launch_bounds__(256)
void transpose_h_k(const float* __restrict__ in, __half* __restrict__ out,
                   int R, int C)
{
    __shared__ float t[32][33];
    int cb = blockIdx.x * 32, rb = blockIdx.y * 32;
    int x = threadIdx.x & 31, y = threadIdx.x >> 5;
#pragma unroll
    for (int j = 0; j < 32; j += 8)
        t[y + j][x] = in[(size_t)(rb + y + j) * C + cb + x];
    __syncthreads();
#pragma unroll
    for (int j = 0; j < 32; j += 8)
        out[(size_t)(cb + y + j) * R + rb + x] = __float2half_rn(t[x][y + j]);
}

__global__ void f2h_k(const float* __restrict__ in, __half* __restrict__ out,
                      int n)
{
    int i = blockIdx.x * 256 + threadIdx.x;
    if (i < n) out[i] = __float2half_rn(in[i]);
}

// ---------------------------------------------------------------------------
// SIMT split-K SGEMM (tall-skinny rank-128 projections), fp32
// ---------------------------------------------------------------------------
template <int ATOMIC>
__global__ __launch_bounds__(256)
void sgemm_k(const float* __restrict__ A, const float* __restrict__ B,
             float* __restrict__ C, int M, int N, int K, int kSplit)
{
    __shared__ __align__(16) float As[8][128];
    __shared__ __align__(16) float Bs[8][128];

    const int tid  = threadIdx.x;
    const int bm   = blockIdx.y;
    const int bn   = blockIdx.x;
    const int k0   = blockIdx.z * kSplit;

    const int arow = tid >> 1;
    const int acol = (tid & 1) << 2;
    const int brow = tid >> 5;
    const int bcol = (tid & 31) << 2;
    const int ty   = tid >> 4;
    const int tx   = tid & 15;

    float acc[8][8];
#pragma unroll
    for (int i = 0; i < 8; i++)
#pragma unroll
        for (int j = 0; j < 8; j++) acc[i][j] = 0.f;

    const float* Ag = A + (size_t)(bm * 128 + arow) * K;
    const float* Bg = B + (size_t)(bn * 128) + bcol;

    for (int kt = 0; kt < kSplit; kt += 8) {
        float4 av = *(const float4*)(Ag + (k0 + kt + acol));
        As[acol + 0][arow] = av.x;
        As[acol + 1][arow] = av.y;
        As[acol + 2][arow] = av.z;
        As[acol + 3][arow] = av.w;
        *(float4*)&Bs[brow][bcol] =
            *(const float4*)(Bg + (size_t)(k0 + kt + brow) * N);
        __syncthreads();

#pragma unroll
        for (int kk = 0; kk < 8; kk++) {
            float4 a0 = *(const float4*)&As[kk][ty * 8];
            float4 a1 = *(const float4*)&As[kk][ty * 8 + 4];
            float4 b0 = *(const float4*)&Bs[kk][tx * 8];
            float4 b1 = *(const float4*)&Bs[kk][tx * 8 + 4];
            float a[8] = {a0.x, a0.y, a0.z, a0.w, a1.x, a1.y, a1.z, a1.w};
            float b[8] = {b0.x, b0.y, b0.z, b0.w, b1.x, b1.y, b1.z, b1.w};
#pragma unroll
            for (int i = 0; i < 8; i++)
#pragma unroll
                for (int j = 0; j < 8; j++)
                    acc[i][j] = fmaf(a[i], b[j], acc[i][j]);
        }
        __syncthreads();
    }

#pragma unroll
    for (int i = 0; i < 8; i++) {
        float* Cp = C + (size_t)(bm * 128 + ty * 8 + i) * N + bn * 128 + tx * 8;
        if (ATOMIC) {
#pragma unroll
            for (int j = 0; j < 8; j++) atomicAdd(Cp + j, acc[i][j]);
        } else {
            *(float4*)(Cp + 0) = make_float4(acc[i][0], acc[i][1], acc[i][2], acc[i][3]);
            *(float4*)(Cp + 4) = make_float4(acc[i][4], acc[i][5], acc[i][6], acc[i][7]);
        }
    }
}

__global__ void zero_k(float* __restrict__ p, int n)
{
    int i = blockIdx.x * 256 + threadIdx.x;
    if (i < n) p[i] = 0.f;
}

// ---------------------------------------------------------------------------
// block-of-128 reduce helper
// ---------------------------------------------------------------------------
__device__ __forceinline__ float block128_sum(float v, float* shm)
{
#pragma unroll
    for (int m = 16; m > 0; m >>= 1) v += __shfl_xor_sync(0xffffffffu, v, m);
    int w = threadIdx.x >> 5;
    if ((threadIdx.x & 31) == 0) shm[w] = v;
    __syncthreads();
    return shm[0] + shm[1] + shm[2] + shm[3];
}

// ---------------------------------------------------------------------------
// fused: depthwise causal conv (K=4) + SiLU + l2norm(q,k).  grid (T, NH).
// ---------------------------------------------------------------------------
__global__ __launch_bounds__(128)
void conv_l2_k(const float* __restrict__ qkv,
               const float* __restrict__ wq, const float* __restrict__ wk,
               const float* __restrict__ wv,
               float* __restrict__ qc, float* __restrict__ kc,
               float* __restrict__ vc)
{
    __shared__ float shm[4];
    int t = blockIdx.x, h = blockIdx.y, d = threadIdx.x;
    int c = h * DH + d;
    float aq = 0.f, ak = 0.f, av = 0.f;
#pragma unroll
    for (int j = 0; j < 4; j++) {
        int tt = t + j - 3;
        if (tt >= 0) {
            size_t base = (size_t)tt * 6144;
            aq = fmaf(wq[j * KD + c], qkv[base + c], aq);
            ak = fmaf(wk[j * KD + c], qkv[base + 2048 + c], ak);
            av = fmaf(wv[j * KD + c], qkv[base + 4096 + c], av);
        }
    }
    aq = aq / (1.f + expf(-aq));
    ak = ak / (1.f + expf(-ak));
    av = av / (1.f + expf(-av));

    size_t idx = (size_t)t * KD + c;
    vc[idx] = av;

    float ssq = block128_sum(aq * aq, shm);
    __syncthreads();
    float ssk = block128_sum(ak * ak, shm);
    qc[idx] = aq * rsqrtf(ssq + 1e-6f) * 0.08838834764831845f;
    kc[idx] = ak * rsqrtf(ssk + 1e-6f);
}

// ---------------------------------------------------------------------------
// gate prep: eg = exp(-exp(A_log[h]) * softplus_stable(graw + dt_bias))
// ---------------------------------------------------------------------------
__global__ __launch_bounds__(256)
void gprep_k(float* __restrict__ eg, const float* __restrict__ dt_bias,
             const float* __restrict__ A_log)
{
    int idx = blockIdx.x * 256 + threadIdx.x;
    int c = idx & (KD - 1);
    int h = c >> 7;
    float xr = eg[idx] + dt_bias[c];
    xr = fminf(fmaxf(xr, -20.f), 20.f);
    float sp = log1pf(expf(xr));
    float g = -expf(A_log[h]) * sp;
    eg[idx] = expf(g);
}

// ---------------------------------------------------------------------------
// beta = sigmoid(x @ Wb)
// ---------------------------------------------------------------------------
__global__ __launch_bounds__(512)
void beta_k(const float* __restrict__ x, const float* __restrict__ Wb,
            float* __restrict__ beta)
{
    __shared__ float sx[DM];
    int t = blockIdx.x;
    for (int i = threadIdx.x; i < DM; i += 512) sx[i] = x[(size_t)t * DM + i];
    __syncthreads();
    int h = threadIdx.x >> 5, lane = threadIdx.x & 31;
    float acc = 0.f;
    for (int k = lane; k < DM; k += 32) acc = fmaf(sx[k], Wb[k * NH + h], acc);
#pragma unroll
    for (int m = 16; m > 0; m >>= 1) acc += __shfl_xor_sync(0xffffffffu, acc, m);
    if (lane == 0) beta[t * NH + h] = 1.f / (1.f + expf(-acc));
}

// ---------------------------------------------------------------------------
// gated delta recurrence: 16 lanes/column, single 4-level butterfly with
// three interleaved chains, register prefetch, no smem/barriers.
// ---------------------------------------------------------------------------
__global__ __launch_bounds__(256)
void recur2_k(const float* __restrict__ qf, const float* __restrict__ kf,
              const float* __restrict__ vv, const float* __restrict__ eg,
              const float* __restrict__ beta, float* __restrict__ o)
{
    const int tid  = threadIdx.x;
    const int wid  = tid >> 5;
    const int lane = tid & 31;
    const int sub  = lane >> 4;
    const int l16  = lane & 15;
    const int colbase = blockIdx.x * 16;
    const int head = colbase >> 7;
    const int col  = colbase + wid * 2 + sub;
    const int j0   = head * DH + l16 * 8;

    float s[8];
#pragma unroll
    for (int i = 0; i < 8; i++) s[i] = 0.f;

    float4 kv0, kv1, qv0, qv1, ev0, ev1;
    float vcur, bcur;
    kv0 = *(const float4*)(kf + j0); kv1 = *(const float4*)(kf + j0 + 4);
    qv0 = *(const float4*)(qf + j0); qv1 = *(const float4*)(qf + j0 + 4);
    ev0 = *(const float4*)(eg + j0); ev1 = *(const float4*)(eg + j0 + 4);
    vcur = vv[col];
    bcur = beta[head];

    for (int t = 0; t < T_LEN; t++) {
        int tn = (t + 1 < T_LEN) ? t + 1 : t;
        size_t off = (size_t)tn * KD + j0;
        float4 nk0 = *(const float4*)(kf + off);
        float4 nk1 = *(const float4*)(kf + off + 4);
        float4 nq0 = *(const float4*)(qf + off);
        float4 nq1 = *(const float4*)(qf + off + 4);
        float4 ne0 = *(const float4*)(eg + off);
        float4 ne1 = *(const float4*)(eg + off + 4);
        float  nv  = vv[(size_t)tn * KD + col];
        float  nb  = beta[tn * NH + head];

        s[0] *= ev0.x; s[1] *= ev0.y; s[2] *= ev0.z; s[3] *= ev0.w;
        s[4] *= ev1.x; s[5] *= ev1.y; s[6] *= ev1.z; s[7] *= ev1.w;

        float r1 = s[0] * kv0.x; float r2 = s[0] * qv0.x; float r3 = kv0.x * qv0.x;
        r1 = fmaf(s[1], kv0.y, r1); r2 = fmaf(s[1], qv0.y, r2); r3 = fmaf(kv0.y, qv0.y, r3);
        r1 = fmaf(s[2], kv0.z, r1); r2 = fmaf(s[2], qv0.z, r2); r3 = fmaf(kv0.z, qv0.z, r3);
        r1 = fmaf(s[3], kv0.w, r1); r2 = fmaf(s[3], qv0.w, r2); r3 = fmaf(kv0.w, qv0.w, r3);
        r1 = fmaf(s[4], kv1.x, r1); r2 = fmaf(s[4], qv1.x, r2); r3 = fmaf(kv1.x, qv1.x, r3);
        r1 = fmaf(s[5], kv1.y, r1); r2 = fmaf(s[5], qv1.y, r2); r3 = fmaf(kv1.y, qv1.y, r3);
        r1 = fmaf(s[6], kv1.z, r1); r2 = fmaf(s[6], qv1.z, r2); r3 = fmaf(kv1.z, qv1.z, r3);
        r1 = fmaf(s[7], kv1.w, r1); r2 = fmaf(s[7], qv1.w, r2); r3 = fmaf(kv1.w, qv1.w, r3);

#pragma unroll
        for (int m = 8; m > 0; m >>= 1) {
            r1 += __shfl_xor_sync(0xffffffffu, r1, m);
            r2 += __shfl_xor_sync(0xffffffffu, r2, m);
            r3 += __shfl_xor_sync(0xffffffffu, r3, m);
        }

        float upd = bcur * (vcur - r1);

        s[0] = fmaf(kv0.x, upd, s[0]); s[1] = fmaf(kv0.y, upd, s[1]);
        s[2] = fmaf(kv0.z, upd, s[2]); s[3] = fmaf(kv0.w, upd, s[3]);
        s[4] = fmaf(kv1.x, upd, s[4]); s[5] = fmaf(kv1.y, upd, s[5]);
        s[6] = fmaf(kv1.z, upd, s[6]); s[7] = fmaf(kv1.w, upd, s[7]);

        if (l16 == 0) o[(size_t)t * KD + col] = fmaf(r3, upd, r2);

        kv0 = nk0; kv1 = nk1; qv0 = nq0; qv1 = nq1; ev0 = ne0; ev1 = ne1;
        vcur = nv; bcur = nb;
    }
}

// ---------------------------------------------------------------------------
// epilogue: og(half) = o * rsqrt(mean(o^2)+eps) * norm_w * sigmoid(gout)
// ---------------------------------------------------------------------------
__global__ __launch_bounds__(128)
void epi_k(const float* __restrict__ o, const float* __restrict__ gout,
           const float* __restrict__ norm_w, __half* __restrict__ og)
{
    __shared__ float shm[4];
    int t = blockIdx.x, h = blockIdx.y, d = threadIdx.x;
    size_t idx = (size_t)t * KD + h * DH + d;
    float ov = o[idx];
    float ss = block128_sum(ov * ov, shm);
    float rstd = rsqrtf(ss * (1.f / 128.f) + 1e-6f);
    float gate = 1.f / (1.f + expf(-gout[idx]));
    og[idx] = __float2half_rn(ov * rstd * norm_w[d] * gate);
}

// ---------------------------------------------------------------------------
// launch
// ---------------------------------------------------------------------------
extern "C" void kernel_launch(void* const* d_in, const int* in_sizes, int n_in,
                              void* d_out, int out_size)
{
    (void)in_sizes; (void)n_in; (void)out_size;
    const float* x      = (const float*)d_in[0];
    const float* Wq     = (const float*)d_in[1];
    const float* Wk     = (const float*)d_in[2];
    const float* Wv     = (const float*)d_in[3];
    const float* conv_q = (const float*)d_in[4];
    const float* conv_k = (const float*)d_in[5];
    const float* conv_v = (const float*)d_in[6];
    const float* Wfa    = (const float*)d_in[7];
    const float* Wfb    = (const float*)d_in[8];
    const float* dt_b   = (const float*)d_in[9];
    const float* A_log  = (const float*)d_in[10];
    const float* Wb     = (const float*)d_in[11];
    const float* Wga    = (const float*)d_in[12];
    const float* Wgb    = (const float*)d_in[13];
    const float* norm_w = (const float*)d_in[14];
    const float* Wo     = (const float*)d_in[15];
    float* out = (float*)d_out;

    float* s = nullptr;
    cudaGetSymbolAddress((void**)&s, g_scratch);
    __half* hb = nullptr;
    cudaGetSymbolAddress((void**)&hb, g_hbuf);

    float* qkv  = s + OFF_QKV;
    float* qc   = s + OFF_QC;
    float* kc   = s + OFF_KC;
    float* vc   = s + OFF_VC;
    float* eg   = s + OFF_EG;
    float* gout = s + OFF_GOUT;
    float* o    = s + OFF_O;
    float* fa   = s + OFF_FA;              // fa | ga contiguous fp32
    float* beta = s + OFF_BETA;

    __half* W3   = hb + HO_W3;
    __half* WOh  = hb + HO_WO;
    __half* WFBh = hb + HO_WFB;
    __half* WGBh = hb + HO_WGB;
    __half* xh   = hb + HO_X;
    __half* fgh  = hb + HO_FG;
    __half* ogh  = hb + HO_OG;

    cudaFuncSetAttribute(hgemm_k, cudaFuncAttributeMaxDynamicSharedMemorySize,
                         H_SMEM);

    // weight transposes -> half, [N][K] K-major. W3 = WqT|WkT|WvT
    transpose_h_k<<<dim3(64, 64), 256>>>(Wq,  W3,                    DM, KD);
    transpose_h_k<<<dim3(64, 64), 256>>>(Wk,  W3 + 2048 * 2048,      DM, KD);
    transpose_h_k<<<dim3(64, 64), 256>>>(Wv,  W3 + 2 * 2048 * 2048,  DM, KD);
    transpose_h_k<<<dim3(64, 64), 256>>>(Wo,  WOh,  KD, DM);
    transpose_h_k<<<dim3(64, 4),  256>>>(Wfb, WFBh, DH, KD);
    transpose_h_k<<<dim3(64, 4),  256>>>(Wgb, WGBh, DH, KD);

    // x -> half
    f2h_k<<<(unsigned)(NTK / 256), 256>>>(x, xh, (int)NTK);

    // fused q|k|v projection (one fp16 GEMM, N=6144)
    hgemm_k<<<dim3(48, 8), 256, H_SMEM>>>(xh, DM, W3, DM, qkv,
                                          T_LEN, 6144, DM);

    // fused causal conv + silu + qk l2norm
    conv_l2_k<<<dim3(T_LEN, NH), 128>>>(qkv, conv_q, conv_k, conv_v,
                                        qc, kc, vc);

    // low-rank gate chains: skinny stage fp32 split-K, wide stage fp16 MMA
    zero_k<<<1024, 256>>>(fa, 262144);
    sgemm_k<1><<<dim3(1, 8, 16), 256>>>(x, Wfa, fa,          T_LEN, DH, DM, 128);
    sgemm_k<1><<<dim3(1, 8, 16), 256>>>(x, Wga, fa + 131072, T_LEN, DH, DM, 128);
    f2h_k<<<1024, 256>>>(fa, fgh, 262144);
    hgemm_k<<<dim3(16, 8), 256, H_SMEM>>>(fgh, DH, WFBh, DH, eg,
                                          T_LEN, KD, DH);
    hgemm_k<<<dim3(16, 8), 256, H_SMEM>>>(fgh + 131072, DH, WGBh, DH, gout,
                                          T_LEN, KD, DH);

    // gate prep + beta
    gprep_k<<<(unsigned)(NTK / 256), 256>>>(eg, dt_b, A_log);
    beta_k<<<T_LEN, 512>>>(x, Wb, beta);

    // gated delta recurrence
    recur2_k<<<128, 256>>>(qc, kc, vc, eg, beta, o);

    // gated rmsnorm epilogue (-> half) + output projection
    epi_k<<<dim3(T_LEN, NH), 128>>>(o, gout, norm_w, ogh);
    hgemm_k<<<dim3(16, 8), 256, H_SMEM>>>(ogh, KD, WOh, KD, out,
                                          T_LEN, DM, KD);
}

// round 8
// speedup vs baseline: 3.0337x; 1.0508x over previous
#include <cuda_runtime.h>
#include <cuda_fp16.h>
#include <math.h>
#include <cstdint>

// ---------------------------------------------------------------------------
// KimiDeltaAttention  (B=1, T=1024, DM=2048, H=16, DH=128, KD=2048, KC=4)
// Round 7: fp16 mma.sync GEMMs + smem-staged recurrence.
//   - recurrence: 4-stage cp.async ring (3-step prefetch distance), smem
//     operand staging (8x fewer L1tex wavefronts), 3-chain single butterfly
//   - merged transpose launches
// ---------------------------------------------------------------------------

#define T_LEN 1024
#define DM    2048
#define NH    16
#define DH    128
#define KD    2048

static constexpr size_t NTK = (size_t)T_LEN * KD;   // 2097152

// fp32 scratch
#define OFF_QKV  ((size_t)0)                  // fused q|k|v GEMM out [T][6144]
#define OFF_QC   (NTK * 3)
#define OFF_KC   (NTK * 4)
#define OFF_VC   (NTK * 5)
#define OFF_EG   (NTK * 6)
#define OFF_GOUT (NTK * 7)
#define OFF_O    (NTK * 8)
#define OFF_FA   (NTK * 9)                    // fa | ga contiguous (fp32)
#define OFF_BETA (NTK * 9 + 262144)
#define SCRATCH_FLOATS (OFF_BETA + 16384)
__device__ float g_scratch[SCRATCH_FLOATS];

// fp16 scratch (halfs)
#define HO_W3   ((size_t)0)                   // [6144][2048]  WqT|WkT|WvT
#define HO_WO   ((size_t)12582912)            // [2048][2048]
#define HO_WFB  ((size_t)16777216)            // [2048][128]
#define HO_WGB  ((size_t)17039360)            // [2048][128]
#define HO_X    ((size_t)17301504)            // [1024][2048]
#define HO_FG   ((size_t)19398656)            // fa then ga, half
#define HO_OG   ((size_t)19660800)            // [1024][2048]
#define HBUF_HALFS ((size_t)21757952)
__device__ __half g_hbuf[HBUF_HALFS];

// ---------------------------------------------------------------------------
// helpers
// ---------------------------------------------------------------------------
__device__ __forceinline__ uint32_t smem_u32(const void* p) {
    uint32_t a;
    asm("{ .reg .u64 t; cvta.to.shared.u64 t, %1; cvt.u32.u64 %0, t; }"
        : "=r"(a) : "l"(p));
    return a;
}
__device__ __forceinline__ void cp16(uint32_t dst, const void* src) {
    asm volatile("cp.async.cg.shared.global [%0], [%1], 16;"
                 :: "r"(dst), "l"(src) : "memory");
}
__device__ __forceinline__ void cp4(uint32_t dst, const void* src) {
    asm volatile("cp.async.ca.shared.global [%0], [%1], 4;"
                 :: "r"(dst), "l"(src) : "memory");
}
#define CP_COMMIT() asm volatile("cp.async.commit_group;" ::: "memory")
#define CP_WAIT(n)  asm volatile("cp.async.wait_group %0;" :: "n"(n) : "memory")

#define LDMX4(r0, r1, r2, r3, addr) \
    asm volatile("ldmatrix.sync.aligned.m8n8.x4.shared.b16 {%0,%1,%2,%3}, [%4];" \
                 : "=r"(r0), "=r"(r1), "=r"(r2), "=r"(r3) : "r"(addr))

// ---------------------------------------------------------------------------
// fp16 GEMM: C[M,N](f32) = A[M,K](h, lda) * Bt[N,K](h, ldb)^T
// grid (N/128, M/128), 256 threads, 2 CTA/SM. K % 32 == 0, K >= 64.
// ---------------------------------------------------------------------------
#define H_RS    40                     // padded row stride (halfs) = 80 B
#define H_STAGE (128 * H_RS)           // halfs per matrix per stage
#define H_SMEM  (3 * 2 * H_STAGE * 2)  // 61440 bytes

__global__ __launch_bounds__(256, 2)
void hgemm_k(const __half* __restrict__ A, int lda,
             const __half* __restrict__ Bt, int ldb,
             float* __restrict__ C, int M, int N, int K)
{
    extern __shared__ __half hsm[];

    const int tid  = threadIdx.x;
    const int wid  = tid >> 5;
    const int lane = tid & 31;
    const int wm   = wid >> 1;           // 0..3
    const int wn   = wid & 1;            // 0..1
    const int m0   = blockIdx.y * 128;
    const int n0   = blockIdx.x * 128;
    const int NT   = K >> 5;

    float acc[2][8][4];
#pragma unroll
    for (int a = 0; a < 2; a++)
#pragma unroll
        for (int b = 0; b < 8; b++)
#pragma unroll
            for (int c = 0; c < 4; c++) acc[a][b][c] = 0.f;

    auto load_stage = [&](int s, int i) {
        const __half* gA = A  + (size_t)m0 * lda + i * 32;
        const __half* gB = Bt + (size_t)n0 * ldb + i * 32;
        __half* dA = hsm + s * 2 * H_STAGE;
        __half* dB = dA + H_STAGE;
#pragma unroll
        for (int t = 0; t < 2; t++) {
            int idx = tid + t * 256;       // 0..511
            int row = idx >> 2;
            int seg = (idx & 3) * 8;       // halfs (16B chunks)
            cp16(smem_u32(dA + row * H_RS + seg), gA + (size_t)row * lda + seg);
            cp16(smem_u32(dB + row * H_RS + seg), gB + (size_t)row * ldb + seg);
        }
        CP_COMMIT();
    };

    load_stage(0, 0);
    load_stage(1, 1);

    for (int i = 0; i < NT; i++) {
        const int s = i % 3;
        if (i + 1 < NT) { CP_WAIT(1); } else { CP_WAIT(0); }
        __syncthreads();

        const uint32_t uA = smem_u32(hsm + s * 2 * H_STAGE);
        const uint32_t uB = uA + H_STAGE * 2;

#pragma unroll
        for (int kk = 0; kk < 32; kk += 16) {
            uint32_t af[2][4];
#pragma unroll
            for (int mt = 0; mt < 2; mt++) {
                int row = wm * 32 + mt * 16 + (lane & 15);
                int kof = kk + ((lane >> 4) << 3);
                LDMX4(af[mt][0], af[mt][1], af[mt][2], af[mt][3],
                      uA + (row * H_RS + kof) * 2);
            }
            uint32_t bf[4][4];
#pragma unroll
            for (int g = 0; g < 4; g++) {
                int nrow = wn * 64 + g * 16 + ((lane >> 4) << 3) + (lane & 7);
                int kof = kk + (((lane >> 3) & 1) << 3);
                LDMX4(bf[g][0], bf[g][1], bf[g][2], bf[g][3],
                      uB + (nrow * H_RS + kof) * 2);
            }
#pragma unroll
            for (int mt = 0; mt < 2; mt++)
#pragma unroll
                for (int nt = 0; nt < 8; nt++) {
                    int g = nt >> 1, sub = nt & 1;
                    asm volatile(
                        "mma.sync.aligned.m16n8k16.row.col.f32.f16.f16.f32 "
                        "{%0,%1,%2,%3}, {%4,%5,%6,%7}, {%8,%9}, {%0,%1,%2,%3};"
                        : "+f"(acc[mt][nt][0]), "+f"(acc[mt][nt][1]),
                          "+f"(acc[mt][nt][2]), "+f"(acc[mt][nt][3])
                        : "r"(af[mt][0]), "r"(af[mt][1]),
                          "r"(af[mt][2]), "r"(af[mt][3]),
                          "r"(bf[g][sub * 2]), "r"(bf[g][sub * 2 + 1]));
                }
        }
        if (i + 2 < NT) load_stage((i + 2) % 3, i + 2);
    }

#pragma unroll
    for (int mt = 0; mt < 2; mt++) {
        int r = m0 + wm * 32 + mt * 16 + (lane >> 2);
#pragma unroll
        for (int nt = 0; nt < 8; nt++) {
            int cn = n0 + wn * 64 + nt * 8 + (lane & 3) * 2;
            *(float2*)(C + (size_t)r * N + cn) =
                make_float2(acc[mt][nt][0], acc[mt][nt][1]);
            *(float2*)(C + (size_t)(r + 8) * N + cn) =
                make_float2(acc[mt][nt][2], acc[mt][nt][3]);
        }
    }
}

// ---------------------------------------------------------------------------
// transpose to half, 3-way (z selects input; out strided by R*C per z)
// ---------------------------------------------------------------------------
__global__ __launch_bounds__(256)
void transpose3_h_k(const float* __restrict__ i0, const float* __restrict__ i1,
                    const float* __restrict__ i2, __half* __restrict__ out,
                    int R, int C)
{
    __shared__ float t[32][33];
    const float* in = (blockIdx.z == 0) ? i0 : (blockIdx.z == 1) ? i1 : i2;
    __half* o = out + (size_t)blockIdx.z * R * C;
    int cb = blockIdx.x * 32, rb = blockIdx.y * 32;
    int x = threadIdx.x & 31, y = threadIdx.x >> 5;
#pragma unroll
    for (int j = 0; j < 32; j += 8)
        t[y + j][x] = in[(size_t)(rb + y + j) * C + cb + x];
    __syncthreads();
#pragma unroll
    for (int j = 0; j < 32; j += 8)
        o[(size_t)(cb + y + j) * R + rb + x] = __float2half_rn(t[x][y + j]);
}

__global__ __launch_bounds__(256)
void transpose_h_k(const float* __restrict__ in, __half* __restrict__ out,
                   int R, int C)
{
    __shared__ float t[32][33];
    int cb = blockIdx.x * 32, rb = blockIdx.y * 32;
    int x = threadIdx.x & 31, y = threadIdx.x >> 5;
#pragma unroll
    for (int j = 0; j < 32; j += 8)
        t[y + j][x] = in[(size_t)(rb + y + j) * C + cb + x];
    __syncthreads();
#pragma unroll
    for (int j = 0; j < 32; j += 8)
        out[(size_t)(cb + y + j) * R + rb + x] = __float2half_rn(t[x][y + j]);
}

__global__ void f2h_k(const float* __restrict__ in, __half* __restrict__ out,
                      int n)
{
    int i = blockIdx.x * 256 + threadIdx.x;
    if (i < n) out[i] = __float2half_rn(in[i]);
}

// ---------------------------------------------------------------------------
// SIMT split-K SGEMM (tall-skinny rank-128 projections), fp32
// ---------------------------------------------------------------------------
template <int ATOMIC>
__global__ __launch_bounds__(256)
void sgemm_k(const float* __restrict__ A, const float* __restrict__ B,
             float* __restrict__ C, int M, int N, int K, int kSplit)
{
    __shared__ __align__(16) float As[8][128];
    __shared__ __align__(16) float Bs[8][128];

    const int tid  = threadIdx.x;
    const int bm   = blockIdx.y;
    const int bn   = blockIdx.x;
    const int k0   = blockIdx.z * kSplit;

    const int arow = tid >> 1;
    const int acol = (tid & 1) << 2;
    const int brow = tid >> 5;
    const int bcol = (tid & 31) << 2;
    const int ty   = tid >> 4;
    const int tx   = tid & 15;

    float acc[8][8];
#pragma unroll
    for (int i = 0; i < 8; i++)
#pragma unroll
        for (int j = 0; j < 8; j++) acc[i][j] = 0.f;

    const float* Ag = A + (size_t)(bm * 128 + arow) * K;
    const float* Bg = B + (size_t)(bn * 128) + bcol;

    for (int kt = 0; kt < kSplit; kt += 8) {
        float4 av = *(const float4*)(Ag + (k0 + kt + acol));
        As[acol + 0][arow] = av.x;
        As[acol + 1][arow] = av.y;
        As[acol + 2][arow] = av.z;
        As[acol + 3][arow] = av.w;
        *(float4*)&Bs[brow][bcol] =
            *(const float4*)(Bg + (size_t)(k0 + kt + brow) * N);
        __syncthreads();

#pragma unroll
        for (int kk = 0; kk < 8; kk++) {
            float4 a0 = *(const float4*)&As[kk][ty * 8];
            float4 a1 = *(const float4*)&As[kk][ty * 8 + 4];
            float4 b0 = *(const float4*)&Bs[kk][tx * 8];
            float4 b1 = *(const float4*)&Bs[kk][tx * 8 + 4];
            float a[8] = {a0.x, a0.y, a0.z, a0.w, a1.x, a1.y, a1.z, a1.w};
            float b[8] = {b0.x, b0.y, b0.z, b0.w, b1.x, b1.y, b1.z, b1.w};
#pragma unroll
            for (int i = 0; i < 8; i++)
#pragma unroll
                for (int j = 0; j < 8; j++)
                    acc[i][j] = fmaf(a[i], b[j], acc[i][j]);
        }
        __syncthreads();
    }

#pragma unroll
    for (int i = 0; i < 8; i++) {
        float* Cp = C + (size_t)(bm * 128 + ty * 8 + i) * N + bn * 128 + tx * 8;
        if (ATOMIC) {
#pragma unroll
            for (int j = 0; j < 8; j++) atomicAdd(Cp + j, acc[i][j]);
        } else {
            *(float4*)(Cp + 0) = make_float4(acc[i][0], acc[i][1], acc[i][2], acc[i][3]);
            *(float4*)(Cp + 4) = make_float4(acc[i][4], acc[i][5], acc[i][6], acc[i][7]);
        }
    }
}

__global__ void zero_k(float* __restrict__ p, int n)
{
    int i = blockIdx.x * 256 + threadIdx.x;
    if (i < n) p[i] = 0.f;
}

// ---------------------------------------------------------------------------
// block-of-128 reduce helper
// ---------------------------------------------------------------------------
__device__ __forceinline__ float block128_sum(float v, float* shm)
{
#pragma unroll
    for (int m = 16; m > 0; m >>= 1) v += __shfl_xor_sync(0xffffffffu, v, m);
    int w = threadIdx.x >> 5;
    if ((threadIdx.x & 31) == 0) shm[w] = v;
    __syncthreads();
    return shm[0] + shm[1] + shm[2] + shm[3];
}

// ---------------------------------------------------------------------------
// fused: depthwise causal conv (K=4) + SiLU + l2norm(q,k).  grid (T, NH).
// ---------------------------------------------------------------------------
__global__ __launch_bounds__(128)
void conv_l2_k(const float* __restrict__ qkv,
               const float* __restrict__ wq, const float* __restrict__ wk,
               const float* __restrict__ wv,
               float* __restrict__ qc, float* __restrict__ kc,
               float* __restrict__ vc)
{
    __shared__ float shm[4];
    int t = blockIdx.x, h = blockIdx.y, d = threadIdx.x;
    int c = h * DH + d;
    float aq = 0.f, ak = 0.f, av = 0.f;
#pragma unroll
    for (int j = 0; j < 4; j++) {
        int tt = t + j - 3;
        if (tt >= 0) {
            size_t base = (size_t)tt * 6144;
            aq = fmaf(wq[j * KD + c], qkv[base + c], aq);
            ak = fmaf(wk[j * KD + c], qkv[base + 2048 + c], ak);
            av = fmaf(wv[j * KD + c], qkv[base + 4096 + c], av);
        }
    }
    aq = aq / (1.f + expf(-aq));
    ak = ak / (1.f + expf(-ak));
    av = av / (1.f + expf(-av));

    size_t idx = (size_t)t * KD + c;
    vc[idx] = av;

    float ssq = block128_sum(aq * aq, shm);
    __syncthreads();
    float ssk = block128_sum(ak * ak, shm);
    qc[idx] = aq * rsqrtf(ssq + 1e-6f) * 0.08838834764831845f;
    kc[idx] = ak * rsqrtf(ssk + 1e-6f);
}

// ---------------------------------------------------------------------------
// gate prep: eg = exp(-exp(A_log[h]) * softplus_stable(graw + dt_bias))
// ---------------------------------------------------------------------------
__global__ __launch_bounds__(256)
void gprep_k(float* __restrict__ eg, const float* __restrict__ dt_bias,
             const float* __restrict__ A_log)
{
    int idx = blockIdx.x * 256 + threadIdx.x;
    int c = idx & (KD - 1);
    int h = c >> 7;
    float xr = eg[idx] + dt_bias[c];
    xr = fminf(fmaxf(xr, -20.f), 20.f);
    float sp = log1pf(expf(xr));
    float g = -expf(A_log[h]) * sp;
    eg[idx] = expf(g);
}

// ---------------------------------------------------------------------------
// beta = sigmoid(x @ Wb)
// ---------------------------------------------------------------------------
__global__ __launch_bounds__(512)
void beta_k(const float* __restrict__ x, const float* __restrict__ Wb,
            float* __restrict__ beta)
{
    __shared__ float sx[DM];
    int t = blockIdx.x;
    for (int i = threadIdx.x; i < DM; i += 512) sx[i] = x[(size_t)t * DM + i];
    __syncthreads();
    int h = threadIdx.x >> 5, lane = threadIdx.x & 31;
    float acc = 0.f;
    for (int k = lane; k < DM; k += 32) acc = fmaf(sx[k], Wb[k * NH + h], acc);
#pragma unroll
    for (int m = 16; m > 0; m >>= 1) acc += __shfl_xor_sync(0xffffffffu, acc, m);
    if (lane == 0) beta[t * NH + h] = 1.f / (1.f + expf(-acc));
}

// ---------------------------------------------------------------------------
// gated delta recurrence v3: smem-staged operands via 4-stage cp.async ring
// (3-step prefetch distance). 16 lanes/column, 2 cols/warp, 16 cols/CTA,
// 3-chain single butterfly. grid: 128 CTAs x 256 threads.
// ---------------------------------------------------------------------------
__global__ __launch_bounds__(256)
void recur3_k(const float* __restrict__ qf, const float* __restrict__ kf,
              const float* __restrict__ vv, const float* __restrict__ eg,
              const float* __restrict__ beta, float* __restrict__ o)
{
    __shared__ __align__(16) float sq[4][128];
    __shared__ __align__(16) float sk[4][128];
    __shared__ __align__(16) float se[4][128];
    __shared__ __align__(16) float sv[4][16];
    __shared__ float sb[4];

    const int tid  = threadIdx.x;
    const int wid  = tid >> 5;
    const int lane = tid & 31;
    const int sub  = lane >> 4;
    const int l16  = lane & 15;
    const int colbase = blockIdx.x * 16;
    const int head = colbase >> 7;
    const int col  = colbase + wid * 2 + sub;
    const int hoff = head * DH;

    // producer: threads 0..31 q, 32..63 k, 64..95 eg (float4 each),
    // 96..99 v (float4 each), 100 beta (scalar).
    auto issue_stage = [&](int t) {
        int st = t & 3;
        if (tid < 96) {
            int arr = tid >> 5;
            int off = (tid & 31) * 4;
            const float* src = (arr == 0 ? qf : (arr == 1 ? kf : eg))
                               + (size_t)t * KD + hoff + off;
            float* dst = (arr == 0 ? sq[st] : (arr == 1 ? sk[st] : se[st])) + off;
            cp16(smem_u32(dst), src);
        } else if (tid < 100) {
            int off = (tid - 96) * 4;
            cp16(smem_u32(sv[st] + off),
                 vv + (size_t)t * KD + colbase + off);
        } else if (tid == 100) {
            cp4(smem_u32(&sb[st]), beta + t * NH + head);
        }
        CP_COMMIT();
    };

    issue_stage(0);
    issue_stage(1);
    issue_stage(2);

    float s0 = 0.f, s1 = 0.f, s2 = 0.f, s3 = 0.f;
    float s4 = 0.f, s5 = 0.f, s6 = 0.f, s7 = 0.f;

    for (int t = 0; t < T_LEN; t++) {
        const int st = t & 3;
        CP_WAIT(2);
        __syncthreads();

        float4 kv0 = *(const float4*)&sk[st][l16 * 8];
        float4 kv1 = *(const float4*)&sk[st][l16 * 8 + 4];
        float4 qv0 = *(const float4*)&sq[st][l16 * 8];
        float4 qv1 = *(const float4*)&sq[st][l16 * 8 + 4];
        float4 ev0 = *(const float4*)&se[st][l16 * 8];
        float4 ev1 = *(const float4*)&se[st][l16 * 8 + 4];
        float vval = sv[st][wid * 2 + sub];
        float bet  = sb[st];

        // prefetch stage t+3 (ring slot (t-1)&3, consumed last iteration)
        if (t + 3 < T_LEN) issue_stage(t + 3);
        else               CP_COMMIT();   // keep per-thread group counts uniform

        // decay
        s0 *= ev0.x; s1 *= ev0.y; s2 *= ev0.z; s3 *= ev0.w;
        s4 *= ev1.x; s5 *= ev1.y; s6 *= ev1.z; s7 *= ev1.w;

        // three interleaved partial dots: r1=k.S', r2=q.S', r3=q.k
        float r1 = s0 * kv0.x; float r2 = s0 * qv0.x; float r3 = kv0.x * qv0.x;
        r1 = fmaf(s1, kv0.y, r1); r2 = fmaf(s1, qv0.y, r2); r3 = fmaf(kv0.y, qv0.y, r3);
        r1 = fmaf(s2, kv0.z, r1); r2 = fmaf(s2, qv0.z, r2); r3 = fmaf(kv0.z, qv0.z, r3);
        r1 = fmaf(s3, kv0.w, r1); r2 = fmaf(s3, qv0.w, r2); r3 = fmaf(kv0.w, qv0.w, r3);
        r1 = fmaf(s4, kv1.x, r1); r2 = fmaf(s4, qv1.x, r2); r3 = fmaf(kv1.x, qv1.x, r3);
        r1 = fmaf(s5, kv1.y, r1); r2 = fmaf(s5, qv1.y, r2); r3 = fmaf(kv1.y, qv1.y, r3);
        r1 = fmaf(s6, kv1.z, r1); r2 = fmaf(s6, qv1.z, r2); r3 = fmaf(kv1.z, qv1.z, r3);
        r1 = fmaf(s7, kv1.w, r1); r2 = fmaf(s7, qv1.w, r2); r3 = fmaf(kv1.w, qv1.w, r3);

        // single 4-level butterfly over 16-lane group, 3 chains
#pragma unroll
        for (int m = 8; m > 0; m >>= 1) {
            r1 += __shfl_xor_sync(0xffffffffu, r1, m);
            r2 += __shfl_xor_sync(0xffffffffu, r2, m);
            r3 += __shfl_xor_sync(0xffffffffu, r3, m);
        }

        float upd = bet * (vval - r1);

        s0 = fmaf(kv0.x, upd, s0); s1 = fmaf(kv0.y, upd, s1);
        s2 = fmaf(kv0.z, upd, s2); s3 = fmaf(kv0.w, upd, s3);
        s4 = fmaf(kv1.x, upd, s4); s5 = fmaf(kv1.y, upd, s5);
        s6 = fmaf(kv1.z, upd, s6); s7 = fmaf(kv1.w, upd, s7);

        // o = q.S_new = r2 + r3*upd
        if (l16 == 0) o[(size_t)t * KD + col] = fmaf(r3, upd, r2);
    }
}

// ---------------------------------------------------------------------------
// epilogue: og(half) = o * rsqrt(mean(o^2)+eps) * norm_w * sigmoid(gout)
// ---------------------------------------------------------------------------
__global__ __launch_bounds__(128)
void epi_k(const float* __restrict__ o, const float* __restrict__ gout,
           const float* __restrict__ norm_w, __half* __restrict__ og)
{
    __shared__ float shm[4];
    int t = blockIdx.x, h = blockIdx.y, d = threadIdx.x;
    size_t idx = (size_t)t * KD + h * DH + d;
    float ov = o[idx];
    float ss = block128_sum(ov * ov, shm);
    float rstd = rsqrtf(ss * (1.f / 128.f) + 1e-6f);
    float gate = 1.f / (1.f + expf(-gout[idx]));
    og[idx] = __float2half_rn(ov * rstd * norm_w[d] * gate);
}

// ---------------------------------------------------------------------------
// launch
// ---------------------------------------------------------------------------
extern "C" void kernel_launch(void* const* d_in, const int* in_sizes, int n_in,
                              void* d_out, int out_size)
{
    (void)in_sizes; (void)n_in; (void)out_size;
    const float* x      = (const float*)d_in[0];
    const float* Wq     = (const float*)d_in[1];
    const float* Wk     = (const float*)d_in[2];
    const float* Wv     = (const float*)d_in[3];
    const float* conv_q = (const float*)d_in[4];
    const float* conv_k = (const float*)d_in[5];
    const float* conv_v = (const float*)d_in[6];
    const float* Wfa    = (const float*)d_in[7];
    const float* Wfb    = (const float*)d_in[8];
    const float* dt_b   = (const float*)d_in[9];
    const float* A_log  = (const float*)d_in[10];
    const float* Wb     = (const float*)d_in[11];
    const float* Wga    = (const float*)d_in[12];
    const float* Wgb    = (const float*)d_in[13];
    const float* norm_w = (const float*)d_in[14];
    const float* Wo     = (const float*)d_in[15];
    float* out = (float*)d_out;

    float* s = nullptr;
    cudaGetSymbolAddress((void**)&s, g_scratch);
    __half* hb = nullptr;
    cudaGetSymbolAddress((void**)&hb, g_hbuf);

    float* qkv  = s + OFF_QKV;
    float* qc   = s + OFF_QC;
    float* kc   = s + OFF_KC;
    float* vc   = s + OFF_VC;
    float* eg   = s + OFF_EG;
    float* gout = s + OFF_GOUT;
    float* o    = s + OFF_O;
    float* fa   = s + OFF_FA;              // fa | ga contiguous fp32
    float* beta = s + OFF_BETA;

    __half* W3   = hb + HO_W3;
    __half* WOh  = hb + HO_WO;
    __half* WFBh = hb + HO_WFB;
    __half* xh   = hb + HO_X;
    __half* fgh  = hb + HO_FG;
    __half* ogh  = hb + HO_OG;

    cudaFuncSetAttribute(hgemm_k, cudaFuncAttributeMaxDynamicSharedMemorySize,
                         H_SMEM);

    // weight transposes -> half, [N][K] K-major. W3 = WqT|WkT|WvT.
    transpose3_h_k<<<dim3(64, 64, 3), 256>>>(Wq, Wk, Wv, W3, DM, KD);
    transpose_h_k<<<dim3(64, 64), 256>>>(Wo, WOh, KD, DM);
    // WFBh and WGBh are contiguous: one 3-way call with Wfb twice wastes work,
    // so use the 2 distinct small transposes via transpose3 z-trick (z=0,1).
    transpose3_h_k<<<dim3(64, 4, 2), 256>>>(Wfb, Wgb, Wgb, WFBh, DH, KD);

    // x -> half
    f2h_k<<<(unsigned)(NTK / 256), 256>>>(x, xh, (int)NTK);

    // fused q|k|v projection (one fp16 GEMM, N=6144)
    hgemm_k<<<dim3(48, 8), 256, H_SMEM>>>(xh, DM, W3, DM, qkv,
                                          T_LEN, 6144, DM);

    // fused causal conv + silu + qk l2norm
    conv_l2_k<<<dim3(T_LEN, NH), 128>>>(qkv, conv_q, conv_k, conv_v,
                                        qc, kc, vc);

    // low-rank gate chains: skinny stage fp32 split-K, wide stage fp16 MMA
    zero_k<<<1024, 256>>>(fa, 262144);
    sgemm_k<1><<<dim3(1, 8, 16), 256>>>(x, Wfa, fa,          T_LEN, DH, DM, 128);
    sgemm_k<1><<<dim3(1, 8, 16), 256>>>(x, Wga, fa + 131072, T_LEN, DH, DM, 128);
    f2h_k<<<1024, 256>>>(fa, fgh, 262144);
    hgemm_k<<<dim3(16, 8), 256, H_SMEM>>>(fgh, DH, WFBh, DH, eg,
                                          T_LEN, KD, DH);
    hgemm_k<<<dim3(16, 8), 256, H_SMEM>>>(fgh + 131072, DH, WFBh + 262144, DH,
                                          gout, T_LEN, KD, DH);

    // gate prep + beta
    gprep_k<<<(unsigned)(NTK / 256), 256>>>(eg, dt_b, A_log);
    beta_k<<<T_LEN, 512>>>(x, Wb, beta);

    // gated delta recurrence (v3: smem-staged)
    recur3_k<<<128, 256>>>(qc, kc, vc, eg, beta, o);

    // gated rmsnorm epilogue (-> half) + output projection
    epi_k<<<dim3(T_LEN, NH), 128>>>(o, gout, norm_w, ogh);
    hgemm_k<<<dim3(16, 8), 256, H_SMEM>>>(ogh, KD, WOh, KD, out,
                                          T_LEN, DM, KD);
}

// round 9
// speedup vs baseline: 3.1578x; 1.0409x over previous
#include <cuda_runtime.h>
#include <cuda_fp16.h>
#include <math.h>
#include <cstdint>

// ---------------------------------------------------------------------------
// KimiDeltaAttention  (B=1, T=1024, DM=2048, H=16, DH=128, KD=2048, KC=4)
// Round 8: stream-overlapped DAG (chain B hidden under chain A) + gprep
// folded into the eg-GEMM epilogue. GEMMs/recurrence as round 7.
// ---------------------------------------------------------------------------

#define T_LEN 1024
#define DM    2048
#define NH    16
#define DH    128
#define KD    2048

static constexpr size_t NTK = (size_t)T_LEN * KD;   // 2097152

// fp32 scratch
#define OFF_QKV  ((size_t)0)                  // fused q|k|v GEMM out [T][6144]
#define OFF_QC   (NTK * 3)
#define OFF_KC   (NTK * 4)
#define OFF_VC   (NTK * 5)
#define OFF_EG   (NTK * 6)
#define OFF_GOUT (NTK * 7)
#define OFF_O    (NTK * 8)
#define OFF_FA   (NTK * 9)                    // fa | ga contiguous (fp32)
#define OFF_BETA (NTK * 9 + 262144)
#define SCRATCH_FLOATS (OFF_BETA + 16384)
__device__ float g_scratch[SCRATCH_FLOATS];

// fp16 scratch (halfs)
#define HO_W3   ((size_t)0)                   // [6144][2048]  WqT|WkT|WvT
#define HO_WO   ((size_t)12582912)            // [2048][2048]
#define HO_WFB  ((size_t)16777216)            // [2048][128] then WGB [2048][128]
#define HO_X    ((size_t)17301504)            // [1024][2048]
#define HO_FG   ((size_t)19398656)            // fa then ga, half
#define HO_OG   ((size_t)19660800)            // [1024][2048]
#define HBUF_HALFS ((size_t)21757952)
__device__ __half g_hbuf[HBUF_HALFS];

// ---------------------------------------------------------------------------
// helpers
// ---------------------------------------------------------------------------
__device__ __forceinline__ uint32_t smem_u32(const void* p) {
    uint32_t a;
    asm("{ .reg .u64 t; cvta.to.shared.u64 t, %1; cvt.u32.u64 %0, t; }"
        : "=r"(a) : "l"(p));
    return a;
}
__device__ __forceinline__ void cp16(uint32_t dst, const void* src) {
    asm volatile("cp.async.cg.shared.global [%0], [%1], 16;"
                 :: "r"(dst), "l"(src) : "memory");
}
__device__ __forceinline__ void cp4(uint32_t dst, const void* src) {
    asm volatile("cp.async.ca.shared.global [%0], [%1], 4;"
                 :: "r"(dst), "l"(src) : "memory");
}
#define CP_COMMIT() asm volatile("cp.async.commit_group;" ::: "memory")
#define CP_WAIT(n)  asm volatile("cp.async.wait_group %0;" :: "n"(n) : "memory")

#define LDMX4(r0, r1, r2, r3, addr) \
    asm volatile("ldmatrix.sync.aligned.m8n8.x4.shared.b16 {%0,%1,%2,%3}, [%4];" \
                 : "=r"(r0), "=r"(r1), "=r"(r2), "=r"(r3) : "r"(addr))

// gate transform: exp(-expA * softplus_stable(v + dtb))
__device__ __forceinline__ float gate_xform(float v, float dtb, float expA)
{
    float xr = fminf(fmaxf(v + dtb, -20.f), 20.f);
    float sp = log1pf(expf(xr));
    return expf(-expA * sp);
}

// ---------------------------------------------------------------------------
// fp16 GEMM: C[M,N](f32) = A[M,K](h, lda) * Bt[N,K](h, ldb)^T
// grid (N/128, M/128), 256 threads, 2 CTA/SM. K % 32 == 0, K >= 64.
// GPREP=1: apply gate_xform(acc, dt_bias[n], exp(A_log[n>>7])) in writeback.
// ---------------------------------------------------------------------------
#define H_RS    40                     // padded row stride (halfs) = 80 B
#define H_STAGE (128 * H_RS)           // halfs per matrix per stage
#define H_SMEM  (3 * 2 * H_STAGE * 2)  // 61440 bytes

template <int GPREP>
__global__ __launch_bounds__(256, 2)
void hgemm_k(const __half* __restrict__ A, int lda,
             const __half* __restrict__ Bt, int ldb,
             float* __restrict__ C, int M, int N, int K,
             const float* __restrict__ dtb, const float* __restrict__ alog)
{
    extern __shared__ __half hsm[];

    const int tid  = threadIdx.x;
    const int wid  = tid >> 5;
    const int lane = tid & 31;
    const int wm   = wid >> 1;           // 0..3
    const int wn   = wid & 1;            // 0..1
    const int m0   = blockIdx.y * 128;
    const int n0   = blockIdx.x * 128;
    const int NT   = K >> 5;

    float acc[2][8][4];
#pragma unroll
    for (int a = 0; a < 2; a++)
#pragma unroll
        for (int b = 0; b < 8; b++)
#pragma unroll
            for (int c = 0; c < 4; c++) acc[a][b][c] = 0.f;

    auto load_stage = [&](int s, int i) {
        const __half* gA = A  + (size_t)m0 * lda + i * 32;
        const __half* gB = Bt + (size_t)n0 * ldb + i * 32;
        __half* dA = hsm + s * 2 * H_STAGE;
        __half* dB = dA + H_STAGE;
#pragma unroll
        for (int t = 0; t < 2; t++) {
            int idx = tid + t * 256;       // 0..511
            int row = idx >> 2;
            int seg = (idx & 3) * 8;       // halfs (16B chunks)
            cp16(smem_u32(dA + row * H_RS + seg), gA + (size_t)row * lda + seg);
            cp16(smem_u32(dB + row * H_RS + seg), gB + (size_t)row * ldb + seg);
        }
        CP_COMMIT();
    };

    load_stage(0, 0);
    load_stage(1, 1);

    for (int i = 0; i < NT; i++) {
        const int s = i % 3;
        if (i + 1 < NT) { CP_WAIT(1); } else { CP_WAIT(0); }
        __syncthreads();

        const uint32_t uA = smem_u32(hsm + s * 2 * H_STAGE);
        const uint32_t uB = uA + H_STAGE * 2;

#pragma unroll
        for (int kk = 0; kk < 32; kk += 16) {
            uint32_t af[2][4];
#pragma unroll
            for (int mt = 0; mt < 2; mt++) {
                int row = wm * 32 + mt * 16 + (lane & 15);
                int kof = kk + ((lane >> 4) << 3);
                LDMX4(af[mt][0], af[mt][1], af[mt][2], af[mt][3],
                      uA + (row * H_RS + kof) * 2);
            }
            uint32_t bf[4][4];
#pragma unroll
            for (int g = 0; g < 4; g++) {
                int nrow = wn * 64 + g * 16 + ((lane >> 4) << 3) + (lane & 7);
                int kof = kk + (((lane >> 3) & 1) << 3);
                LDMX4(bf[g][0], bf[g][1], bf[g][2], bf[g][3],
                      uB + (nrow * H_RS + kof) * 2);
            }
#pragma unroll
            for (int mt = 0; mt < 2; mt++)
#pragma unroll
                for (int nt = 0; nt < 8; nt++) {
                    int g = nt >> 1, sub = nt & 1;
                    asm volatile(
                        "mma.sync.aligned.m16n8k16.row.col.f32.f16.f16.f32 "
                        "{%0,%1,%2,%3}, {%4,%5,%6,%7}, {%8,%9}, {%0,%1,%2,%3};"
                        : "+f"(acc[mt][nt][0]), "+f"(acc[mt][nt][1]),
                          "+f"(acc[mt][nt][2]), "+f"(acc[mt][nt][3])
                        : "r"(af[mt][0]), "r"(af[mt][1]),
                          "r"(af[mt][2]), "r"(af[mt][3]),
                          "r"(bf[g][sub * 2]), "r"(bf[g][sub * 2 + 1]));
                }
        }
        if (i + 2 < NT) load_stage((i + 2) % 3, i + 2);
    }

#pragma unroll
    for (int mt = 0; mt < 2; mt++) {
        int r = m0 + wm * 32 + mt * 16 + (lane >> 2);
#pragma unroll
        for (int nt = 0; nt < 8; nt++) {
            int cn = n0 + wn * 64 + nt * 8 + (lane & 3) * 2;
            float v0a = acc[mt][nt][0], v1a = acc[mt][nt][1];
            float v0b = acc[mt][nt][2], v1b = acc[mt][nt][3];
            if (GPREP) {
                float ea0 = expf(alog[cn >> 7]);
                float ea1 = expf(alog[(cn + 1) >> 7]);
                float d0 = dtb[cn], d1 = dtb[cn + 1];
                v0a = gate_xform(v0a, d0, ea0); v1a = gate_xform(v1a, d1, ea1);
                v0b = gate_xform(v0b, d0, ea0); v1b = gate_xform(v1b, d1, ea1);
            }
            *(float2*)(C + (size_t)r * N + cn) = make_float2(v0a, v1a);
            *(float2*)(C + (size_t)(r + 8) * N + cn) = make_float2(v0b, v1b);
        }
    }
}

// ---------------------------------------------------------------------------
// transpose to half, 3-way (z selects input; out strided by R*C per z)
// ---------------------------------------------------------------------------
__global__ __launch_bounds__(256)
void transpose3_h_k(const float* __restrict__ i0, const float* __restrict__ i1,
                    const float* __restrict__ i2, __half* __restrict__ out,
                    int R, int C)
{
    __shared__ float t[32][33];
    const float* in = (blockIdx.z == 0) ? i0 : (blockIdx.z == 1) ? i1 : i2;
    __half* o = out + (size_t)blockIdx.z * R * C;
    int cb = blockIdx.x * 32, rb = blockIdx.y * 32;
    int x = threadIdx.x & 31, y = threadIdx.x >> 5;
#pragma unroll
    for (int j = 0; j < 32; j += 8)
        t[y + j][x] = in[(size_t)(rb + y + j) * C + cb + x];
    __syncthreads();
#pragma unroll
    for (int j = 0; j < 32; j += 8)
        o[(size_t)(cb + y + j) * R + rb + x] = __float2half_rn(t[x][y + j]);
}

__global__ __launch_bounds__(256)
void transpose_h_k(const float* __restrict__ in, __half* __restrict__ out,
                   int R, int C)
{
    __shared__ float t[32][33];
    int cb = blockIdx.x * 32, rb = blockIdx.y * 32;
    int x = threadIdx.x & 31, y = threadIdx.x >> 5;
#pragma unroll
    for (int j = 0; j < 32; j += 8)
        t[y + j][x] = in[(size_t)(rb + y + j) * C + cb + x];
    __syncthreads();
#pragma unroll
    for (int j = 0; j < 32; j += 8)
        out[(size_t)(cb + y + j) * R + rb + x] = __float2half_rn(t[x][y + j]);
}

__global__ void f2h_k(const float* __restrict__ in, __half* __restrict__ out,
                      int n)
{
    int i = blockIdx.x * 256 + threadIdx.x;
    if (i < n) out[i] = __float2half_rn(in[i]);
}

// ---------------------------------------------------------------------------
// SIMT split-K SGEMM (tall-skinny rank-128 projections), fp32
// ---------------------------------------------------------------------------
template <int ATOMIC>
__global__ __launch_bounds__(256)
void sgemm_k(const float* __restrict__ A, const float* __restrict__ B,
             float* __restrict__ C, int M, int N, int K, int kSplit)
{
    __shared__ __align__(16) float As[8][128];
    __shared__ __align__(16) float Bs[8][128];

    const int tid  = threadIdx.x;
    const int bm   = blockIdx.y;
    const int bn   = blockIdx.x;
    const int k0   = blockIdx.z * kSplit;

    const int arow = tid >> 1;
    const int acol = (tid & 1) << 2;
    const int brow = tid >> 5;
    const int bcol = (tid & 31) << 2;
    const int ty   = tid >> 4;
    const int tx   = tid & 15;

    float acc[8][8];
#pragma unroll
    for (int i = 0; i < 8; i++)
#pragma unroll
        for (int j = 0; j < 8; j++) acc[i][j] = 0.f;

    const float* Ag = A + (size_t)(bm * 128 + arow) * K;
    const float* Bg = B + (size_t)(bn * 128) + bcol;

    for (int kt = 0; kt < kSplit; kt += 8) {
        float4 av = *(const float4*)(Ag + (k0 + kt + acol));
        As[acol + 0][arow] = av.x;
        As[acol + 1][arow] = av.y;
        As[acol + 2][arow] = av.z;
        As[acol + 3][arow] = av.w;
        *(float4*)&Bs[brow][bcol] =
            *(const float4*)(Bg + (size_t)(k0 + kt + brow) * N);
        __syncthreads();

#pragma unroll
        for (int kk = 0; kk < 8; kk++) {
            float4 a0 = *(const float4*)&As[kk][ty * 8];
            float4 a1 = *(const float4*)&As[kk][ty * 8 + 4];
            float4 b0 = *(const float4*)&Bs[kk][tx * 8];
            float4 b1 = *(const float4*)&Bs[kk][tx * 8 + 4];
            float a[8] = {a0.x, a0.y, a0.z, a0.w, a1.x, a1.y, a1.z, a1.w};
            float b[8] = {b0.x, b0.y, b0.z, b0.w, b1.x, b1.y, b1.z, b1.w};
#pragma unroll
            for (int i = 0; i < 8; i++)
#pragma unroll
                for (int j = 0; j < 8; j++)
                    acc[i][j] = fmaf(a[i], b[j], acc[i][j]);
        }
        __syncthreads();
    }

#pragma unroll
    for (int i = 0; i < 8; i++) {
        float* Cp = C + (size_t)(bm * 128 + ty * 8 + i) * N + bn * 128 + tx * 8;
        if (ATOMIC) {
#pragma unroll
            for (int j = 0; j < 8; j++) atomicAdd(Cp + j, acc[i][j]);
        } else {
            *(float4*)(Cp + 0) = make_float4(acc[i][0], acc[i][1], acc[i][2], acc[i][3]);
            *(float4*)(Cp + 4) = make_float4(acc[i][4], acc[i][5], acc[i][6], acc[i][7]);
        }
    }
}

__global__ void zero_k(float* __restrict__ p, int n)
{
    int i = blockIdx.x * 256 + threadIdx.x;
    if (i < n) p[i] = 0.f;
}

// ---------------------------------------------------------------------------
// block-of-128 reduce helper
// ---------------------------------------------------------------------------
__device__ __forceinline__ float block128_sum(float v, float* shm)
{
#pragma unroll
    for (int m = 16; m > 0; m >>= 1) v += __shfl_xor_sync(0xffffffffu, v, m);
    int w = threadIdx.x >> 5;
    if ((threadIdx.x & 31) == 0) shm[w] = v;
    __syncthreads();
    return shm[0] + shm[1] + shm[2] + shm[3];
}

// ---------------------------------------------------------------------------
// fused: depthwise causal conv (K=4) + SiLU + l2norm(q,k).  grid (T, NH).
// ---------------------------------------------------------------------------
__global__ __launch_bounds__(128)
void conv_l2_k(const float* __restrict__ qkv,
               const float* __restrict__ wq, const float* __restrict__ wk,
               const float* __restrict__ wv,
               float* __restrict__ qc, float* __restrict__ kc,
               float* __restrict__ vc)
{
    __shared__ float shm[4];
    int t = blockIdx.x, h = blockIdx.y, d = threadIdx.x;
    int c = h * DH + d;
    float aq = 0.f, ak = 0.f, av = 0.f;
#pragma unroll
    for (int j = 0; j < 4; j++) {
        int tt = t + j - 3;
        if (tt >= 0) {
            size_t base = (size_t)tt * 6144;
            aq = fmaf(wq[j * KD + c], qkv[base + c], aq);
            ak = fmaf(wk[j * KD + c], qkv[base + 2048 + c], ak);
            av = fmaf(wv[j * KD + c], qkv[base + 4096 + c], av);
        }
    }
    aq = aq / (1.f + expf(-aq));
    ak = ak / (1.f + expf(-ak));
    av = av / (1.f + expf(-av));

    size_t idx = (size_t)t * KD + c;
    vc[idx] = av;

    float ssq = block128_sum(aq * aq, shm);
    __syncthreads();
    float ssk = block128_sum(ak * ak, shm);
    qc[idx] = aq * rsqrtf(ssq + 1e-6f) * 0.08838834764831845f;
    kc[idx] = ak * rsqrtf(ssk + 1e-6f);
}

// ---------------------------------------------------------------------------
// beta = sigmoid(x @ Wb)
// ---------------------------------------------------------------------------
__global__ __launch_bounds__(512)
void beta_k(const float* __restrict__ x, const float* __restrict__ Wb,
            float* __restrict__ beta)
{
    __shared__ float sx[DM];
    int t = blockIdx.x;
    for (int i = threadIdx.x; i < DM; i += 512) sx[i] = x[(size_t)t * DM + i];
    __syncthreads();
    int h = threadIdx.x >> 5, lane = threadIdx.x & 31;
    float acc = 0.f;
    for (int k = lane; k < DM; k += 32) acc = fmaf(sx[k], Wb[k * NH + h], acc);
#pragma unroll
    for (int m = 16; m > 0; m >>= 1) acc += __shfl_xor_sync(0xffffffffu, acc, m);
    if (lane == 0) beta[t * NH + h] = 1.f / (1.f + expf(-acc));
}

// ---------------------------------------------------------------------------
// gated delta recurrence v3: smem-staged operands via 4-stage cp.async ring
// ---------------------------------------------------------------------------
__global__ __launch_bounds__(256)
void recur3_k(const float* __restrict__ qf, const float* __restrict__ kf,
              const float* __restrict__ vv, const float* __restrict__ eg,
              const float* __restrict__ beta, float* __restrict__ o)
{
    __shared__ __align__(16) float sq[4][128];
    __shared__ __align__(16) float sk[4][128];
    __shared__ __align__(16) float se[4][128];
    __shared__ __align__(16) float sv[4][16];
    __shared__ float sb[4];

    const int tid  = threadIdx.x;
    const int wid  = tid >> 5;
    const int lane = tid & 31;
    const int sub  = lane >> 4;
    const int l16  = lane & 15;
    const int colbase = blockIdx.x * 16;
    const int head = colbase >> 7;
    const int col  = colbase + wid * 2 + sub;
    const int hoff = head * DH;

    auto issue_stage = [&](int t) {
        int st = t & 3;
        if (tid < 96) {
            int arr = tid >> 5;
            int off = (tid & 31) * 4;
            const float* src = (arr == 0 ? qf : (arr == 1 ? kf : eg))
                               + (size_t)t * KD + hoff + off;
            float* dst = (arr == 0 ? sq[st] : (arr == 1 ? sk[st] : se[st])) + off;
            cp16(smem_u32(dst), src);
        } else if (tid < 100) {
            int off = (tid - 96) * 4;
            cp16(smem_u32(sv[st] + off),
                 vv + (size_t)t * KD + colbase + off);
        } else if (tid == 100) {
            cp4(smem_u32(&sb[st]), beta + t * NH + head);
        }
        CP_COMMIT();
    };

    issue_stage(0);
    issue_stage(1);
    issue_stage(2);

    float s0 = 0.f, s1 = 0.f, s2 = 0.f, s3 = 0.f;
    float s4 = 0.f, s5 = 0.f, s6 = 0.f, s7 = 0.f;

    for (int t = 0; t < T_LEN; t++) {
        const int st = t & 3;
        CP_WAIT(2);
        __syncthreads();

        float4 kv0 = *(const float4*)&sk[st][l16 * 8];
        float4 kv1 = *(const float4*)&sk[st][l16 * 8 + 4];
        float4 qv0 = *(const float4*)&sq[st][l16 * 8];
        float4 qv1 = *(const float4*)&sq[st][l16 * 8 + 4];
        float4 ev0 = *(const float4*)&se[st][l16 * 8];
        float4 ev1 = *(const float4*)&se[st][l16 * 8 + 4];
        float vval = sv[st][wid * 2 + sub];
        float bet  = sb[st];

        if (t + 3 < T_LEN) issue_stage(t + 3);
        else               CP_COMMIT();

        s0 *= ev0.x; s1 *= ev0.y; s2 *= ev0.z; s3 *= ev0.w;
        s4 *= ev1.x; s5 *= ev1.y; s6 *= ev1.z; s7 *= ev1.w;

        float r1 = s0 * kv0.x; float r2 = s0 * qv0.x; float r3 = kv0.x * qv0.x;
        r1 = fmaf(s1, kv0.y, r1); r2 = fmaf(s1, qv0.y, r2); r3 = fmaf(kv0.y, qv0.y, r3);
        r1 = fmaf(s2, kv0.z, r1); r2 = fmaf(s2, qv0.z, r2); r3 = fmaf(kv0.z, qv0.z, r3);
        r1 = fmaf(s3, kv0.w, r1); r2 = fmaf(s3, qv0.w, r2); r3 = fmaf(kv0.w, qv0.w, r3);
        r1 = fmaf(s4, kv1.x, r1); r2 = fmaf(s4, qv1.x, r2); r3 = fmaf(kv1.x, qv1.x, r3);
        r1 = fmaf(s5, kv1.y, r1); r2 = fmaf(s5, qv1.y, r2); r3 = fmaf(kv1.y, qv1.y, r3);
        r1 = fmaf(s6, kv1.z, r1); r2 = fmaf(s6, qv1.z, r2); r3 = fmaf(kv1.z, qv1.z, r3);
        r1 = fmaf(s7, kv1.w, r1); r2 = fmaf(s7, qv1.w, r2); r3 = fmaf(kv1.w, qv1.w, r3);

#pragma unroll
        for (int m = 8; m > 0; m >>= 1) {
            r1 += __shfl_xor_sync(0xffffffffu, r1, m);
            r2 += __shfl_xor_sync(0xffffffffu, r2, m);
            r3 += __shfl_xor_sync(0xffffffffu, r3, m);
        }

        float upd = bet * (vval - r1);

        s0 = fmaf(kv0.x, upd, s0); s1 = fmaf(kv0.y, upd, s1);
        s2 = fmaf(kv0.z, upd, s2); s3 = fmaf(kv0.w, upd, s3);
        s4 = fmaf(kv1.x, upd, s4); s5 = fmaf(kv1.y, upd, s5);
        s6 = fmaf(kv1.z, upd, s6); s7 = fmaf(kv1.w, upd, s7);

        if (l16 == 0) o[(size_t)t * KD + col] = fmaf(r3, upd, r2);
    }
}

// ---------------------------------------------------------------------------
// epilogue: og(half) = o * rsqrt(mean(o^2)+eps) * norm_w * sigmoid(gout)
// ---------------------------------------------------------------------------
__global__ __launch_bounds__(128)
void epi_k(const float* __restrict__ o, const float* __restrict__ gout,
           const float* __restrict__ norm_w, __half* __restrict__ og)
{
    __shared__ float shm[4];
    int t = blockIdx.x, h = blockIdx.y, d = threadIdx.x;
    size_t idx = (size_t)t * KD + h * DH + d;
    float ov = o[idx];
    float ss = block128_sum(ov * ov, shm);
    float rstd = rsqrtf(ss * (1.f / 128.f) + 1e-6f);
    float gate = 1.f / (1.f + expf(-gout[idx]));
    og[idx] = __float2half_rn(ov * rstd * norm_w[d] * gate);
}

// ---------------------------------------------------------------------------
// launch: two-stream DAG. Chain B (gates/weights) overlaps chain A (qkv).
// ---------------------------------------------------------------------------
extern "C" void kernel_launch(void* const* d_in, const int* in_sizes, int n_in,
                              void* d_out, int out_size)
{
    (void)in_sizes; (void)n_in; (void)out_size;
    const float* x      = (const float*)d_in[0];
    const float* Wq     = (const float*)d_in[1];
    const float* Wk     = (const float*)d_in[2];
    const float* Wv     = (const float*)d_in[3];
    const float* conv_q = (const float*)d_in[4];
    const float* conv_k = (const float*)d_in[5];
    const float* conv_v = (const float*)d_in[6];
    const float* Wfa    = (const float*)d_in[7];
    const float* Wfb    = (const float*)d_in[8];
    const float* dt_b   = (const float*)d_in[9];
    const float* A_log  = (const float*)d_in[10];
    const float* Wb     = (const float*)d_in[11];
    const float* Wga    = (const float*)d_in[12];
    const float* Wgb    = (const float*)d_in[13];
    const float* norm_w = (const float*)d_in[14];
    const float* Wo     = (const float*)d_in[15];
    float* out = (float*)d_out;

    float* s = nullptr;
    cudaGetSymbolAddress((void**)&s, g_scratch);
    __half* hb = nullptr;
    cudaGetSymbolAddress((void**)&hb, g_hbuf);

    float* qkv  = s + OFF_QKV;
    float* qc   = s + OFF_QC;
    float* kc   = s + OFF_KC;
    float* vc   = s + OFF_VC;
    float* eg   = s + OFF_EG;
    float* gout = s + OFF_GOUT;
    float* o    = s + OFF_O;
    float* fa   = s + OFF_FA;              // fa | ga contiguous fp32
    float* beta = s + OFF_BETA;

    __half* W3   = hb + HO_W3;
    __half* WOh  = hb + HO_WO;
    __half* WFBh = hb + HO_WFB;
    __half* xh   = hb + HO_X;
    __half* fgh  = hb + HO_FG;
    __half* ogh  = hb + HO_OG;

    // persistent fork/join resources (handles only; DAG identical per call)
    static cudaStream_t sB = nullptr;
    static cudaEvent_t eFork = nullptr, eJoin = nullptr;
    if (!sB) {
        cudaStreamCreateWithFlags(&sB, cudaStreamNonBlocking);
        cudaEventCreateWithFlags(&eFork, cudaEventDisableTiming);
        cudaEventCreateWithFlags(&eJoin, cudaEventDisableTiming);
    }

    static bool attr_done = false;
    if (!attr_done) {
        cudaFuncSetAttribute(hgemm_k<0>,
                             cudaFuncAttributeMaxDynamicSharedMemorySize, H_SMEM);
        cudaFuncSetAttribute(hgemm_k<1>,
                             cudaFuncAttributeMaxDynamicSharedMemorySize, H_SMEM);
        attr_done = true;
    }

    // ---- fork chain B off the (captured) default stream ----
    cudaEventRecord(eFork, 0);
    cudaStreamWaitEvent(sB, eFork, 0);

    // ---- chain A (default stream): qkv path ----
    transpose3_h_k<<<dim3(64, 64, 3), 256>>>(Wq, Wk, Wv, W3, DM, KD);
    f2h_k<<<(unsigned)(NTK / 256), 256>>>(x, xh, (int)NTK);
    hgemm_k<0><<<dim3(48, 8), 256, H_SMEM>>>(xh, DM, W3, DM, qkv,
                                             T_LEN, 6144, DM, nullptr, nullptr);
    conv_l2_k<<<dim3(T_LEN, NH), 128>>>(qkv, conv_q, conv_k, conv_v,
                                        qc, kc, vc);

    // ---- chain B (stream sB): gates, beta, weight transposes ----
    zero_k<<<1024, 256, 0, sB>>>(fa, 262144);
    sgemm_k<1><<<dim3(1, 8, 16), 256, 0, sB>>>(x, Wfa, fa,
                                               T_LEN, DH, DM, 128);
    sgemm_k<1><<<dim3(1, 8, 16), 256, 0, sB>>>(x, Wga, fa + 131072,
                                               T_LEN, DH, DM, 128);
    f2h_k<<<1024, 256, 0, sB>>>(fa, fgh, 262144);
    transpose3_h_k<<<dim3(64, 4, 2), 256, 0, sB>>>(Wfb, Wgb, Wgb, WFBh, DH, KD);
    transpose_h_k<<<dim3(64, 64), 256, 0, sB>>>(Wo, WOh, KD, DM);
    // eg GEMM with fused gate transform (gprep folded into epilogue)
    hgemm_k<1><<<dim3(16, 8), 256, H_SMEM, sB>>>(fgh, DH, WFBh, DH, eg,
                                                 T_LEN, KD, DH, dt_b, A_log);
    hgemm_k<0><<<dim3(16, 8), 256, H_SMEM, sB>>>(fgh + 131072, DH,
                                                 WFBh + 262144, DH, gout,
                                                 T_LEN, KD, DH, nullptr, nullptr);
    beta_k<<<T_LEN, 512, 0, sB>>>(x, Wb, beta);
    cudaEventRecord(eJoin, sB);

    // ---- join, then recurrence + epilogue (default stream) ----
    cudaStreamWaitEvent(0, eJoin, 0);
    recur3_k<<<128, 256>>>(qc, kc, vc, eg, beta, o);
    epi_k<<<dim3(T_LEN, NH), 128>>>(o, gout, norm_w, ogh);
    hgemm_k<0><<<dim3(16, 8), 256, H_SMEM>>>(ogh, KD, WOh, KD, out,
                                             T_LEN, DM, KD, nullptr, nullptr);
}

// round 11
// speedup vs baseline: 3.2143x; 1.0179x over previous
#include <cuda_runtime.h>
#include <cuda_fp16.h>
#include <math.h>
#include <cstdint>

// ---------------------------------------------------------------------------
// KimiDeltaAttention  (B=1, T=1024, DM=2048, H=16, DH=128, KD=2048, KC=4)
// Round 10 (resubmit after infra failure): deep-pipelined recurrence
// (8-stage ring, distance 6) + persistent-CTA fp16 GEMM + stream overlap.
// ---------------------------------------------------------------------------

#define T_LEN 1024
#define DM    2048
#define NH    16
#define DH    128
#define KD    2048

static constexpr size_t NTK = (size_t)T_LEN * KD;   // 2097152

// fp32 scratch
#define OFF_QKV  ((size_t)0)                  // fused q|k|v GEMM out [T][6144]
#define OFF_QC   (NTK * 3)
#define OFF_KC   (NTK * 4)
#define OFF_VC   (NTK * 5)
#define OFF_EG   (NTK * 6)
#define OFF_GOUT (NTK * 7)
#define OFF_O    (NTK * 8)
#define OFF_FA   (NTK * 9)                    // fa | ga contiguous (fp32)
#define OFF_BETA (NTK * 9 + 262144)
#define SCRATCH_FLOATS (OFF_BETA + 16384)
__device__ float g_scratch[SCRATCH_FLOATS];

// fp16 scratch (halfs)
#define HO_W3   ((size_t)0)                   // [6144][2048]  WqT|WkT|WvT
#define HO_WO   ((size_t)12582912)            // [2048][2048]
#define HO_WFB  ((size_t)16777216)            // [2048][128] then WGB [2048][128]
#define HO_X    ((size_t)17301504)            // [1024][2048]
#define HO_FG   ((size_t)19398656)            // fa then ga, half
#define HO_OG   ((size_t)19660800)            // [1024][2048]
#define HBUF_HALFS ((size_t)21757952)
__device__ __half g_hbuf[HBUF_HALFS];

// ---------------------------------------------------------------------------
// helpers
// ---------------------------------------------------------------------------
__device__ __forceinline__ uint32_t smem_u32(const void* p) {
    uint32_t a;
    asm("{ .reg .u64 t; cvta.to.shared.u64 t, %1; cvt.u32.u64 %0, t; }"
        : "=r"(a) : "l"(p));
    return a;
}
__device__ __forceinline__ void cp16(uint32_t dst, const void* src) {
    asm volatile("cp.async.cg.shared.global [%0], [%1], 16;"
                 :: "r"(dst), "l"(src) : "memory");
}
__device__ __forceinline__ void cp4(uint32_t dst, const void* src) {
    asm volatile("cp.async.ca.shared.global [%0], [%1], 4;"
                 :: "r"(dst), "l"(src) : "memory");
}
#define CP_COMMIT() asm volatile("cp.async.commit_group;" ::: "memory")
#define CP_WAIT(n)  asm volatile("cp.async.wait_group %0;" :: "n"(n) : "memory")

#define LDMX4(r0, r1, r2, r3, addr) \
    asm volatile("ldmatrix.sync.aligned.m8n8.x4.shared.b16 {%0,%1,%2,%3}, [%4];" \
                 : "=r"(r0), "=r"(r1), "=r"(r2), "=r"(r3) : "r"(addr))

// gate transform: exp(-expA * softplus_stable(v + dtb))
__device__ __forceinline__ float gate_xform(float v, float dtb, float expA)
{
    float xr = fminf(fmaxf(v + dtb, -20.f), 20.f);
    float sp = log1pf(expf(xr));
    return expf(-expA * sp);
}

// ---------------------------------------------------------------------------
// fp16 GEMM (persistent CTAs): C[M,N](f32) = A[M,K](h, lda) * Bt[N,K](h)^T
// 1D grid; each CTA loops linear 128x128 tiles. 256 threads, 2 CTA/SM.
// GPREP=1: apply gate_xform(acc, dt_bias[n], exp(A_log[n>>7])) in writeback.
// ---------------------------------------------------------------------------
#define H_RS    40                     // padded row stride (halfs) = 80 B
#define H_STAGE (128 * H_RS)           // halfs per matrix per stage
#define H_SMEM  (3 * 2 * H_STAGE * 2)  // 61440 bytes

template <int GPREP>
__global__ __launch_bounds__(256, 2)
void hgemm_k(const __half* __restrict__ A, int lda,
             const __half* __restrict__ Bt, int ldb,
             float* __restrict__ C, int M, int N, int K,
             const float* __restrict__ dtb, const float* __restrict__ alog)
{
    extern __shared__ __half hsm[];

    const int tid  = threadIdx.x;
    const int wid  = tid >> 5;
    const int lane = tid & 31;
    const int wm   = wid >> 1;           // 0..3
    const int wn   = wid & 1;            // 0..1
    const int NT   = K >> 5;
    const int nTileN = N >> 7;
    const int nTiles = (M >> 7) * nTileN;

    for (int tile = blockIdx.x; tile < nTiles; tile += gridDim.x) {
        const int m0 = (tile / nTileN) * 128;
        const int n0 = (tile % nTileN) * 128;

        float acc[2][8][4];
#pragma unroll
        for (int a = 0; a < 2; a++)
#pragma unroll
            for (int b = 0; b < 8; b++)
#pragma unroll
                for (int c = 0; c < 4; c++) acc[a][b][c] = 0.f;

        auto load_stage = [&](int s, int i) {
            const __half* gA = A  + (size_t)m0 * lda + i * 32;
            const __half* gB = Bt + (size_t)n0 * ldb + i * 32;
            __half* dA = hsm + s * 2 * H_STAGE;
            __half* dB = dA + H_STAGE;
#pragma unroll
            for (int t = 0; t < 2; t++) {
                int idx = tid + t * 256;       // 0..511
                int row = idx >> 2;
                int seg = (idx & 3) * 8;       // halfs (16B chunks)
                cp16(smem_u32(dA + row * H_RS + seg),
                     gA + (size_t)row * lda + seg);
                cp16(smem_u32(dB + row * H_RS + seg),
                     gB + (size_t)row * ldb + seg);
            }
            CP_COMMIT();
        };

        load_stage(0, 0);
        load_stage(1, 1);

        for (int i = 0; i < NT; i++) {
            const int s = i % 3;
            if (i + 1 < NT) { CP_WAIT(1); } else { CP_WAIT(0); }
            __syncthreads();

            const uint32_t uA = smem_u32(hsm + s * 2 * H_STAGE);
            const uint32_t uB = uA + H_STAGE * 2;

#pragma unroll
            for (int kk = 0; kk < 32; kk += 16) {
                uint32_t af[2][4];
#pragma unroll
                for (int mt = 0; mt < 2; mt++) {
                    int row = wm * 32 + mt * 16 + (lane & 15);
                    int kof = kk + ((lane >> 4) << 3);
                    LDMX4(af[mt][0], af[mt][1], af[mt][2], af[mt][3],
                          uA + (row * H_RS + kof) * 2);
                }
                uint32_t bf[4][4];
#pragma unroll
                for (int g = 0; g < 4; g++) {
                    int nrow = wn * 64 + g * 16 + ((lane >> 4) << 3) + (lane & 7);
                    int kof = kk + (((lane >> 3) & 1) << 3);
                    LDMX4(bf[g][0], bf[g][1], bf[g][2], bf[g][3],
                          uB + (nrow * H_RS + kof) * 2);
                }
#pragma unroll
                for (int mt = 0; mt < 2; mt++)
#pragma unroll
                    for (int nt = 0; nt < 8; nt++) {
                        int g = nt >> 1, sub = nt & 1;
                        asm volatile(
                            "mma.sync.aligned.m16n8k16.row.col.f32.f16.f16.f32 "
                            "{%0,%1,%2,%3}, {%4,%5,%6,%7}, {%8,%9}, {%0,%1,%2,%3};"
                            : "+f"(acc[mt][nt][0]), "+f"(acc[mt][nt][1]),
                              "+f"(acc[mt][nt][2]), "+f"(acc[mt][nt][3])
                            : "r"(af[mt][0]), "r"(af[mt][1]),
                              "r"(af[mt][2]), "r"(af[mt][3]),
                              "r"(bf[g][sub * 2]), "r"(bf[g][sub * 2 + 1]));
                    }
            }
            if (i + 2 < NT) load_stage((i + 2) % 3, i + 2);
        }

#pragma unroll
        for (int mt = 0; mt < 2; mt++) {
            int r = m0 + wm * 32 + mt * 16 + (lane >> 2);
#pragma unroll
            for (int nt = 0; nt < 8; nt++) {
                int cn = n0 + wn * 64 + nt * 8 + (lane & 3) * 2;
                float v0a = acc[mt][nt][0], v1a = acc[mt][nt][1];
                float v0b = acc[mt][nt][2], v1b = acc[mt][nt][3];
                if (GPREP) {
                    float ea0 = expf(alog[cn >> 7]);
                    float ea1 = expf(alog[(cn + 1) >> 7]);
                    float d0 = dtb[cn], d1 = dtb[cn + 1];
                    v0a = gate_xform(v0a, d0, ea0); v1a = gate_xform(v1a, d1, ea1);
                    v0b = gate_xform(v0b, d0, ea0); v1b = gate_xform(v1b, d1, ea1);
                }
                *(float2*)(C + (size_t)r * N + cn) = make_float2(v0a, v1a);
                *(float2*)(C + (size_t)(r + 8) * N + cn) = make_float2(v0b, v1b);
            }
        }
        __syncthreads();   // smem reuse barrier between tiles
    }
}

// ---------------------------------------------------------------------------
// transpose to half, 3-way (z selects input; out strided by R*C per z)
// ---------------------------------------------------------------------------
__global__ __launch_bounds__(256)
void transpose3_h_k(const float* __restrict__ i0, const float* __restrict__ i1,
                    const float* __restrict__ i2, __half* __restrict__ out,
                    int R, int C)
{
    __shared__ float t[32][33];
    const float* in = (blockIdx.z == 0) ? i0 : (blockIdx.z == 1) ? i1 : i2;
    __half* o = out + (size_t)blockIdx.z * R * C;
    int cb = blockIdx.x * 32, rb = blockIdx.y * 32;
    int x = threadIdx.x & 31, y = threadIdx.x >> 5;
#pragma unroll
    for (int j = 0; j < 32; j += 8)
        t[y + j][x] = in[(size_t)(rb + y + j) * C + cb + x];
    __syncthreads();
#pragma unroll
    for (int j = 0; j < 32; j += 8)
        o[(size_t)(cb + y + j) * R + rb + x] = __float2half_rn(t[x][y + j]);
}

__global__ __launch_bounds__(256)
void transpose_h_k(const float* __restrict__ in, __half* __restrict__ out,
                   int R, int C)
{
    __shared__ float t[32][33];
    int cb = blockIdx.x * 32, rb = blockIdx.y * 32;
    int x = threadIdx.x & 31, y = threadIdx.x >> 5;
#pragma unroll
    for (int j = 0; j < 32; j += 8)
        t[y + j][x] = in[(size_t)(rb + y + j) * C + cb + x];
    __syncthreads();
#pragma unroll
    for (int j = 0; j < 32; j += 8)
        out[(size_t)(cb + y + j) * R + rb + x] = __float2half_rn(t[x][y + j]);
}

__global__ void f2h_k(const float* __restrict__ in, __half* __restrict__ out,
                      int n)
{
    int i = blockIdx.x * 256 + threadIdx.x;
    if (i < n) out[i] = __float2half_rn(in[i]);
}

// ---------------------------------------------------------------------------
// SIMT split-K SGEMM (tall-skinny rank-128 projections), fp32
// ---------------------------------------------------------------------------
template <int ATOMIC>
__global__ __launch_bounds__(256)
void sgemm_k(const float* __restrict__ A, const float* __restrict__ B,
             float* __restrict__ C, int M, int N, int K, int kSplit)
{
    __shared__ __align__(16) float As[8][128];
    __shared__ __align__(16) float Bs[8][128];

    const int tid  = threadIdx.x;
    const int bm   = blockIdx.y;
    const int bn   = blockIdx.x;
    const int k0   = blockIdx.z * kSplit;

    const int arow = tid >> 1;
    const int acol = (tid & 1) << 2;
    const int brow = tid >> 5;
    const int bcol = (tid & 31) << 2;
    const int ty   = tid >> 4;
    const int tx   = tid & 15;

    float acc[8][8];
#pragma unroll
    for (int i = 0; i < 8; i++)
#pragma unroll
        for (int j = 0; j < 8; j++) acc[i][j] = 0.f;

    const float* Ag = A + (size_t)(bm * 128 + arow) * K;
    const float* Bg = B + (size_t)(bn * 128) + bcol;

    for (int kt = 0; kt < kSplit; kt += 8) {
        float4 av = *(const float4*)(Ag + (k0 + kt + acol));
        As[acol + 0][arow] = av.x;
        As[acol + 1][arow] = av.y;
        As[acol + 2][arow] = av.z;
        As[acol + 3][arow] = av.w;
        *(float4*)&Bs[brow][bcol] =
            *(const float4*)(Bg + (size_t)(k0 + kt + brow) * N);
        __syncthreads();

#pragma unroll
        for (int kk = 0; kk < 8; kk++) {
            float4 a0 = *(const float4*)&As[kk][ty * 8];
            float4 a1 = *(const float4*)&As[kk][ty * 8 + 4];
            float4 b0 = *(const float4*)&Bs[kk][tx * 8];
            float4 b1 = *(const float4*)&Bs[kk][tx * 8 + 4];
            float a[8] = {a0.x, a0.y, a0.z, a0.w, a1.x, a1.y, a1.z, a1.w};
            float b[8] = {b0.x, b0.y, b0.z, b0.w, b1.x, b1.y, b1.z, b1.w};
#pragma unroll
            for (int i = 0; i < 8; i++)
#pragma unroll
                for (int j = 0; j < 8; j++)
                    acc[i][j] = fmaf(a[i], b[j], acc[i][j]);
        }
        __syncthreads();
    }

#pragma unroll
    for (int i = 0; i < 8; i++) {
        float* Cp = C + (size_t)(bm * 128 + ty * 8 + i) * N + bn * 128 + tx * 8;
        if (ATOMIC) {
#pragma unroll
            for (int j = 0; j < 8; j++) atomicAdd(Cp + j, acc[i][j]);
        } else {
            *(float4*)(Cp + 0) = make_float4(acc[i][0], acc[i][1], acc[i][2], acc[i][3]);
            *(float4*)(Cp + 4) = make_float4(acc[i][4], acc[i][5], acc[i][6], acc[i][7]);
        }
    }
}

__global__ void zero_k(float* __restrict__ p, int n)
{
    int i = blockIdx.x * 256 + threadIdx.x;
    if (i < n) p[i] = 0.f;
}

// ---------------------------------------------------------------------------
// block-of-128 reduce helper
// ---------------------------------------------------------------------------
__device__ __forceinline__ float block128_sum(float v, float* shm)
{
#pragma unroll
    for (int m = 16; m > 0; m >>= 1) v += __shfl_xor_sync(0xffffffffu, v, m);
    int w = threadIdx.x >> 5;
    if ((threadIdx.x & 31) == 0) shm[w] = v;
    __syncthreads();
    return shm[0] + shm[1] + shm[2] + shm[3];
}

// ---------------------------------------------------------------------------
// fused: depthwise causal conv (K=4) + SiLU + l2norm(q,k).  grid (T, NH).
// ---------------------------------------------------------------------------
__global__ __launch_bounds__(128)
void conv_l2_k(const float* __restrict__ qkv,
               const float* __restrict__ wq, const float* __restrict__ wk,
               const float* __restrict__ wv,
               float* __restrict__ qc, float* __restrict__ kc,
               float* __restrict__ vc)
{
    __shared__ float shm[4];
    int t = blockIdx.x, h = blockIdx.y, d = threadIdx.x;
    int c = h * DH + d;
    float aq = 0.f, ak = 0.f, av = 0.f;
#pragma unroll
    for (int j = 0; j < 4; j++) {
        int tt = t + j - 3;
        if (tt >= 0) {
            size_t base = (size_t)tt * 6144;
            aq = fmaf(wq[j * KD + c], qkv[base + c], aq);
            ak = fmaf(wk[j * KD + c], qkv[base + 2048 + c], ak);
            av = fmaf(wv[j * KD + c], qkv[base + 4096 + c], av);
        }
    }
    aq = aq / (1.f + expf(-aq));
    ak = ak / (1.f + expf(-ak));
    av = av / (1.f + expf(-av));

    size_t idx = (size_t)t * KD + c;
    vc[idx] = av;

    float ssq = block128_sum(aq * aq, shm);
    __syncthreads();
    float ssk = block128_sum(ak * ak, shm);
    qc[idx] = aq * rsqrtf(ssq + 1e-6f) * 0.08838834764831845f;
    kc[idx] = ak * rsqrtf(ssk + 1e-6f);
}

// ---------------------------------------------------------------------------
// beta = sigmoid(x @ Wb)
// ---------------------------------------------------------------------------
__global__ __launch_bounds__(512)
void beta_k(const float* __restrict__ x, const float* __restrict__ Wb,
            float* __restrict__ beta)
{
    __shared__ float sx[DM];
    int t = blockIdx.x;
    for (int i = threadIdx.x; i < DM; i += 512) sx[i] = x[(size_t)t * DM + i];
    __syncthreads();
    int h = threadIdx.x >> 5, lane = threadIdx.x & 31;
    float acc = 0.f;
    for (int k = lane; k < DM; k += 32) acc = fmaf(sx[k], Wb[k * NH + h], acc);
#pragma unroll
    for (int m = 16; m > 0; m >>= 1) acc += __shfl_xor_sync(0xffffffffu, acc, m);
    if (lane == 0) beta[t * NH + h] = 1.f / (1.f + expf(-acc));
}

// ---------------------------------------------------------------------------
// gated delta recurrence v4: 8-stage cp.async ring, prefetch distance 6.
// 16 lanes/column, 2 cols/warp, 16 cols/CTA. 3-chain single butterfly.
// grid: 128 CTAs x 256 threads.
// ---------------------------------------------------------------------------
__global__ __launch_bounds__(256)
void recur4_k(const float* __restrict__ qf, const float* __restrict__ kf,
              const float* __restrict__ vv, const float* __restrict__ eg,
              const float* __restrict__ beta, float* __restrict__ o)
{
    __shared__ __align__(16) float sq[8][128];
    __shared__ __align__(16) float sk[8][128];
    __shared__ __align__(16) float se[8][128];
    __shared__ __align__(16) float sv[8][16];
    __shared__ float sb[8];

    const int tid  = threadIdx.x;
    const int wid  = tid >> 5;
    const int lane = tid & 31;
    const int sub  = lane >> 4;
    const int l16  = lane & 15;
    const int colbase = blockIdx.x * 16;
    const int head = colbase >> 7;
    const int col  = colbase + wid * 2 + sub;
    const int hoff = head * DH;

    // producer: threads 0..31 q, 32..63 k, 64..95 eg (float4 each),
    // 96..99 v (float4 each), 100 beta (scalar).
    auto issue_stage = [&](int t) {
        int st = t & 7;
        if (tid < 96) {
            int arr = tid >> 5;
            int off = (tid & 31) * 4;
            const float* src = (arr == 0 ? qf : (arr == 1 ? kf : eg))
                               + (size_t)t * KD + hoff + off;
            float* dst = (arr == 0 ? sq[st] : (arr == 1 ? sk[st] : se[st])) + off;
            cp16(smem_u32(dst), src);
        } else if (tid < 100) {
            int off = (tid - 96) * 4;
            cp16(smem_u32(sv[st] + off),
                 vv + (size_t)t * KD + colbase + off);
        } else if (tid == 100) {
            cp4(smem_u32(&sb[st]), beta + t * NH + head);
        }
        CP_COMMIT();
    };

#pragma unroll
    for (int p = 0; p < 6; p++) issue_stage(p);

    float s0 = 0.f, s1 = 0.f, s2 = 0.f, s3 = 0.f;
    float s4 = 0.f, s5 = 0.f, s6 = 0.f, s7 = 0.f;

    for (int t = 0; t < T_LEN; t++) {
        const int st = t & 7;
        CP_WAIT(5);
        __syncthreads();

        float4 kv0 = *(const float4*)&sk[st][l16 * 8];
        float4 kv1 = *(const float4*)&sk[st][l16 * 8 + 4];
        float4 qv0 = *(const float4*)&sq[st][l16 * 8];
        float4 qv1 = *(const float4*)&sq[st][l16 * 8 + 4];
        float4 ev0 = *(const float4*)&se[st][l16 * 8];
        float4 ev1 = *(const float4*)&se[st][l16 * 8 + 4];
        float vval = sv[st][wid * 2 + sub];
        float bet  = sb[st];

        // prefetch stage t+6 (slot (t-2)&7: last read two barriers ago)
        if (t + 6 < T_LEN) issue_stage(t + 6);
        else               CP_COMMIT();   // keep group counts uniform

        // decay
        s0 *= ev0.x; s1 *= ev0.y; s2 *= ev0.z; s3 *= ev0.w;
        s4 *= ev1.x; s5 *= ev1.y; s6 *= ev1.z; s7 *= ev1.w;

        // three interleaved partial dots: r1=k.S', r2=q.S', r3=q.k
        float r1 = s0 * kv0.x; float r2 = s0 * qv0.x; float r3 = kv0.x * qv0.x;
        r1 = fmaf(s1, kv0.y, r1); r2 = fmaf(s1, qv0.y, r2); r3 = fmaf(kv0.y, qv0.y, r3);
        r1 = fmaf(s2, kv0.z, r1); r2 = fmaf(s2, qv0.z, r2); r3 = fmaf(kv0.z, qv0.z, r3);
        r1 = fmaf(s3, kv0.w, r1); r2 = fmaf(s3, qv0.w, r2); r3 = fmaf(kv0.w, qv0.w, r3);
        r1 = fmaf(s4, kv1.x, r1); r2 = fmaf(s4, qv1.x, r2); r3 = fmaf(kv1.x, qv1.x, r3);
        r1 = fmaf(s5, kv1.y, r1); r2 = fmaf(s5, qv1.y, r2); r3 = fmaf(kv1.y, qv1.y, r3);
        r1 = fmaf(s6, kv1.z, r1); r2 = fmaf(s6, qv1.z, r2); r3 = fmaf(kv1.z, qv1.z, r3);
        r1 = fmaf(s7, kv1.w, r1); r2 = fmaf(s7, qv1.w, r2); r3 = fmaf(kv1.w, qv1.w, r3);

        // single 4-level butterfly over 16-lane group, 3 chains
#pragma unroll
        for (int m = 8; m > 0; m >>= 1) {
            r1 += __shfl_xor_sync(0xffffffffu, r1, m);
            r2 += __shfl_xor_sync(0xffffffffu, r2, m);
            r3 += __shfl_xor_sync(0xffffffffu, r3, m);
        }

        float upd = bet * (vval - r1);

        s0 = fmaf(kv0.x, upd, s0); s1 = fmaf(kv0.y, upd, s1);
        s2 = fmaf(kv0.z, upd, s2); s3 = fmaf(kv0.w, upd, s3);
        s4 = fmaf(kv1.x, upd, s4); s5 = fmaf(kv1.y, upd, s5);
        s6 = fmaf(kv1.z, upd, s6); s7 = fmaf(kv1.w, upd, s7);

        // o = q.S_new = r2 + r3*upd
        if (l16 == 0) o[(size_t)t * KD + col] = fmaf(r3, upd, r2);
    }
}

// ---------------------------------------------------------------------------
// epilogue: og(half) = o * rsqrt(mean(o^2)+eps) * norm_w * sigmoid(gout)
// ---------------------------------------------------------------------------
__global__ __launch_bounds__(128)
void epi_k(const float* __restrict__ o, const float* __restrict__ gout,
           const float* __restrict__ norm_w, __half* __restrict__ og)
{
    __shared__ float shm[4];
    int t = blockIdx.x, h = blockIdx.y, d = threadIdx.x;
    size_t idx = (size_t)t * KD + h * DH + d;
    float ov = o[idx];
    float ss = block128_sum(ov * ov, shm);
    float rstd = rsqrtf(ss * (1.f / 128.f) + 1e-6f);
    float gate = 1.f / (1.f + expf(-gout[idx]));
    og[idx] = __float2half_rn(ov * rstd * norm_w[d] * gate);
}

// ---------------------------------------------------------------------------
// launch: two-stream DAG. Chain B (gates/weights) overlaps chain A (qkv).
// ---------------------------------------------------------------------------
extern "C" void kernel_launch(void* const* d_in, const int* in_sizes, int n_in,
                              void* d_out, int out_size)
{
    (void)in_sizes; (void)n_in; (void)out_size;
    const float* x      = (const float*)d_in[0];
    const float* Wq     = (const float*)d_in[1];
    const float* Wk     = (const float*)d_in[2];
    const float* Wv     = (const float*)d_in[3];
    const float* conv_q = (const float*)d_in[4];
    const float* conv_k = (const float*)d_in[5];
    const float* conv_v = (const float*)d_in[6];
    const float* Wfa    = (const float*)d_in[7];
    const float* Wfb    = (const float*)d_in[8];
    const float* dt_b   = (const float*)d_in[9];
    const float* A_log  = (const float*)d_in[10];
    const float* Wb     = (const float*)d_in[11];
    const float* Wga    = (const float*)d_in[12];
    const float* Wgb    = (const float*)d_in[13];
    const float* norm_w = (const float*)d_in[14];
    const float* Wo     = (const float*)d_in[15];
    float* out = (float*)d_out;

    float* s = nullptr;
    cudaGetSymbolAddress((void**)&s, g_scratch);
    __half* hb = nullptr;
    cudaGetSymbolAddress((void**)&hb, g_hbuf);

    float* qkv  = s + OFF_QKV;
    float* qc   = s + OFF_QC;
    float* kc   = s + OFF_KC;
    float* vc   = s + OFF_VC;
    float* eg   = s + OFF_EG;
    float* gout = s + OFF_GOUT;
    float* o    = s + OFF_O;
    float* fa   = s + OFF_FA;              // fa | ga contiguous fp32
    float* beta = s + OFF_BETA;

    __half* W3   = hb + HO_W3;
    __half* WOh  = hb + HO_WO;
    __half* WFBh = hb + HO_WFB;
    __half* xh   = hb + HO_X;
    __half* fgh  = hb + HO_FG;
    __half* ogh  = hb + HO_OG;

    // persistent fork/join resources (handles only; DAG identical per call)
    static cudaStream_t sB = nullptr;
    static cudaEvent_t eFork = nullptr, eJoin = nullptr;
    if (!sB) {
        cudaStreamCreateWithFlags(&sB, cudaStreamNonBlocking);
        cudaEventCreateWithFlags(&eFork, cudaEventDisableTiming);
        cudaEventCreateWithFlags(&eJoin, cudaEventDisableTiming);
    }

    static bool attr_done = false;
    if (!attr_done) {
        cudaFuncSetAttribute(hgemm_k<0>,
                             cudaFuncAttributeMaxDynamicSharedMemorySize, H_SMEM);
        cudaFuncSetAttribute(hgemm_k<1>,
                             cudaFuncAttributeMaxDynamicSharedMemorySize, H_SMEM);
        attr_done = true;
    }

    // ---- fork chain B off the (captured) default stream ----
    cudaEventRecord(eFork, 0);
    cudaStreamWaitEvent(sB, eFork, 0);

    // ---- chain A (default stream): qkv path ----
    transpose3_h_k<<<dim3(64, 64, 3), 256>>>(Wq, Wk, Wv, W3, DM, KD);
    f2h_k<<<(unsigned)(NTK / 256), 256>>>(x, xh, (int)NTK);
    hgemm_k<0><<<296, 256, H_SMEM>>>(xh, DM, W3, DM, qkv,
                                     T_LEN, 6144, DM, nullptr, nullptr);
    conv_l2_k<<<dim3(T_LEN, NH), 128>>>(qkv, conv_q, conv_k, conv_v,
                                        qc, kc, vc);

    // ---- chain B (stream sB): gates, beta, weight transposes ----
    zero_k<<<1024, 256, 0, sB>>>(fa, 262144);
    sgemm_k<1><<<dim3(1, 8, 16), 256, 0, sB>>>(x, Wfa, fa,
                                               T_LEN, DH, DM, 128);
    sgemm_k<1><<<dim3(1, 8, 16), 256, 0, sB>>>(x, Wga, fa + 131072,
                                               T_LEN, DH, DM, 128);
    f2h_k<<<1024, 256, 0, sB>>>(fa, fgh, 262144);
    transpose3_h_k<<<dim3(64, 4, 2), 256, 0, sB>>>(Wfb, Wgb, Wgb, WFBh, DH, KD);
    transpose_h_k<<<dim3(64, 64), 256, 0, sB>>>(Wo, WOh, KD, DM);
    hgemm_k<1><<<128, 256, H_SMEM, sB>>>(fgh, DH, WFBh, DH, eg,
                                         T_LEN, KD, DH, dt_b, A_log);
    hgemm_k<0><<<128, 256, H_SMEM, sB>>>(fgh + 131072, DH,
                                         WFBh + 262144, DH, gout,
                                         T_LEN, KD, DH, nullptr, nullptr);
    beta_k<<<T_LEN, 512, 0, sB>>>(x, Wb, beta);
    cudaEventRecord(eJoin, sB);

    // ---- join, then recurrence + epilogue (default stream) ----
    cudaStreamWaitEvent(0, eJoin, 0);
    recur4_k<<<128, 256>>>(qc, kc, vc, eg, beta, o);
    epi_k<<<dim3(T_LEN, NH), 128>>>(o, gout, norm_w, ogh);
    hgemm_k<0><<<128, 256, H_SMEM>>>(ogh, KD, WOh, KD, out,
                                     T_LEN, DM, KD, nullptr, nullptr);
}

// round 13
// speedup vs baseline: 3.6438x; 1.1336x over previous
#include <cuda_runtime.h>
#include <cuda_fp16.h>
#include <math.h>
#include <cstdint>

// ---------------------------------------------------------------------------
// KimiDeltaAttention  (B=1, T=1024, DM=2048, H=16, DH=128, KD=2048, KC=4)
// Round 12 (resubmit after infra failure): recurrence v5 — conflict-free
// smem lane permutation + 2-step unroll. GEMMs / overlap as round 10.
// ---------------------------------------------------------------------------

#define T_LEN 1024
#define DM    2048
#define NH    16
#define DH    128
#define KD    2048

static constexpr size_t NTK = (size_t)T_LEN * KD;   // 2097152

// fp32 scratch
#define OFF_QKV  ((size_t)0)                  // fused q|k|v GEMM out [T][6144]
#define OFF_QC   (NTK * 3)
#define OFF_KC   (NTK * 4)
#define OFF_VC   (NTK * 5)
#define OFF_EG   (NTK * 6)
#define OFF_GOUT (NTK * 7)
#define OFF_O    (NTK * 8)
#define OFF_FA   (NTK * 9)                    // fa | ga contiguous (fp32)
#define OFF_BETA (NTK * 9 + 262144)
#define SCRATCH_FLOATS (OFF_BETA + 16384)
__device__ float g_scratch[SCRATCH_FLOATS];

// fp16 scratch (halfs)
#define HO_W3   ((size_t)0)                   // [6144][2048]  WqT|WkT|WvT
#define HO_WO   ((size_t)12582912)            // [2048][2048]
#define HO_WFB  ((size_t)16777216)            // [2048][128] then WGB [2048][128]
#define HO_X    ((size_t)17301504)            // [1024][2048]
#define HO_FG   ((size_t)19398656)            // fa then ga, half
#define HO_OG   ((size_t)19660800)            // [1024][2048]
#define HBUF_HALFS ((size_t)21757952)
__device__ __half g_hbuf[HBUF_HALFS];

// ---------------------------------------------------------------------------
// helpers
// ---------------------------------------------------------------------------
__device__ __forceinline__ uint32_t smem_u32(const void* p) {
    uint32_t a;
    asm("{ .reg .u64 t; cvta.to.shared.u64 t, %1; cvt.u32.u64 %0, t; }"
        : "=r"(a) : "l"(p));
    return a;
}
__device__ __forceinline__ void cp16(uint32_t dst, const void* src) {
    asm volatile("cp.async.cg.shared.global [%0], [%1], 16;"
                 :: "r"(dst), "l"(src) : "memory");
}
__device__ __forceinline__ void cp4(uint32_t dst, const void* src) {
    asm volatile("cp.async.ca.shared.global [%0], [%1], 4;"
                 :: "r"(dst), "l"(src) : "memory");
}
#define CP_COMMIT() asm volatile("cp.async.commit_group;" ::: "memory")
#define CP_WAIT(n)  asm volatile("cp.async.wait_group %0;" :: "n"(n) : "memory")

#define LDMX4(r0, r1, r2, r3, addr) \
    asm volatile("ldmatrix.sync.aligned.m8n8.x4.shared.b16 {%0,%1,%2,%3}, [%4];" \
                 : "=r"(r0), "=r"(r1), "=r"(r2), "=r"(r3) : "r"(addr))

// gate transform: exp(-expA * softplus_stable(v + dtb))
__device__ __forceinline__ float gate_xform(float v, float dtb, float expA)
{
    float xr = fminf(fmaxf(v + dtb, -20.f), 20.f);
    float sp = log1pf(expf(xr));
    return expf(-expA * sp);
}

// ---------------------------------------------------------------------------
// fp16 GEMM (persistent CTAs): C[M,N](f32) = A[M,K](h, lda) * Bt[N,K](h)^T
// ---------------------------------------------------------------------------
#define H_RS    40                     // padded row stride (halfs) = 80 B
#define H_STAGE (128 * H_RS)           // halfs per matrix per stage
#define H_SMEM  (3 * 2 * H_STAGE * 2)  // 61440 bytes

template <int GPREP>
__global__ __launch_bounds__(256, 2)
void hgemm_k(const __half* __restrict__ A, int lda,
             const __half* __restrict__ Bt, int ldb,
             float* __restrict__ C, int M, int N, int K,
             const float* __restrict__ dtb, const float* __restrict__ alog)
{
    extern __shared__ __half hsm[];

    const int tid  = threadIdx.x;
    const int wid  = tid >> 5;
    const int lane = tid & 31;
    const int wm   = wid >> 1;           // 0..3
    const int wn   = wid & 1;            // 0..1
    const int NT   = K >> 5;
    const int nTileN = N >> 7;
    const int nTiles = (M >> 7) * nTileN;

    for (int tile = blockIdx.x; tile < nTiles; tile += gridDim.x) {
        const int m0 = (tile / nTileN) * 128;
        const int n0 = (tile % nTileN) * 128;

        float acc[2][8][4];
#pragma unroll
        for (int a = 0; a < 2; a++)
#pragma unroll
            for (int b = 0; b < 8; b++)
#pragma unroll
                for (int c = 0; c < 4; c++) acc[a][b][c] = 0.f;

        auto load_stage = [&](int s, int i) {
            const __half* gA = A  + (size_t)m0 * lda + i * 32;
            const __half* gB = Bt + (size_t)n0 * ldb + i * 32;
            __half* dA = hsm + s * 2 * H_STAGE;
            __half* dB = dA + H_STAGE;
#pragma unroll
            for (int t = 0; t < 2; t++) {
                int idx = tid + t * 256;       // 0..511
                int row = idx >> 2;
                int seg = (idx & 3) * 8;       // halfs (16B chunks)
                cp16(smem_u32(dA + row * H_RS + seg),
                     gA + (size_t)row * lda + seg);
                cp16(smem_u32(dB + row * H_RS + seg),
                     gB + (size_t)row * ldb + seg);
            }
            CP_COMMIT();
        };

        load_stage(0, 0);
        load_stage(1, 1);

        for (int i = 0; i < NT; i++) {
            const int s = i % 3;
            if (i + 1 < NT) { CP_WAIT(1); } else { CP_WAIT(0); }
            __syncthreads();

            const uint32_t uA = smem_u32(hsm + s * 2 * H_STAGE);
            const uint32_t uB = uA + H_STAGE * 2;

#pragma unroll
            for (int kk = 0; kk < 32; kk += 16) {
                uint32_t af[2][4];
#pragma unroll
                for (int mt = 0; mt < 2; mt++) {
                    int row = wm * 32 + mt * 16 + (lane & 15);
                    int kof = kk + ((lane >> 4) << 3);
                    LDMX4(af[mt][0], af[mt][1], af[mt][2], af[mt][3],
                          uA + (row * H_RS + kof) * 2);
                }
                uint32_t bf[4][4];
#pragma unroll
                for (int g = 0; g < 4; g++) {
                    int nrow = wn * 64 + g * 16 + ((lane >> 4) << 3) + (lane & 7);
                    int kof = kk + (((lane >> 3) & 1) << 3);
                    LDMX4(bf[g][0], bf[g][1], bf[g][2], bf[g][3],
                          uB + (nrow * H_RS + kof) * 2);
                }
#pragma unroll
                for (int mt = 0; mt < 2; mt++)
#pragma unroll
                    for (int nt = 0; nt < 8; nt++) {
                        int g = nt >> 1, sub = nt & 1;
                        asm volatile(
                            "mma.sync.aligned.m16n8k16.row.col.f32.f16.f16.f32 "
                            "{%0,%1,%2,%3}, {%4,%5,%6,%7}, {%8,%9}, {%0,%1,%2,%3};"
                            : "+f"(acc[mt][nt][0]), "+f"(acc[mt][nt][1]),
                              "+f"(acc[mt][nt][2]), "+f"(acc[mt][nt][3])
                            : "r"(af[mt][0]), "r"(af[mt][1]),
                              "r"(af[mt][2]), "r"(af[mt][3]),
                              "r"(bf[g][sub * 2]), "r"(bf[g][sub * 2 + 1]));
                    }
            }
            if (i + 2 < NT) load_stage((i + 2) % 3, i + 2);
        }

#pragma unroll
        for (int mt = 0; mt < 2; mt++) {
            int r = m0 + wm * 32 + mt * 16 + (lane >> 2);
#pragma unroll
            for (int nt = 0; nt < 8; nt++) {
                int cn = n0 + wn * 64 + nt * 8 + (lane & 3) * 2;
                float v0a = acc[mt][nt][0], v1a = acc[mt][nt][1];
                float v0b = acc[mt][nt][2], v1b = acc[mt][nt][3];
                if (GPREP) {
                    float ea0 = expf(alog[cn >> 7]);
                    float ea1 = expf(alog[(cn + 1) >> 7]);
                    float d0 = dtb[cn], d1 = dtb[cn + 1];
                    v0a = gate_xform(v0a, d0, ea0); v1a = gate_xform(v1a, d1, ea1);
                    v0b = gate_xform(v0b, d0, ea0); v1b = gate_xform(v1b, d1, ea1);
                }
                *(float2*)(C + (size_t)r * N + cn) = make_float2(v0a, v1a);
                *(float2*)(C + (size_t)(r + 8) * N + cn) = make_float2(v0b, v1b);
            }
        }
        __syncthreads();   // smem reuse barrier between tiles
    }
}

// ---------------------------------------------------------------------------
// transpose to half, 3-way (z selects input; out strided by R*C per z)
// ---------------------------------------------------------------------------
__global__ __launch_bounds__(256)
void transpose3_h_k(const float* __restrict__ i0, const float* __restrict__ i1,
                    const float* __restrict__ i2, __half* __restrict__ out,
                    int R, int C)
{
    __shared__ float t[32][33];
    const float* in = (blockIdx.z == 0) ? i0 : (blockIdx.z == 1) ? i1 : i2;
    __half* o = out + (size_t)blockIdx.z * R * C;
    int cb = blockIdx.x * 32, rb = blockIdx.y * 32;
    int x = threadIdx.x & 31, y = threadIdx.x >> 5;
#pragma unroll
    for (int j = 0; j < 32; j += 8)
        t[y + j][x] = in[(size_t)(rb + y + j) * C + cb + x];
    __syncthreads();
#pragma unroll
    for (int j = 0; j < 32; j += 8)
        o[(size_t)(cb + y + j) * R + rb + x] = __float2half_rn(t[x][y + j]);
}

__global__ __launch_bounds__(256)
void transpose_h_k(const float* __restrict__ in, __half* __restrict__ out,
                   int R, int C)
{
    __shared__ float t[32][33];
    int cb = blockIdx.x * 32, rb = blockIdx.y * 32;
    int x = threadIdx.x & 31, y = threadIdx.x >> 5;
#pragma unroll
    for (int j = 0; j < 32; j += 8)
        t[y + j][x] = in[(size_t)(rb + y + j) * C + cb + x];
    __syncthreads();
#pragma unroll
    for (int j = 0; j < 32; j += 8)
        out[(size_t)(cb + y + j) * R + rb + x] = __float2half_rn(t[x][y + j]);
}

__global__ void f2h_k(const float* __restrict__ in, __half* __restrict__ out,
                      int n)
{
    int i = blockIdx.x * 256 + threadIdx.x;
    if (i < n) out[i] = __float2half_rn(in[i]);
}

// ---------------------------------------------------------------------------
// SIMT split-K SGEMM (tall-skinny rank-128 projections), fp32
// ---------------------------------------------------------------------------
template <int ATOMIC>
__global__ __launch_bounds__(256)
void sgemm_k(const float* __restrict__ A, const float* __restrict__ B,
             float* __restrict__ C, int M, int N, int K, int kSplit)
{
    __shared__ __align__(16) float As[8][128];
    __shared__ __align__(16) float Bs[8][128];

    const int tid  = threadIdx.x;
    const int bm   = blockIdx.y;
    const int bn   = blockIdx.x;
    const int k0   = blockIdx.z * kSplit;

    const int arow = tid >> 1;
    const int acol = (tid & 1) << 2;
    const int brow = tid >> 5;
    const int bcol = (tid & 31) << 2;
    const int ty   = tid >> 4;
    const int tx   = tid & 15;

    float acc[8][8];
#pragma unroll
    for (int i = 0; i < 8; i++)
#pragma unroll
        for (int j = 0; j < 8; j++) acc[i][j] = 0.f;

    const float* Ag = A + (size_t)(bm * 128 + arow) * K;
    const float* Bg = B + (size_t)(bn * 128) + bcol;

    for (int kt = 0; kt < kSplit; kt += 8) {
        float4 av = *(const float4*)(Ag + (k0 + kt + acol));
        As[acol + 0][arow] = av.x;
        As[acol + 1][arow] = av.y;
        As[acol + 2][arow] = av.z;
        As[acol + 3][arow] = av.w;
        *(float4*)&Bs[brow][bcol] =
            *(const float4*)(Bg + (size_t)(k0 + kt + brow) * N);
        __syncthreads();

#pragma unroll
        for (int kk = 0; kk < 8; kk++) {
            float4 a0 = *(const float4*)&As[kk][ty * 8];
            float4 a1 = *(const float4*)&As[kk][ty * 8 + 4];
            float4 b0 = *(const float4*)&Bs[kk][tx * 8];
            float4 b1 = *(const float4*)&Bs[kk][tx * 8 + 4];
            float a[8] = {a0.x, a0.y, a0.z, a0.w, a1.x, a1.y, a1.z, a1.w};
            float b[8] = {b0.x, b0.y, b0.z, b0.w, b1.x, b1.y, b1.z, b1.w};
#pragma unroll
            for (int i = 0; i < 8; i++)
#pragma unroll
                for (int j = 0; j < 8; j++)
                    acc[i][j] = fmaf(a[i], b[j], acc[i][j]);
        }
        __syncthreads();
    }

#pragma unroll
    for (int i = 0; i < 8; i++) {
        float* Cp = C + (size_t)(bm * 128 + ty * 8 + i) * N + bn * 128 + tx * 8;
        if (ATOMIC) {
#pragma unroll
            for (int j = 0; j < 8; j++) atomicAdd(Cp + j, acc[i][j]);
        } else {
            *(float4*)(Cp + 0) = make_float4(acc[i][0], acc[i][1], acc[i][2], acc[i][3]);
            *(float4*)(Cp + 4) = make_float4(acc[i][4], acc[i][5], acc[i][6], acc[i][7]);
        }
    }
}

__global__ void zero_k(float* __restrict__ p, int n)
{
    int i = blockIdx.x * 256 + threadIdx.x;
    if (i < n) p[i] = 0.f;
}

// ---------------------------------------------------------------------------
// block-of-128 reduce helper
// ---------------------------------------------------------------------------
__device__ __forceinline__ float block128_sum(float v, float* shm)
{
#pragma unroll
    for (int m = 16; m > 0; m >>= 1) v += __shfl_xor_sync(0xffffffffu, v, m);
    int w = threadIdx.x >> 5;
    if ((threadIdx.x & 31) == 0) shm[w] = v;
    __syncthreads();
    return shm[0] + shm[1] + shm[2] + shm[3];
}

// ---------------------------------------------------------------------------
// fused: depthwise causal conv (K=4) + SiLU + l2norm(q,k).  grid (T, NH).
// ---------------------------------------------------------------------------
__global__ __launch_bounds__(128)
void conv_l2_k(const float* __restrict__ qkv,
               const float* __restrict__ wq, const float* __restrict__ wk,
               const float* __restrict__ wv,
               float* __restrict__ qc, float* __restrict__ kc,
               float* __restrict__ vc)
{
    __shared__ float shm[4];
    int t = blockIdx.x, h = blockIdx.y, d = threadIdx.x;
    int c = h * DH + d;
    float aq = 0.f, ak = 0.f, av = 0.f;
#pragma unroll
    for (int j = 0; j < 4; j++) {
        int tt = t + j - 3;
        if (tt >= 0) {
            size_t base = (size_t)tt * 6144;
            aq = fmaf(wq[j * KD + c], qkv[base + c], aq);
            ak = fmaf(wk[j * KD + c], qkv[base + 2048 + c], ak);
            av = fmaf(wv[j * KD + c], qkv[base + 4096 + c], av);
        }
    }
    aq = aq / (1.f + expf(-aq));
    ak = ak / (1.f + expf(-ak));
    av = av / (1.f + expf(-av));

    size_t idx = (size_t)t * KD + c;
    vc[idx] = av;

    float ssq = block128_sum(aq * aq, shm);
    __syncthreads();
    float ssk = block128_sum(ak * ak, shm);
    qc[idx] = aq * rsqrtf(ssq + 1e-6f) * 0.08838834764831845f;
    kc[idx] = ak * rsqrtf(ssk + 1e-6f);
}

// ---------------------------------------------------------------------------
// beta = sigmoid(x @ Wb)
// ---------------------------------------------------------------------------
__global__ __launch_bounds__(512)
void beta_k(const float* __restrict__ x, const float* __restrict__ Wb,
            float* __restrict__ beta)
{
    __shared__ float sx[DM];
    int t = blockIdx.x;
    for (int i = threadIdx.x; i < DM; i += 512) sx[i] = x[(size_t)t * DM + i];
    __syncthreads();
    int h = threadIdx.x >> 5, lane = threadIdx.x & 31;
    float acc = 0.f;
    for (int k = lane; k < DM; k += 32) acc = fmaf(sx[k], Wb[k * NH + h], acc);
#pragma unroll
    for (int m = 16; m > 0; m >>= 1) acc += __shfl_xor_sync(0xffffffffu, acc, m);
    if (lane == 0) beta[t * NH + h] = 1.f / (1.f + expf(-acc));
}

// ---------------------------------------------------------------------------
// gated delta recurrence v5: conflict-free lane mapping + 2-step unroll.
// Lane l16 owns dims {4*l16..4*l16+3} U {64+4*l16..64+4*l16+3} (permutation
// of the 128 dims -- dots are permutation-invariant). float4 loads at index
// l16 / l16+16 -> all 32 banks, conflict-free. 8-stage ring, distance 6,
// one CP_WAIT+__syncthreads per TWO timesteps. grid 128 x 256.
// ---------------------------------------------------------------------------
__device__ __forceinline__ void recur_step(
    const float4 kv0, const float4 kv1, const float4 qv0, const float4 qv1,
    const float4 ev0, const float4 ev1, const float vval, const float bet,
    float* s, float* out /* valid only for l16==0 lanes */)
{
    // decay
    s[0] *= ev0.x; s[1] *= ev0.y; s[2] *= ev0.z; s[3] *= ev0.w;
    s[4] *= ev1.x; s[5] *= ev1.y; s[6] *= ev1.z; s[7] *= ev1.w;

    // three interleaved partial dots: r1=k.S', r2=q.S', r3=q.k
    float r1 = s[0] * kv0.x; float r2 = s[0] * qv0.x; float r3 = kv0.x * qv0.x;
    r1 = fmaf(s[1], kv0.y, r1); r2 = fmaf(s[1], qv0.y, r2); r3 = fmaf(kv0.y, qv0.y, r3);
    r1 = fmaf(s[2], kv0.z, r1); r2 = fmaf(s[2], qv0.z, r2); r3 = fmaf(kv0.z, qv0.z, r3);
    r1 = fmaf(s[3], kv0.w, r1); r2 = fmaf(s[3], qv0.w, r2); r3 = fmaf(kv0.w, qv0.w, r3);
    r1 = fmaf(s[4], kv1.x, r1); r2 = fmaf(s[4], qv1.x, r2); r3 = fmaf(kv1.x, qv1.x, r3);
    r1 = fmaf(s[5], kv1.y, r1); r2 = fmaf(s[5], qv1.y, r2); r3 = fmaf(kv1.y, qv1.y, r3);
    r1 = fmaf(s[6], kv1.z, r1); r2 = fmaf(s[6], qv1.z, r2); r3 = fmaf(kv1.z, qv1.z, r3);
    r1 = fmaf(s[7], kv1.w, r1); r2 = fmaf(s[7], qv1.w, r2); r3 = fmaf(kv1.w, qv1.w, r3);

#pragma unroll
    for (int m = 8; m > 0; m >>= 1) {
        r1 += __shfl_xor_sync(0xffffffffu, r1, m);
        r2 += __shfl_xor_sync(0xffffffffu, r2, m);
        r3 += __shfl_xor_sync(0xffffffffu, r3, m);
    }

    float upd = bet * (vval - r1);

    s[0] = fmaf(kv0.x, upd, s[0]); s[1] = fmaf(kv0.y, upd, s[1]);
    s[2] = fmaf(kv0.z, upd, s[2]); s[3] = fmaf(kv0.w, upd, s[3]);
    s[4] = fmaf(kv1.x, upd, s[4]); s[5] = fmaf(kv1.y, upd, s[5]);
    s[6] = fmaf(kv1.z, upd, s[6]); s[7] = fmaf(kv1.w, upd, s[7]);

    *out = fmaf(r3, upd, r2);   // o = q.S_new
}

__global__ __launch_bounds__(256)
void recur5_k(const float* __restrict__ qf, const float* __restrict__ kf,
              const float* __restrict__ vv, const float* __restrict__ eg,
              const float* __restrict__ beta, float* __restrict__ o)
{
    __shared__ __align__(16) float sq[8][128];
    __shared__ __align__(16) float sk[8][128];
    __shared__ __align__(16) float se[8][128];
    __shared__ __align__(16) float sv[8][16];
    __shared__ float sb[8];

    const int tid  = threadIdx.x;
    const int wid  = tid >> 5;
    const int lane = tid & 31;
    const int sub  = lane >> 4;
    const int l16  = lane & 15;
    const int colbase = blockIdx.x * 16;
    const int head = colbase >> 7;
    const int col  = colbase + wid * 2 + sub;
    const int hoff = head * DH;

    // producer: threads 0..31 q, 32..63 k, 64..95 eg (float4 each),
    // 96..99 v (float4 each), 100 beta (scalar).
    auto issue_stage = [&](int t) {
        int st = t & 7;
        if (tid < 96) {
            int arr = tid >> 5;
            int off = (tid & 31) * 4;
            const float* src = (arr == 0 ? qf : (arr == 1 ? kf : eg))
                               + (size_t)t * KD + hoff + off;
            float* dst = (arr == 0 ? sq[st] : (arr == 1 ? sk[st] : se[st])) + off;
            cp16(smem_u32(dst), src);
        } else if (tid < 100) {
            int off = (tid - 96) * 4;
            cp16(smem_u32(sv[st] + off),
                 vv + (size_t)t * KD + colbase + off);
        } else if (tid == 100) {
            cp4(smem_u32(&sb[st]), beta + t * NH + head);
        }
        CP_COMMIT();
    };

#pragma unroll
    for (int p = 0; p < 6; p++) issue_stage(p);

    float s[8];
#pragma unroll
    for (int i = 0; i < 8; i++) s[i] = 0.f;

    for (int t = 0; t < T_LEN; t += 2) {
        const int st0 = t & 7;
        const int st1 = (t + 1) & 7;
        CP_WAIT(4);                 // stages t, t+1 landed (4 younger pending)
        __syncthreads();

        // conflict-free float4 loads: index l16 and l16+16
        float4 kA0 = ((const float4*)sk[st0])[l16];
        float4 kA1 = ((const float4*)sk[st0])[l16 + 16];
        float4 qA0 = ((const float4*)sq[st0])[l16];
        float4 qA1 = ((const float4*)sq[st0])[l16 + 16];
        float4 eA0 = ((const float4*)se[st0])[l16];
        float4 eA1 = ((const float4*)se[st0])[l16 + 16];
        float  vA  = sv[st0][wid * 2 + sub];
        float  bA  = sb[st0];

        float4 kB0 = ((const float4*)sk[st1])[l16];
        float4 kB1 = ((const float4*)sk[st1])[l16 + 16];
        float4 qB0 = ((const float4*)sq[st1])[l16];
        float4 qB1 = ((const float4*)sq[st1])[l16 + 16];
        float4 eB0 = ((const float4*)se[st1])[l16];
        float4 eB1 = ((const float4*)se[st1])[l16 + 16];
        float  vB  = sv[st1][wid * 2 + sub];
        float  bB  = sb[st1];

        // prefetch stages t+6, t+7 (slots consumed before this barrier)
        if (t + 6 < T_LEN) issue_stage(t + 6); else CP_COMMIT();
        if (t + 7 < T_LEN) issue_stage(t + 7); else CP_COMMIT();

        float oA, oB;
        recur_step(kA0, kA1, qA0, qA1, eA0, eA1, vA, bA, s, &oA);
        recur_step(kB0, kB1, qB0, qB1, eB0, eB1, vB, bB, s, &oB);

        if (l16 == 0) {
            o[(size_t)t * KD + col] = oA;
            o[(size_t)(t + 1) * KD + col] = oB;
        }
    }
}

// ---------------------------------------------------------------------------
// epilogue: og(half) = o * rsqrt(mean(o^2)+eps) * norm_w * sigmoid(gout)
// ---------------------------------------------------------------------------
__global__ __launch_bounds__(128)
void epi_k(const float* __restrict__ o, const float* __restrict__ gout,
           const float* __restrict__ norm_w, __half* __restrict__ og)
{
    __shared__ float shm[4];
    int t = blockIdx.x, h = blockIdx.y, d = threadIdx.x;
    size_t idx = (size_t)t * KD + h * DH + d;
    float ov = o[idx];
    float ss = block128_sum(ov * ov, shm);
    float rstd = rsqrtf(ss * (1.f / 128.f) + 1e-6f);
    float gate = 1.f / (1.f + expf(-gout[idx]));
    og[idx] = __float2half_rn(ov * rstd * norm_w[d] * gate);
}

// ---------------------------------------------------------------------------
// launch: two-stream DAG. Chain B (gates/weights) overlaps chain A (qkv).
// ---------------------------------------------------------------------------
extern "C" void kernel_launch(void* const* d_in, const int* in_sizes, int n_in,
                              void* d_out, int out_size)
{
    (void)in_sizes; (void)n_in; (void)out_size;
    const float* x      = (const float*)d_in[0];
    const float* Wq     = (const float*)d_in[1];
    const float* Wk     = (const float*)d_in[2];
    const float* Wv     = (const float*)d_in[3];
    const float* conv_q = (const float*)d_in[4];
    const float* conv_k = (const float*)d_in[5];
    const float* conv_v = (const float*)d_in[6];
    const float* Wfa    = (const float*)d_in[7];
    const float* Wfb    = (const float*)d_in[8];
    const float* dt_b   = (const float*)d_in[9];
    const float* A_log  = (const float*)d_in[10];
    const float* Wb     = (const float*)d_in[11];
    const float* Wga    = (const float*)d_in[12];
    const float* Wgb    = (const float*)d_in[13];
    const float* norm_w = (const float*)d_in[14];
    const float* Wo     = (const float*)d_in[15];
    float* out = (float*)d_out;

    float* s = nullptr;
    cudaGetSymbolAddress((void**)&s, g_scratch);
    __half* hb = nullptr;
    cudaGetSymbolAddress((void**)&hb, g_hbuf);

    float* qkv  = s + OFF_QKV;
    float* qc   = s + OFF_QC;
    float* kc   = s + OFF_KC;
    float* vc   = s + OFF_VC;
    float* eg   = s + OFF_EG;
    float* gout = s + OFF_GOUT;
    float* o    = s + OFF_O;
    float* fa   = s + OFF_FA;              // fa | ga contiguous fp32
    float* beta = s + OFF_BETA;

    __half* W3   = hb + HO_W3;
    __half* WOh  = hb + HO_WO;
    __half* WFBh = hb + HO_WFB;
    __half* xh   = hb + HO_X;
    __half* fgh  = hb + HO_FG;
    __half* ogh  = hb + HO_OG;

    // persistent fork/join resources (handles only; DAG identical per call)
    static cudaStream_t sB = nullptr;
    static cudaEvent_t eFork = nullptr, eJoin = nullptr;
    if (!sB) {
        cudaStreamCreateWithFlags(&sB, cudaStreamNonBlocking);
        cudaEventCreateWithFlags(&eFork, cudaEventDisableTiming);
        cudaEventCreateWithFlags(&eJoin, cudaEventDisableTiming);
    }

    static bool attr_done = false;
    if (!attr_done) {
        cudaFuncSetAttribute(hgemm_k<0>,
                             cudaFuncAttributeMaxDynamicSharedMemorySize, H_SMEM);
        cudaFuncSetAttribute(hgemm_k<1>,
                             cudaFuncAttributeMaxDynamicSharedMemorySize, H_SMEM);
        attr_done = true;
    }

    // ---- fork chain B off the (captured) default stream ----
    cudaEventRecord(eFork, 0);
    cudaStreamWaitEvent(sB, eFork, 0);

    // ---- chain A (default stream): qkv path ----
    transpose3_h_k<<<dim3(64, 64, 3), 256>>>(Wq, Wk, Wv, W3, DM, KD);
    f2h_k<<<(unsigned)(NTK / 256), 256>>>(x, xh, (int)NTK);
    hgemm_k<0><<<296, 256, H_SMEM>>>(xh, DM, W3, DM, qkv,
                                     T_LEN, 6144, DM, nullptr, nullptr);
    conv_l2_k<<<dim3(T_LEN, NH), 128>>>(qkv, conv_q, conv_k, conv_v,
                                        qc, kc, vc);

    // ---- chain B (stream sB): gates, beta, weight transposes ----
    zero_k<<<1024, 256, 0, sB>>>(fa, 262144);
    sgemm_k<1><<<dim3(1, 8, 16), 256, 0, sB>>>(x, Wfa, fa,
                                               T_LEN, DH, DM, 128);
    sgemm_k<1><<<dim3(1, 8, 16), 256, 0, sB>>>(x, Wga, fa + 131072,
                                               T_LEN, DH, DM, 128);
    f2h_k<<<1024, 256, 0, sB>>>(fa, fgh, 262144);
    transpose3_h_k<<<dim3(64, 4, 2), 256, 0, sB>>>(Wfb, Wgb, Wgb, WFBh, DH, KD);
    transpose_h_k<<<dim3(64, 64), 256, 0, sB>>>(Wo, WOh, KD, DM);
    hgemm_k<1><<<128, 256, H_SMEM, sB>>>(fgh, DH, WFBh, DH, eg,
                                         T_LEN, KD, DH, dt_b, A_log);
    hgemm_k<0><<<128, 256, H_SMEM, sB>>>(fgh + 131072, DH,
                                         WFBh + 262144, DH, gout,
                                         T_LEN, KD, DH, nullptr, nullptr);
    beta_k<<<T_LEN, 512, 0, sB>>>(x, Wb, beta);
    cudaEventRecord(eJoin, sB);

    // ---- join, then recurrence + epilogue (default stream) ----
    cudaStreamWaitEvent(0, eJoin, 0);
    recur5_k<<<128, 256>>>(qc, kc, vc, eg, beta, o);
    epi_k<<<dim3(T_LEN, NH), 128>>>(o, gout, norm_w, ogh);
    hgemm_k<0><<<128, 256, H_SMEM>>>(ogh, KD, WOh, KD, out,
                                     T_LEN, DM, KD, nullptr, nullptr);
}

// round 14
// speedup vs baseline: 3.6571x; 1.0037x over previous
#include <cuda_runtime.h>
#include <cuda_fp16.h>
#include <math.h>
#include <cstdint>

// ---------------------------------------------------------------------------
// KimiDeltaAttention  (B=1, T=1024, DM=2048, H=16, DH=128, KD=2048, KC=4)
// Round 13: recurrence v6 — 2-step lookahead linearization. Eight concurrent
// reduction chains (one butterfly phase per TWO timesteps); serial tail is
// scalar-only. Conflict-free layout + 8-stage ring as v5. GEMMs unchanged.
// ---------------------------------------------------------------------------

#define T_LEN 1024
#define DM    2048
#define NH    16
#define DH    128
#define KD    2048

static constexpr size_t NTK = (size_t)T_LEN * KD;   // 2097152

// fp32 scratch
#define OFF_QKV  ((size_t)0)
#define OFF_QC   (NTK * 3)
#define OFF_KC   (NTK * 4)
#define OFF_VC   (NTK * 5)
#define OFF_EG   (NTK * 6)
#define OFF_GOUT (NTK * 7)
#define OFF_O    (NTK * 8)
#define OFF_FA   (NTK * 9)
#define OFF_BETA (NTK * 9 + 262144)
#define SCRATCH_FLOATS (OFF_BETA + 16384)
__device__ float g_scratch[SCRATCH_FLOATS];

// fp16 scratch (halfs)
#define HO_W3   ((size_t)0)
#define HO_WO   ((size_t)12582912)
#define HO_WFB  ((size_t)16777216)
#define HO_X    ((size_t)17301504)
#define HO_FG   ((size_t)19398656)
#define HO_OG   ((size_t)19660800)
#define HBUF_HALFS ((size_t)21757952)
__device__ __half g_hbuf[HBUF_HALFS];

// ---------------------------------------------------------------------------
// helpers
// ---------------------------------------------------------------------------
__device__ __forceinline__ uint32_t smem_u32(const void* p) {
    uint32_t a;
    asm("{ .reg .u64 t; cvta.to.shared.u64 t, %1; cvt.u32.u64 %0, t; }"
        : "=r"(a) : "l"(p));
    return a;
}
__device__ __forceinline__ void cp16(uint32_t dst, const void* src) {
    asm volatile("cp.async.cg.shared.global [%0], [%1], 16;"
                 :: "r"(dst), "l"(src) : "memory");
}
__device__ __forceinline__ void cp4(uint32_t dst, const void* src) {
    asm volatile("cp.async.ca.shared.global [%0], [%1], 4;"
                 :: "r"(dst), "l"(src) : "memory");
}
#define CP_COMMIT() asm volatile("cp.async.commit_group;" ::: "memory")
#define CP_WAIT(n)  asm volatile("cp.async.wait_group %0;" :: "n"(n) : "memory")

#define LDMX4(r0, r1, r2, r3, addr) \
    asm volatile("ldmatrix.sync.aligned.m8n8.x4.shared.b16 {%0,%1,%2,%3}, [%4];" \
                 : "=r"(r0), "=r"(r1), "=r"(r2), "=r"(r3) : "r"(addr))

// gate transform: exp(-expA * softplus_stable(v + dtb))
__device__ __forceinline__ float gate_xform(float v, float dtb, float expA)
{
    float xr = fminf(fmaxf(v + dtb, -20.f), 20.f);
    float sp = log1pf(expf(xr));
    return expf(-expA * sp);
}

// ---------------------------------------------------------------------------
// fp16 GEMM (persistent CTAs): C[M,N](f32) = A[M,K](h, lda) * Bt[N,K](h)^T
// ---------------------------------------------------------------------------
#define H_RS    40
#define H_STAGE (128 * H_RS)
#define H_SMEM  (3 * 2 * H_STAGE * 2)  // 61440 bytes

template <int GPREP>
__global__ __launch_bounds__(256, 2)
void hgemm_k(const __half* __restrict__ A, int lda,
             const __half* __restrict__ Bt, int ldb,
             float* __restrict__ C, int M, int N, int K,
             const float* __restrict__ dtb, const float* __restrict__ alog)
{
    extern __shared__ __half hsm[];

    const int tid  = threadIdx.x;
    const int wid  = tid >> 5;
    const int lane = tid & 31;
    const int wm   = wid >> 1;
    const int wn   = wid & 1;
    const int NT   = K >> 5;
    const int nTileN = N >> 7;
    const int nTiles = (M >> 7) * nTileN;

    for (int tile = blockIdx.x; tile < nTiles; tile += gridDim.x) {
        const int m0 = (tile / nTileN) * 128;
        const int n0 = (tile % nTileN) * 128;

        float acc[2][8][4];
#pragma unroll
        for (int a = 0; a < 2; a++)
#pragma unroll
            for (int b = 0; b < 8; b++)
#pragma unroll
                for (int c = 0; c < 4; c++) acc[a][b][c] = 0.f;

        auto load_stage = [&](int s, int i) {
            const __half* gA = A  + (size_t)m0 * lda + i * 32;
            const __half* gB = Bt + (size_t)n0 * ldb + i * 32;
            __half* dA = hsm + s * 2 * H_STAGE;
            __half* dB = dA + H_STAGE;
#pragma unroll
            for (int t = 0; t < 2; t++) {
                int idx = tid + t * 256;
                int row = idx >> 2;
                int seg = (idx & 3) * 8;
                cp16(smem_u32(dA + row * H_RS + seg),
                     gA + (size_t)row * lda + seg);
                cp16(smem_u32(dB + row * H_RS + seg),
                     gB + (size_t)row * ldb + seg);
            }
            CP_COMMIT();
        };

        load_stage(0, 0);
        load_stage(1, 1);

        for (int i = 0; i < NT; i++) {
            const int s = i % 3;
            if (i + 1 < NT) { CP_WAIT(1); } else { CP_WAIT(0); }
            __syncthreads();

            const uint32_t uA = smem_u32(hsm + s * 2 * H_STAGE);
            const uint32_t uB = uA + H_STAGE * 2;

#pragma unroll
            for (int kk = 0; kk < 32; kk += 16) {
                uint32_t af[2][4];
#pragma unroll
                for (int mt = 0; mt < 2; mt++) {
                    int row = wm * 32 + mt * 16 + (lane & 15);
                    int kof = kk + ((lane >> 4) << 3);
                    LDMX4(af[mt][0], af[mt][1], af[mt][2], af[mt][3],
                          uA + (row * H_RS + kof) * 2);
                }
                uint32_t bf[4][4];
#pragma unroll
                for (int g = 0; g < 4; g++) {
                    int nrow = wn * 64 + g * 16 + ((lane >> 4) << 3) + (lane & 7);
                    int kof = kk + (((lane >> 3) & 1) << 3);
                    LDMX4(bf[g][0], bf[g][1], bf[g][2], bf[g][3],
                          uB + (nrow * H_RS + kof) * 2);
                }
#pragma unroll
                for (int mt = 0; mt < 2; mt++)
#pragma unroll
                    for (int nt = 0; nt < 8; nt++) {
                        int g = nt >> 1, sub = nt & 1;
                        asm volatile(
                            "mma.sync.aligned.m16n8k16.row.col.f32.f16.f16.f32 "
                            "{%0,%1,%2,%3}, {%4,%5,%6,%7}, {%8,%9}, {%0,%1,%2,%3};"
                            : "+f"(acc[mt][nt][0]), "+f"(acc[mt][nt][1]),
                              "+f"(acc[mt][nt][2]), "+f"(acc[mt][nt][3])
                            : "r"(af[mt][0]), "r"(af[mt][1]),
                              "r"(af[mt][2]), "r"(af[mt][3]),
                              "r"(bf[g][sub * 2]), "r"(bf[g][sub * 2 + 1]));
                    }
            }
            if (i + 2 < NT) load_stage((i + 2) % 3, i + 2);
        }

#pragma unroll
        for (int mt = 0; mt < 2; mt++) {
            int r = m0 + wm * 32 + mt * 16 + (lane >> 2);
#pragma unroll
            for (int nt = 0; nt < 8; nt++) {
                int cn = n0 + wn * 64 + nt * 8 + (lane & 3) * 2;
                float v0a = acc[mt][nt][0], v1a = acc[mt][nt][1];
                float v0b = acc[mt][nt][2], v1b = acc[mt][nt][3];
                if (GPREP) {
                    float ea0 = expf(alog[cn >> 7]);
                    float ea1 = expf(alog[(cn + 1) >> 7]);
                    float d0 = dtb[cn], d1 = dtb[cn + 1];
                    v0a = gate_xform(v0a, d0, ea0); v1a = gate_xform(v1a, d1, ea1);
                    v0b = gate_xform(v0b, d0, ea0); v1b = gate_xform(v1b, d1, ea1);
                }
                *(float2*)(C + (size_t)r * N + cn) = make_float2(v0a, v1a);
                *(float2*)(C + (size_t)(r + 8) * N + cn) = make_float2(v0b, v1b);
            }
        }
        __syncthreads();
    }
}

// ---------------------------------------------------------------------------
// transpose to half, 3-way
// ---------------------------------------------------------------------------
__global__ __launch_bounds__(256)
void transpose3_h_k(const float* __restrict__ i0, const float* __restrict__ i1,
                    const float* __restrict__ i2, __half* __restrict__ out,
                    int R, int C)
{
    __shared__ float t[32][33];
    const float* in = (blockIdx.z == 0) ? i0 : (blockIdx.z == 1) ? i1 : i2;
    __half* o = out + (size_t)blockIdx.z * R * C;
    int cb = blockIdx.x * 32, rb = blockIdx.y * 32;
    int x = threadIdx.x & 31, y = threadIdx.x >> 5;
#pragma unroll
    for (int j = 0; j < 32; j += 8)
        t[y + j][x] = in[(size_t)(rb + y + j) * C + cb + x];
    __syncthreads();
#pragma unroll
    for (int j = 0; j < 32; j += 8)
        o[(size_t)(cb + y + j) * R + rb + x] = __float2half_rn(t[x][y + j]);
}

__global__ __launch_bounds__(256)
void transpose_h_k(const float* __restrict__ in, __half* __restrict__ out,
                   int R, int C)
{
    __shared__ float t[32][33];
    int cb = blockIdx.x * 32, rb = blockIdx.y * 32;
    int x = threadIdx.x & 31, y = threadIdx.x >> 5;
#pragma unroll
    for (int j = 0; j < 32; j += 8)
        t[y + j][x] = in[(size_t)(rb + y + j) * C + cb + x];
    __syncthreads();
#pragma unroll
    for (int j = 0; j < 32; j += 8)
        out[(size_t)(cb + y + j) * R + rb + x] = __float2half_rn(t[x][y + j]);
}

__global__ void f2h_k(const float* __restrict__ in, __half* __restrict__ out,
                      int n)
{
    int i = blockIdx.x * 256 + threadIdx.x;
    if (i < n) out[i] = __float2half_rn(in[i]);
}

// ---------------------------------------------------------------------------
// SIMT split-K SGEMM (tall-skinny rank-128 projections), fp32
// ---------------------------------------------------------------------------
template <int ATOMIC>
__global__ __launch_bounds__(256)
void sgemm_k(const float* __restrict__ A, const float* __restrict__ B,
             float* __restrict__ C, int M, int N, int K, int kSplit)
{
    __shared__ __align__(16) float As[8][128];
    __shared__ __align__(16) float Bs[8][128];

    const int tid  = threadIdx.x;
    const int bm   = blockIdx.y;
    const int bn   = blockIdx.x;
    const int k0   = blockIdx.z * kSplit;

    const int arow = tid >> 1;
    const int acol = (tid & 1) << 2;
    const int brow = tid >> 5;
    const int bcol = (tid & 31) << 2;
    const int ty   = tid >> 4;
    const int tx   = tid & 15;

    float acc[8][8];
#pragma unroll
    for (int i = 0; i < 8; i++)
#pragma unroll
        for (int j = 0; j < 8; j++) acc[i][j] = 0.f;

    const float* Ag = A + (size_t)(bm * 128 + arow) * K;
    const float* Bg = B + (size_t)(bn * 128) + bcol;

    for (int kt = 0; kt < kSplit; kt += 8) {
        float4 av = *(const float4*)(Ag + (k0 + kt + acol));
        As[acol + 0][arow] = av.x;
        As[acol + 1][arow] = av.y;
        As[acol + 2][arow] = av.z;
        As[acol + 3][arow] = av.w;
        *(float4*)&Bs[brow][bcol] =
            *(const float4*)(Bg + (size_t)(k0 + kt + brow) * N);
        __syncthreads();

#pragma unroll
        for (int kk = 0; kk < 8; kk++) {
            float4 a0 = *(const float4*)&As[kk][ty * 8];
            float4 a1 = *(const float4*)&As[kk][ty * 8 + 4];
            float4 b0 = *(const float4*)&Bs[kk][tx * 8];
            float4 b1 = *(const float4*)&Bs[kk][tx * 8 + 4];
            float a[8] = {a0.x, a0.y, a0.z, a0.w, a1.x, a1.y, a1.z, a1.w};
            float b[8] = {b0.x, b0.y, b0.z, b0.w, b1.x, b1.y, b1.z, b1.w};
#pragma unroll
            for (int i = 0; i < 8; i++)
#pragma unroll
                for (int j = 0; j < 8; j++)
                    acc[i][j] = fmaf(a[i], b[j], acc[i][j]);
        }
        __syncthreads();
    }

#pragma unroll
    for (int i = 0; i < 8; i++) {
        float* Cp = C + (size_t)(bm * 128 + ty * 8 + i) * N + bn * 128 + tx * 8;
        if (ATOMIC) {
#pragma unroll
            for (int j = 0; j < 8; j++) atomicAdd(Cp + j, acc[i][j]);
        } else {
            *(float4*)(Cp + 0) = make_float4(acc[i][0], acc[i][1], acc[i][2], acc[i][3]);
            *(float4*)(Cp + 4) = make_float4(acc[i][4], acc[i][5], acc[i][6], acc[i][7]);
        }
    }
}

__global__ void zero_k(float* __restrict__ p, int n)
{
    int i = blockIdx.x * 256 + threadIdx.x;
    if (i < n) p[i] = 0.f;
}

__device__ __forceinline__ float block128_sum(float v, float* shm)
{
#pragma unroll
    for (int m = 16; m > 0; m >>= 1) v += __shfl_xor_sync(0xffffffffu, v, m);
    int w = threadIdx.x >> 5;
    if ((threadIdx.x & 31) == 0) shm[w] = v;
    __syncthreads();
    return shm[0] + shm[1] + shm[2] + shm[3];
}

// ---------------------------------------------------------------------------
// fused: depthwise causal conv (K=4) + SiLU + l2norm(q,k).  grid (T, NH).
// ---------------------------------------------------------------------------
__global__ __launch_bounds__(128)
void conv_l2_k(const float* __restrict__ qkv,
               const float* __restrict__ wq, const float* __restrict__ wk,
               const float* __restrict__ wv,
               float* __restrict__ qc, float* __restrict__ kc,
               float* __restrict__ vc)
{
    __shared__ float shm[4];
    int t = blockIdx.x, h = blockIdx.y, d = threadIdx.x;
    int c = h * DH + d;
    float aq = 0.f, ak = 0.f, av = 0.f;
#pragma unroll
    for (int j = 0; j < 4; j++) {
        int tt = t + j - 3;
        if (tt >= 0) {
            size_t base = (size_t)tt * 6144;
            aq = fmaf(wq[j * KD + c], qkv[base + c], aq);
            ak = fmaf(wk[j * KD + c], qkv[base + 2048 + c], ak);
            av = fmaf(wv[j * KD + c], qkv[base + 4096 + c], av);
        }
    }
    aq = aq / (1.f + expf(-aq));
    ak = ak / (1.f + expf(-ak));
    av = av / (1.f + expf(-av));

    size_t idx = (size_t)t * KD + c;
    vc[idx] = av;

    float ssq = block128_sum(aq * aq, shm);
    __syncthreads();
    float ssk = block128_sum(ak * ak, shm);
    qc[idx] = aq * rsqrtf(ssq + 1e-6f) * 0.08838834764831845f;
    kc[idx] = ak * rsqrtf(ssk + 1e-6f);
}

// ---------------------------------------------------------------------------
// beta = sigmoid(x @ Wb)
// ---------------------------------------------------------------------------
__global__ __launch_bounds__(512)
void beta_k(const float* __restrict__ x, const float* __restrict__ Wb,
            float* __restrict__ beta)
{
    __shared__ float sx[DM];
    int t = blockIdx.x;
    for (int i = threadIdx.x; i < DM; i += 512) sx[i] = x[(size_t)t * DM + i];
    __syncthreads();
    int h = threadIdx.x >> 5, lane = threadIdx.x & 31;
    float acc = 0.f;
    for (int k = lane; k < DM; k += 32) acc = fmaf(sx[k], Wb[k * NH + h], acc);
#pragma unroll
    for (int m = 16; m > 0; m >>= 1) acc += __shfl_xor_sync(0xffffffffu, acc, m);
    if (lane == 0) beta[t * NH + h] = 1.f / (1.f + expf(-acc));
}

// ---------------------------------------------------------------------------
// gated delta recurrence v6: 2-step lookahead linearization.
//   d0 = e0*S, d1 = e1*d0, w = e1*k0
//   P1=k0.d0 P2=q0.d0 P3=q0.k0 P4=k1.d1 P5=q1.d1 P6=k1.w P7=q1.w P8=q1.k1
//   u0 = b0(v0-P1); o0 = P2+P3*u0
//   u1 = b1(v1-(P4+P6*u0)); o1 = P5+P7*u0+P8*u1
//   S' = d1 + w*u0 + k1*u1
// One butterfly phase (8 concurrent chains) per TWO timesteps.
// Conflict-free layout, 8-stage ring, distance 6. grid 128 x 256.
// ---------------------------------------------------------------------------
__global__ __launch_bounds__(256)
void recur6_k(const float* __restrict__ qf, const float* __restrict__ kf,
              const float* __restrict__ vv, const float* __restrict__ eg,
              const float* __restrict__ beta, float* __restrict__ o)
{
    __shared__ __align__(16) float sq[8][128];
    __shared__ __align__(16) float sk[8][128];
    __shared__ __align__(16) float se[8][128];
    __shared__ __align__(16) float sv[8][16];
    __shared__ float sb[8];

    const int tid  = threadIdx.x;
    const int wid  = tid >> 5;
    const int lane = tid & 31;
    const int sub  = lane >> 4;
    const int l16  = lane & 15;
    const int colbase = blockIdx.x * 16;
    const int head = colbase >> 7;
    const int col  = colbase + wid * 2 + sub;
    const int hoff = head * DH;

    auto issue_stage = [&](int t) {
        int st = t & 7;
        if (tid < 96) {
            int arr = tid >> 5;
            int off = (tid & 31) * 4;
            const float* src = (arr == 0 ? qf : (arr == 1 ? kf : eg))
                               + (size_t)t * KD + hoff + off;
            float* dst = (arr == 0 ? sq[st] : (arr == 1 ? sk[st] : se[st])) + off;
            cp16(smem_u32(dst), src);
        } else if (tid < 100) {
            int off = (tid - 96) * 4;
            cp16(smem_u32(sv[st] + off),
                 vv + (size_t)t * KD + colbase + off);
        } else if (tid == 100) {
            cp4(smem_u32(&sb[st]), beta + t * NH + head);
        }
        CP_COMMIT();
    };

#pragma unroll
    for (int p = 0; p < 6; p++) issue_stage(p);

    float s[8];
#pragma unroll
    for (int i = 0; i < 8; i++) s[i] = 0.f;

    for (int t = 0; t < T_LEN; t += 2) {
        const int st0 = t & 7;
        const int st1 = (t + 1) & 7;
        CP_WAIT(4);
        __syncthreads();

        // conflict-free float4 loads (indices l16 and l16+16)
        float k0v[8], k1v[8], q0v[8], q1v[8], e0v[8], e1v[8];
        *(float4*)&k0v[0] = ((const float4*)sk[st0])[l16];
        *(float4*)&k0v[4] = ((const float4*)sk[st0])[l16 + 16];
        *(float4*)&q0v[0] = ((const float4*)sq[st0])[l16];
        *(float4*)&q0v[4] = ((const float4*)sq[st0])[l16 + 16];
        *(float4*)&e0v[0] = ((const float4*)se[st0])[l16];
        *(float4*)&e0v[4] = ((const float4*)se[st0])[l16 + 16];
        *(float4*)&k1v[0] = ((const float4*)sk[st1])[l16];
        *(float4*)&k1v[4] = ((const float4*)sk[st1])[l16 + 16];
        *(float4*)&q1v[0] = ((const float4*)sq[st1])[l16];
        *(float4*)&q1v[4] = ((const float4*)sq[st1])[l16 + 16];
        *(float4*)&e1v[0] = ((const float4*)se[st1])[l16];
        *(float4*)&e1v[4] = ((const float4*)se[st1])[l16 + 16];
        float v0 = sv[st0][wid * 2 + sub];
        float v1 = sv[st1][wid * 2 + sub];
        float b0 = sb[st0];
        float b1 = sb[st1];

        // prefetch stages t+6, t+7
        if (t + 6 < T_LEN) issue_stage(t + 6); else CP_COMMIT();
        if (t + 7 < T_LEN) issue_stage(t + 7); else CP_COMMIT();

        // elementwise precomputes
        float d0v[8], d1v[8], wv8[8];
#pragma unroll
        for (int i = 0; i < 8; i++) {
            d0v[i] = e0v[i] * s[i];
            d1v[i] = e1v[i] * d0v[i];
            wv8[i] = e1v[i] * k0v[i];
        }

        // eight partial dots
        float P1 = 0.f, P2 = 0.f, P3 = 0.f, P4 = 0.f;
        float P5 = 0.f, P6 = 0.f, P7 = 0.f, P8 = 0.f;
#pragma unroll
        for (int i = 0; i < 8; i++) {
            P1 = fmaf(k0v[i], d0v[i], P1);
            P2 = fmaf(q0v[i], d0v[i], P2);
            P3 = fmaf(q0v[i], k0v[i], P3);
            P4 = fmaf(k1v[i], d1v[i], P4);
            P5 = fmaf(q1v[i], d1v[i], P5);
            P6 = fmaf(k1v[i], wv8[i], P6);
            P7 = fmaf(q1v[i], wv8[i], P7);
            P8 = fmaf(q1v[i], k1v[i], P8);
        }

        // one butterfly phase, 8 concurrent chains (16-lane groups)
#pragma unroll
        for (int m = 8; m > 0; m >>= 1) {
            P1 += __shfl_xor_sync(0xffffffffu, P1, m);
            P2 += __shfl_xor_sync(0xffffffffu, P2, m);
            P3 += __shfl_xor_sync(0xffffffffu, P3, m);
            P4 += __shfl_xor_sync(0xffffffffu, P4, m);
            P5 += __shfl_xor_sync(0xffffffffu, P5, m);
            P6 += __shfl_xor_sync(0xffffffffu, P6, m);
            P7 += __shfl_xor_sync(0xffffffffu, P7, m);
            P8 += __shfl_xor_sync(0xffffffffu, P8, m);
        }

        // scalar serial tail
        float u0 = b0 * (v0 - P1);
        float o0 = fmaf(P3, u0, P2);
        float r  = fmaf(P6, u0, P4);
        float u1 = b1 * (v1 - r);
        float o1 = fmaf(P8, u1, fmaf(P7, u0, P5));

        // state update: S' = d1 + w*u0 + k1*u1
#pragma unroll
        for (int i = 0; i < 8; i++)
            s[i] = fmaf(k1v[i], u1, fmaf(wv8[i], u0, d1v[i]));

        if (l16 == 0) {
            o[(size_t)t * KD + col] = o0;
            o[(size_t)(t + 1) * KD + col] = o1;
        }
    }
}

// ---------------------------------------------------------------------------
// epilogue: og(half) = o * rsqrt(mean(o^2)+eps) * norm_w * sigmoid(gout)
// ---------------------------------------------------------------------------
__global__ __launch_bounds__(128)
void epi_k(const float* __restrict__ o, const float* __restrict__ gout,
           const float* __restrict__ norm_w, __half* __restrict__ og)
{
    __shared__ float shm[4];
    int t = blockIdx.x, h = blockIdx.y, d = threadIdx.x;
    size_t idx = (size_t)t * KD + h * DH + d;
    float ov = o[idx];
    float ss = block128_sum(ov * ov, shm);
    float rstd = rsqrtf(ss * (1.f / 128.f) + 1e-6f);
    float gate = 1.f / (1.f + expf(-gout[idx]));
    og[idx] = __float2half_rn(ov * rstd * norm_w[d] * gate);
}

// ---------------------------------------------------------------------------
// launch: two-stream DAG. Chain B (gates/weights) overlaps chain A (qkv).
// ---------------------------------------------------------------------------
extern "C" void kernel_launch(void* const* d_in, const int* in_sizes, int n_in,
                              void* d_out, int out_size)
{
    (void)in_sizes; (void)n_in; (void)out_size;
    const float* x      = (const float*)d_in[0];
    const float* Wq     = (const float*)d_in[1];
    const float* Wk     = (const float*)d_in[2];
    const float* Wv     = (const float*)d_in[3];
    const float* conv_q = (const float*)d_in[4];
    const float* conv_k = (const float*)d_in[5];
    const float* conv_v = (const float*)d_in[6];
    const float* Wfa    = (const float*)d_in[7];
    const float* Wfb    = (const float*)d_in[8];
    const float* dt_b   = (const float*)d_in[9];
    const float* A_log  = (const float*)d_in[10];
    const float* Wb     = (const float*)d_in[11];
    const float* Wga    = (const float*)d_in[12];
    const float* Wgb    = (const float*)d_in[13];
    const float* norm_w = (const float*)d_in[14];
    const float* Wo     = (const float*)d_in[15];
    float* out = (float*)d_out;

    float* s = nullptr;
    cudaGetSymbolAddress((void**)&s, g_scratch);
    __half* hb = nullptr;
    cudaGetSymbolAddress((void**)&hb, g_hbuf);

    float* qkv  = s + OFF_QKV;
    float* qc   = s + OFF_QC;
    float* kc   = s + OFF_KC;
    float* vc   = s + OFF_VC;
    float* eg   = s + OFF_EG;
    float* gout = s + OFF_GOUT;
    float* o    = s + OFF_O;
    float* fa   = s + OFF_FA;
    float* beta = s + OFF_BETA;

    __half* W3   = hb + HO_W3;
    __half* WOh  = hb + HO_WO;
    __half* WFBh = hb + HO_WFB;
    __half* xh   = hb + HO_X;
    __half* fgh  = hb + HO_FG;
    __half* ogh  = hb + HO_OG;

    static cudaStream_t sB = nullptr;
    static cudaEvent_t eFork = nullptr, eJoin = nullptr;
    if (!sB) {
        cudaStreamCreateWithFlags(&sB, cudaStreamNonBlocking);
        cudaEventCreateWithFlags(&eFork, cudaEventDisableTiming);
        cudaEventCreateWithFlags(&eJoin, cudaEventDisableTiming);
    }

    static bool attr_done = false;
    if (!attr_done) {
        cudaFuncSetAttribute(hgemm_k<0>,
                             cudaFuncAttributeMaxDynamicSharedMemorySize, H_SMEM);
        cudaFuncSetAttribute(hgemm_k<1>,
                             cudaFuncAttributeMaxDynamicSharedMemorySize, H_SMEM);
        attr_done = true;
    }

    // ---- fork chain B off the (captured) default stream ----
    cudaEventRecord(eFork, 0);
    cudaStreamWaitEvent(sB, eFork, 0);

    // ---- chain A (default stream): qkv path ----
    transpose3_h_k<<<dim3(64, 64, 3), 256>>>(Wq, Wk, Wv, W3, DM, KD);
    f2h_k<<<(unsigned)(NTK / 256), 256>>>(x, xh, (int)NTK);
    hgemm_k<0><<<296, 256, H_SMEM>>>(xh, DM, W3, DM, qkv,
                                     T_LEN, 6144, DM, nullptr, nullptr);
    conv_l2_k<<<dim3(T_LEN, NH), 128>>>(qkv, conv_q, conv_k, conv_v,
                                        qc, kc, vc);

    // ---- chain B (stream sB): gates, beta, weight transposes ----
    zero_k<<<1024, 256, 0, sB>>>(fa, 262144);
    sgemm_k<1><<<dim3(1, 8, 16), 256, 0, sB>>>(x, Wfa, fa,
                                               T_LEN, DH, DM, 128);
    sgemm_k<1><<<dim3(1, 8, 16), 256, 0, sB>>>(x, Wga, fa + 131072,
                                               T_LEN, DH, DM, 128);
    f2h_k<<<1024, 256, 0, sB>>>(fa, fgh, 262144);
    transpose3_h_k<<<dim3(64, 4, 2), 256, 0, sB>>>(Wfb, Wgb, Wgb, WFBh, DH, KD);
    transpose_h_k<<<dim3(64, 64), 256, 0, sB>>>(Wo, WOh, KD, DM);
    hgemm_k<1><<<128, 256, H_SMEM, sB>>>(fgh, DH, WFBh, DH, eg,
                                         T_LEN, KD, DH, dt_b, A_log);
    hgemm_k<0><<<128, 256, H_SMEM, sB>>>(fgh + 131072, DH,
                                         WFBh + 262144, DH, gout,
                                         T_LEN, KD, DH, nullptr, nullptr);
    beta_k<<<T_LEN, 512, 0, sB>>>(x, Wb, beta);
    cudaEventRecord(eJoin, sB);

    // ---- join, then recurrence + epilogue (default stream) ----
    cudaStreamWaitEvent(0, eJoin, 0);
    recur6_k<<<128, 256>>>(qc, kc, vc, eg, beta, o);
    epi_k<<<dim3(T_LEN, NH), 128>>>(o, gout, norm_w, ogh);
    hgemm_k<0><<<128, 256, H_SMEM>>>(ogh, KD, WOh, KD, out,
                                     T_LEN, DM, KD, nullptr, nullptr);
}